// round 7
// baseline (speedup 1.0000x reference)
#include <cuda_runtime.h>
#include <cuda_bf16.h>

#define BB 4
#define SS 1024
#define HH 16
#define HDIM 64
#define DD 1024

// ---------------------------------------------------------------------------
// scratch (device globals — no allocation allowed)
// ---------------------------------------------------------------------------
__device__ float g_qkv[BB * SS * 3 * DD];   // [B,S,3D] fp32 (for vT)
__device__ __nv_bfloat16 g_xhi[BB * SS * DD];
__device__ __nv_bfloat16 g_xlo[BB * SS * DD];
__device__ __nv_bfloat16 g_wqT_hi[3 * DD * DD];
__device__ __nv_bfloat16 g_wqT_lo[3 * DD * DD];
__device__ __nv_bfloat16 g_woT_hi[DD * DD];
__device__ __nv_bfloat16 g_woT_lo[DD * DD];
__device__ __nv_bfloat16 g_vhi[BB * SS * DD];   // values hi (attn epilogue)
__device__ __nv_bfloat16 g_vlo[BB * SS * DD];
__device__ __nv_bfloat16 g_qh[BB * SS * 3 * DD];   // qkv split hi (gemm epilogue)
__device__ __nv_bfloat16 g_ql[BB * SS * 3 * DD];
__device__ __nv_bfloat16 g_vTh[BB * HH * HDIM * SS]; // V^T per (b,h): [64][S]
__device__ __nv_bfloat16 g_vTl[BB * HH * HDIM * SS];

// ---------------------------------------------------------------------------
__device__ __forceinline__ unsigned smem_u32(const void* p) {
    unsigned a;
    asm("{ .reg .u64 t; cvta.to.shared.u64 t, %1; cvt.u32.u64 %0, t; }" : "=r"(a) : "l"(p));
    return a;
}
#define SWZ128(o) ((o) ^ (((o) >> 3) & 0x70))
#define SWZ64(o)  ((o) ^ (((o) >> 3) & 0x30))

#define CP_ASYNC16(saddr, gptr) \
    asm volatile("cp.async.cg.shared.global [%0], [%1], 16;" :: "r"(saddr), "l"(gptr) : "memory")
#define CP_COMMIT() asm volatile("cp.async.commit_group;" ::: "memory")
#define CP_WAIT1()  asm volatile("cp.async.wait_group 1;" ::: "memory")
#define CP_WAIT0()  asm volatile("cp.async.wait_group 0;" ::: "memory")

#define LDMX4(r0, r1, r2, r3, a) \
    asm volatile("ldmatrix.sync.aligned.m8n8.x4.shared.b16 {%0,%1,%2,%3}, [%4];" \
        : "=r"(r0), "=r"(r1), "=r"(r2), "=r"(r3) : "r"(a))

#define MMA16816(d, a, b0, b1) \
    asm volatile("mma.sync.aligned.m16n8k16.row.col.f32.bf16.bf16.f32 " \
        "{%0,%1,%2,%3}, {%4,%5,%6,%7}, {%8,%9}, {%0,%1,%2,%3};" \
        : "+f"((d)[0]), "+f"((d)[1]), "+f"((d)[2]), "+f"((d)[3]) \
        : "r"((a)[0]), "r"((a)[1]), "r"((a)[2]), "r"((a)[3]), "r"(b0), "r"(b1))

__device__ __forceinline__ unsigned pack_hi2(float x, float y, unsigned& lo) {
    __nv_bfloat16 hx = __float2bfloat16(x);
    __nv_bfloat16 hy = __float2bfloat16(y);
    __nv_bfloat16 lx = __float2bfloat16(x - __bfloat162float(hx));
    __nv_bfloat16 ly = __float2bfloat16(y - __bfloat162float(hy));
    lo = ((unsigned)__bfloat16_as_ushort(ly) << 16) | __bfloat16_as_ushort(lx);
    return ((unsigned)__bfloat16_as_ushort(hy) << 16) | __bfloat16_as_ushort(hx);
}
__device__ __forceinline__ float bflo(unsigned u) {
    return __bfloat162float(__ushort_as_bfloat16((unsigned short)(u & 0xFFFF)));
}
__device__ __forceinline__ float bfhi(unsigned u) {
    return __bfloat162float(__ushort_as_bfloat16((unsigned short)(u >> 16)));
}

// ---------------------------------------------------------------------------
__global__ __launch_bounds__(256) void split_kernel(
    const float* __restrict__ src, __nv_bfloat16* __restrict__ hi,
    __nv_bfloat16* __restrict__ lo, int n4)
{
    int i = blockIdx.x * 256 + threadIdx.x;
    if (i >= n4) return;
    float4 v = ((const float4*)src)[i];
    unsigned l0, l1, h0, h1;
    h0 = pack_hi2(v.x, v.y, l0);
    h1 = pack_hi2(v.z, v.w, l1);
    ((uint2*)hi)[i] = make_uint2(h0, h1);
    ((uint2*)lo)[i] = make_uint2(l0, l1);
}

__global__ __launch_bounds__(256) void tsplit_kernel(
    const float* __restrict__ W, __nv_bfloat16* __restrict__ hiT,
    __nv_bfloat16* __restrict__ loT, int K, int N)
{
    __shared__ float t[32][33];
    int k0 = blockIdx.y * 32, n0 = blockIdx.x * 32;
    int tx = threadIdx.x, ty = threadIdx.y;
    #pragma unroll
    for (int i = 0; i < 32; i += 8)
        t[ty + i][tx] = W[(size_t)(k0 + ty + i) * N + n0 + tx];
    __syncthreads();
    #pragma unroll
    for (int i = 0; i < 32; i += 8) {
        float v = t[tx][ty + i];
        __nv_bfloat16 h = __float2bfloat16(v);
        size_t o = (size_t)(n0 + ty + i) * K + k0 + tx;
        hiT[o] = h;
        loT[o] = __float2bfloat16(v - __bfloat162float(h));
    }
}

__global__ __launch_bounds__(256) void vT_kernel(
    const float* __restrict__ qkv, __nv_bfloat16* __restrict__ vTh,
    __nv_bfloat16* __restrict__ vTl)
{
    __shared__ float t[32][33];
    int s0 = blockIdx.x * 32, d0 = blockIdx.y * 32, bh = blockIdx.z;
    int b = bh >> 4, h = bh & 15;
    int tx = threadIdx.x, ty = threadIdx.y;
    #pragma unroll
    for (int i = 0; i < 32; i += 8)
        t[ty + i][tx] = qkv[(size_t)(b * SS + s0 + ty + i) * 3072 + h * 192 + 128 + d0 + tx];
    __syncthreads();
    #pragma unroll
    for (int i = 0; i < 32; i += 8) {
        float v = t[tx][ty + i];
        __nv_bfloat16 hh = __float2bfloat16(v);
        size_t o = (size_t)(bh * HDIM + d0 + ty + i) * SS + s0 + tx;
        vTh[o] = hh;
        vTl[o] = __float2bfloat16(v - __bfloat162float(hh));
    }
}

// ---------------------------------------------------------------------------
// Combined-pass GEMM: per K-chunk(32) stage holds Ahi|Alo|BThi|BTlo (8KB each).
// 64B rows, SWZ64. THREE stages, depth-2 lookahead (wait_group <= 1).
// ---------------------------------------------------------------------------
#define GS_STAGE 32768
#define GS_TOTAL 98304

__device__ __forceinline__ void gload64(const __nv_bfloat16* __restrict__ src,
                                        int rbase, int K, int kt, unsigned dst, int tid)
{
    #pragma unroll
    for (int i = 0; i < 2; i++) {
        int idx = tid + i * 256;
        int row = idx >> 2;
        int c16 = (idx & 3) * 16;
        CP_ASYNC16(dst + SWZ64((unsigned)(row * 64 + c16)),
                   (const char*)(src + (size_t)(rbase + row) * K + kt) + c16);
    }
}

__device__ __forceinline__ void prefetch_chunk(
    const __nv_bfloat16* __restrict__ Ahi, const __nv_bfloat16* __restrict__ Alo,
    const __nv_bfloat16* __restrict__ BThi, const __nv_bfloat16* __restrict__ BTlo,
    int brow, int bcol, int K, int kt, unsigned stage, int tid)
{
    gload64(Ahi, brow, K, kt, stage, tid);
    gload64(Alo, brow, K, kt, stage + 8192, tid);
    gload64(BThi, bcol, K, kt, stage + 16384, tid);
    gload64(BTlo, bcol, K, kt, stage + 24576, tid);
}

__global__ __launch_bounds__(256, 2) void gemm3x_mma(
    const __nv_bfloat16* __restrict__ Ahi, const __nv_bfloat16* __restrict__ Alo,
    const __nv_bfloat16* __restrict__ BThi, const __nv_bfloat16* __restrict__ BTlo,
    const float* __restrict__ bias, float* __restrict__ C,
    __nv_bfloat16* __restrict__ Chi, __nv_bfloat16* __restrict__ Clo,
    int M, int N, int K)
{
    extern __shared__ char smem[];
    unsigned sb = smem_u32(smem);
    const int tid = threadIdx.x, w = tid >> 5, lane = tid & 31;
    const int brow = blockIdx.y * 128, bcol = blockIdx.x * 128;
    const int wm = (w >> 2) * 64;
    const int wn = (w & 3) * 32;
    const int lrow = lane & 15;
    const int lcol = (lane >> 4) * 16;

    const int nch = K >> 5;   // 32

    float acc[4][4][4] = {};

    prefetch_chunk(Ahi, Alo, BThi, BTlo, brow, bcol, K, 0, sb, tid);
    CP_COMMIT();
    prefetch_chunk(Ahi, Alo, BThi, BTlo, brow, bcol, K, 32, sb + GS_STAGE, tid);
    CP_COMMIT();
    CP_WAIT1();          // chunk 0 complete; chunk 1 in flight
    __syncthreads();

    int s_cur = 0;       // stage of chunk c
    for (int c = 0; c < nch; c++) {
        // issue prefetch for c+2 before MMA so it overlaps two MMA spans
        if (c + 2 < nch) {
            int s2 = s_cur + 2; if (s2 >= 3) s2 -= 3;
            prefetch_chunk(Ahi, Alo, BThi, BTlo, brow, bcol, K, (c + 2) << 5,
                           sb + s2 * GS_STAGE, tid);
            CP_COMMIT();
        }

        unsigned base = sb + s_cur * GS_STAGE;
        #pragma unroll
        for (int ks = 0; ks < 2; ks++) {
            int kb = ks * 32;
            unsigned bH[2][4], bL[2][4];
            #pragma unroll
            for (int j2 = 0; j2 < 2; j2++) {
                unsigned off = (unsigned)((wn + j2 * 16 + lrow) * 64 + kb + lcol);
                LDMX4(bH[j2][0], bH[j2][1], bH[j2][2], bH[j2][3], base + 16384 + SWZ64(off));
                LDMX4(bL[j2][0], bL[j2][1], bL[j2][2], bL[j2][3], base + 24576 + SWZ64(off));
            }
            #pragma unroll
            for (int i = 0; i < 4; i++) {
                unsigned off = (unsigned)((wm + i * 16 + lrow) * 64 + kb + lcol);
                unsigned aH[4], aL[4];
                LDMX4(aH[0], aH[1], aH[2], aH[3], base + SWZ64(off));
                LDMX4(aL[0], aL[1], aL[2], aL[3], base + 8192 + SWZ64(off));
                #pragma unroll
                for (int j = 0; j < 4; j++) {
                    unsigned h0 = (j & 1) ? bH[j >> 1][1] : bH[j >> 1][0];
                    unsigned h1 = (j & 1) ? bH[j >> 1][3] : bH[j >> 1][2];
                    unsigned l0 = (j & 1) ? bL[j >> 1][1] : bL[j >> 1][0];
                    unsigned l1 = (j & 1) ? bL[j >> 1][3] : bL[j >> 1][2];
                    MMA16816(acc[i][j], aH, h0, h1);
                    MMA16816(acc[i][j], aL, h0, h1);
                    MMA16816(acc[i][j], aH, l0, l1);
                }
            }
        }

        if (c + 1 < nch) {
            if (c + 2 < nch) { CP_WAIT1(); } else { CP_WAIT0(); }
        }
        __syncthreads();
        if (++s_cur == 3) s_cur = 0;
    }

    const int r0 = brow + wm + (lane >> 2);
    const int c0 = bcol + wn + (lane & 3) * 2;
    #pragma unroll
    for (int i = 0; i < 4; i++) {
        #pragma unroll
        for (int j = 0; j < 4; j++) {
            int col = c0 + j * 8;
            float bx = bias[col], by = bias[col + 1];
            float v00 = acc[i][j][0] + bx, v01 = acc[i][j][1] + by;
            float v10 = acc[i][j][2] + bx, v11 = acc[i][j][3] + by;
            size_t o0 = (size_t)(r0 + i * 16) * N + col;
            size_t o1 = (size_t)(r0 + i * 16 + 8) * N + col;
            *(float2*)&C[o0] = make_float2(v00, v01);
            *(float2*)&C[o1] = make_float2(v10, v11);
            if (Chi) {
                unsigned l0, l1;
                unsigned h0 = pack_hi2(v00, v01, l0);
                unsigned h1 = pack_hi2(v10, v11, l1);
                *(unsigned*)&Chi[o0] = h0;
                *(unsigned*)&Clo[o0] = l0;
                *(unsigned*)&Chi[o1] = h1;
                *(unsigned*)&Clo[o1] = l1;
            }
        }
    }
}

// ---------------------------------------------------------------------------
// Attention (unchanged from R6): packed bf16 hi/lo logits, PSTRIDE-padded.
// ---------------------------------------------------------------------------
#define AT_SPL  66048
#define AT_STAT 132096
#define AT_QH   132224
#define AT_QL   136320
#define AT_KV   140416
#define AT_TOTAL 205952
#define PSTRIDE 2064

__device__ __forceinline__ void attn_load_k(
    const __nv_bfloat16* __restrict__ qh, const __nv_bfloat16* __restrict__ ql,
    int b, int h, int kb, unsigned dstH, unsigned dstL, int tid)
{
    #pragma unroll
    for (int i = 0; i < 4; i++) {
        int idx = tid + i * 256;
        int row = idx >> 3, c16 = (idx & 7) * 16;
        unsigned so = SWZ128((unsigned)(row * 128 + c16));
        CP_ASYNC16(dstH + so, (const char*)(qh + (size_t)(b * SS + kb + row) * 3072 + h * 192 + 64) + c16);
        CP_ASYNC16(dstL + so, (const char*)(ql + (size_t)(b * SS + kb + row) * 3072 + h * 192 + 64) + c16);
    }
}

__device__ __forceinline__ void attn_load_v(
    const __nv_bfloat16* __restrict__ vTh, const __nv_bfloat16* __restrict__ vTl,
    int bh, int kb, unsigned dst, int tid)
{
    #pragma unroll
    for (int s = 0; s < 2; s++) {
        #pragma unroll
        for (int i = 0; i < 2; i++) {
            int idx = tid + i * 256;
            int row = idx >> 3, c16 = (idx & 7) * 16;
            unsigned so = SWZ128((unsigned)(row * 128 + c16));
            const char* gh = (const char*)(vTh + (size_t)(bh * HDIM + row) * SS + kb + s * 64) + c16;
            const char* gl = (const char*)(vTl + (size_t)(bh * HDIM + row) * SS + kb + s * 64) + c16;
            CP_ASYNC16(dst + s * 8192 + so, gh);
            CP_ASYNC16(dst + 16384 + s * 8192 + so, gl);
        }
    }
}

__global__ __launch_bounds__(256) void attn_mma(
    const __nv_bfloat16* __restrict__ qh, const __nv_bfloat16* __restrict__ ql,
    const __nv_bfloat16* __restrict__ vTh, const __nv_bfloat16* __restrict__ vTl,
    float* __restrict__ attn_out)
{
    extern __shared__ char smem[];
    unsigned sb = smem_u32(smem);
    float* sStat = (float*)(smem + AT_STAT);

    const int qt = blockIdx.x, h = blockIdx.y, b = blockIdx.z;
    const int bh = b * HH + h;
    const int q0 = qt * 32;
    const int tid = threadIdx.x, w = tid >> 5, lane = tid & 31;
    const int lrow = lane & 15, lcol = (lane >> 4) * 16;

    {
        int row = tid >> 3, c16 = (tid & 7) * 16;
        unsigned so = SWZ128((unsigned)(row * 128 + c16));
        CP_ASYNC16(sb + AT_QH + so, (const char*)(qh + (size_t)(b * SS + q0 + row) * 3072 + h * 192) + c16);
        CP_ASYNC16(sb + AT_QL + so, (const char*)(ql + (size_t)(b * SS + q0 + row) * 3072 + h * 192) + c16);
    }
    attn_load_k(qh, ql, b, h, 0, sb + AT_KV, sb + AT_KV + 16384, tid);
    CP_COMMIT();
    CP_WAIT0();
    __syncthreads();

    const int wm = (w >> 2) * 16;
    const int wn = (w & 3) * 32;
    for (int c = 0; c < 8; c++) {
        if (c + 1 < 8) {
            unsigned nb = sb + AT_KV + ((c + 1) & 1) * 32768;
            attn_load_k(qh, ql, b, h, (c + 1) * 128, nb, nb + 16384, tid);
            CP_COMMIT();
        }
        unsigned bufH = sb + AT_KV + (c & 1) * 32768;
        unsigned bufL = bufH + 16384;
        float acc[4][4] = {};
        #pragma unroll
        for (int ks = 0; ks < 4; ks++) {
            int kb = ks * 32;
            unsigned aoff = SWZ128((unsigned)((wm + lrow) * 128 + kb + lcol));
            unsigned aH[4], aL[4];
            LDMX4(aH[0], aH[1], aH[2], aH[3], sb + AT_QH + aoff);
            LDMX4(aL[0], aL[1], aL[2], aL[3], sb + AT_QL + aoff);
            unsigned bH[2][4], bL[2][4];
            #pragma unroll
            for (int j2 = 0; j2 < 2; j2++) {
                unsigned boff = SWZ128((unsigned)((wn + j2 * 16 + lrow) * 128 + kb + lcol));
                LDMX4(bH[j2][0], bH[j2][1], bH[j2][2], bH[j2][3], bufH + boff);
                LDMX4(bL[j2][0], bL[j2][1], bL[j2][2], bL[j2][3], bufL + boff);
            }
            #pragma unroll
            for (int j = 0; j < 4; j++) {
                unsigned h0 = (j & 1) ? bH[j >> 1][1] : bH[j >> 1][0];
                unsigned h1 = (j & 1) ? bH[j >> 1][3] : bH[j >> 1][2];
                unsigned l0 = (j & 1) ? bL[j >> 1][1] : bL[j >> 1][0];
                unsigned l1 = (j & 1) ? bL[j >> 1][3] : bL[j >> 1][2];
                MMA16816(acc[j], aH, h0, h1);
                MMA16816(acc[j], aL, h0, h1);
                MMA16816(acc[j], aH, l0, l1);
            }
        }
        int r0 = wm + (lane >> 2);
        int cb = c * 128 + wn + (lane & 3) * 2;
        #pragma unroll
        for (int j = 0; j < 4; j++) {
            int col = cb + j * 8;
            unsigned lp0, lp1;
            unsigned hp0 = pack_hi2(acc[j][0] * 0.125f, acc[j][1] * 0.125f, lp0);
            unsigned hp1 = pack_hi2(acc[j][2] * 0.125f, acc[j][3] * 0.125f, lp1);
            unsigned o0 = (unsigned)(r0 * PSTRIDE + col * 2);
            unsigned o1 = (unsigned)((r0 + 8) * PSTRIDE + col * 2);
            *(unsigned*)(smem + o0) = hp0;
            *(unsigned*)(smem + AT_SPL + o0) = lp0;
            *(unsigned*)(smem + o1) = hp1;
            *(unsigned*)(smem + AT_SPL + o1) = lp1;
        }
        if (c + 1 < 8) { CP_WAIT0(); }
        __syncthreads();
    }

    attn_load_v(vTh, vTl, bh, 0, sb + AT_KV, tid);
    CP_COMMIT();

    for (int r = w; r < 32; r += 8) {
        float m = -1e30f;
        #pragma unroll 4
        for (int it = 0; it < 16; it++) {
            unsigned o = (unsigned)(r * PSTRIDE + it * 128 + lane * 4);
            unsigned uh = *(unsigned*)(smem + o);
            unsigned ul = *(unsigned*)(smem + AT_SPL + o);
            float l0 = bflo(uh) + bflo(ul);
            float l1 = bfhi(uh) + bfhi(ul);
            m = fmaxf(m, fmaxf(l0, l1));
        }
        #pragma unroll
        for (int o = 16; o > 0; o >>= 1) m = fmaxf(m, __shfl_xor_sync(0xFFFFFFFFu, m, o));
        float sum = 0.f;
        #pragma unroll 4
        for (int it = 0; it < 16; it++) {
            unsigned o = (unsigned)(r * PSTRIDE + it * 128 + lane * 4);
            unsigned uh = *(unsigned*)(smem + o);
            unsigned ul = *(unsigned*)(smem + AT_SPL + o);
            float e0 = __expf(bflo(uh) + bflo(ul) - m);
            float e1 = __expf(bfhi(uh) + bfhi(ul) - m);
            sum += e0 + e1;
            unsigned lp;
            unsigned hp = pack_hi2(e0, e1, lp);
            *(unsigned*)(smem + o) = hp;
            *(unsigned*)(smem + AT_SPL + o) = lp;
        }
        #pragma unroll
        for (int o = 16; o > 0; o >>= 1) sum += __shfl_xor_sync(0xFFFFFFFFu, sum, o);
        float inv = 1.0f / sum;
        if (lane == 0) sStat[r] = inv;
        size_t base = ((size_t)(bh * SS) + q0 + r) * SS;
        #pragma unroll 4
        for (int it = 0; it < 16; it++) {
            unsigned o = (unsigned)(r * PSTRIDE + it * 128 + lane * 4);
            unsigned uh = *(unsigned*)(smem + o);
            unsigned ul = *(unsigned*)(smem + AT_SPL + o);
            float v0 = (bflo(uh) + bflo(ul)) * inv;
            float v1 = (bfhi(uh) + bfhi(ul)) * inv;
            *(float2*)&attn_out[base + it * 64 + lane * 2] = make_float2(v0, v1);
        }
    }
    CP_WAIT0();
    __syncthreads();

    const int wmv = (w >> 2) * 16;
    const int wnv = (w & 3) * 16;
    float vac[2][4] = {};
    for (int c = 0; c < 8; c++) {
        if (c + 1 < 8) {
            attn_load_v(vTh, vTl, bh, (c + 1) * 128, sb + AT_KV + ((c + 1) & 1) * 32768, tid);
            CP_COMMIT();
        }
        unsigned vbase = sb + AT_KV + (c & 1) * 32768;
        #pragma unroll
        for (int ks = 0; ks < 8; ks++) {
            int s = ks >> 2;
            int kb = (ks & 3) * 32;
            unsigned ao = (unsigned)((wmv + lrow) * PSTRIDE + c * 256 + ks * 32 + lcol);
            unsigned aH[4], aL[4];
            LDMX4(aH[0], aH[1], aH[2], aH[3], sb + ao);
            LDMX4(aL[0], aL[1], aL[2], aL[3], sb + AT_SPL + ao);
            unsigned bo = SWZ128((unsigned)((wnv + lrow) * 128 + kb + lcol));
            unsigned bH[4], bL[4];
            LDMX4(bH[0], bH[1], bH[2], bH[3], vbase + s * 8192 + bo);
            LDMX4(bL[0], bL[1], bL[2], bL[3], vbase + 16384 + s * 8192 + bo);
            MMA16816(vac[0], aH, bH[0], bH[2]);
            MMA16816(vac[1], aH, bH[1], bH[3]);
            MMA16816(vac[0], aL, bH[0], bH[2]);
            MMA16816(vac[1], aL, bH[1], bH[3]);
            MMA16816(vac[0], aH, bL[0], bL[2]);
            MMA16816(vac[1], aH, bL[1], bL[3]);
        }
        if (c + 1 < 8) { CP_WAIT0(); }
        __syncthreads();
    }

    {
        int r0 = wmv + (lane >> 2);
        float inv0 = sStat[r0], inv1 = sStat[r0 + 8];
        int c0 = wnv + (lane & 3) * 2;
        #pragma unroll
        for (int j = 0; j < 2; j++) {
            int col = h * 64 + c0 + j * 8;
            size_t o0 = (size_t)(b * SS + q0 + r0) * DD + col;
            size_t o1 = (size_t)(b * SS + q0 + r0 + 8) * DD + col;
            unsigned l0, l1;
            unsigned h0 = pack_hi2(vac[j][0] * inv0, vac[j][1] * inv0, l0);
            unsigned h1 = pack_hi2(vac[j][2] * inv1, vac[j][3] * inv1, l1);
            *(unsigned*)&g_vhi[o0] = h0;
            *(unsigned*)&g_vlo[o0] = l0;
            *(unsigned*)&g_vhi[o1] = h1;
            *(unsigned*)&g_vlo[o1] = l1;
        }
    }
}

// ---------------------------------------------------------------------------
extern "C" void kernel_launch(void* const* d_in, const int* in_sizes, int n_in,
                              void* d_out, int out_size)
{
    const float* x     = (const float*)d_in[0];
    const float* W_qkv = (const float*)d_in[1];
    const float* b_qkv = (const float*)d_in[2];
    const float* W_o   = (const float*)d_in[3];
    const float* b_o   = (const float*)d_in[4];

    float* out_o    = (float*)d_out;
    float* out_attn = (float*)d_out + (size_t)BB * SS * DD;

    float* qkv_ptr;
    __nv_bfloat16 *xhi, *xlo, *wqh, *wql, *woh, *wol, *vhi, *vlo;
    __nv_bfloat16 *qhp, *qlp, *vthp, *vtlp;
    cudaGetSymbolAddress((void**)&qkv_ptr, g_qkv);
    cudaGetSymbolAddress((void**)&xhi, g_xhi);
    cudaGetSymbolAddress((void**)&xlo, g_xlo);
    cudaGetSymbolAddress((void**)&wqh, g_wqT_hi);
    cudaGetSymbolAddress((void**)&wql, g_wqT_lo);
    cudaGetSymbolAddress((void**)&woh, g_woT_hi);
    cudaGetSymbolAddress((void**)&wol, g_woT_lo);
    cudaGetSymbolAddress((void**)&vhi, g_vhi);
    cudaGetSymbolAddress((void**)&vlo, g_vlo);
    cudaGetSymbolAddress((void**)&qhp, g_qh);
    cudaGetSymbolAddress((void**)&qlp, g_ql);
    cudaGetSymbolAddress((void**)&vthp, g_vTh);
    cudaGetSymbolAddress((void**)&vtlp, g_vTl);

    cudaFuncSetAttribute(gemm3x_mma, cudaFuncAttributeMaxDynamicSharedMemorySize, GS_TOTAL);
    cudaFuncSetAttribute(attn_mma, cudaFuncAttributeMaxDynamicSharedMemorySize, AT_TOTAL);

    // 0) prep
    {
        int n4 = BB * SS * DD / 4;
        split_kernel<<<(n4 + 255) / 256, 256>>>(x, xhi, xlo, n4);
        dim3 g1(3 * DD / 32, DD / 32);
        tsplit_kernel<<<g1, dim3(32, 8)>>>(W_qkv, wqh, wql, DD, 3 * DD);
        dim3 g2(DD / 32, DD / 32);
        tsplit_kernel<<<g2, dim3(32, 8)>>>(W_o, woh, wol, DD, DD);
    }

    // 1) QKV projection (tensor) — epilogue also emits bf16 hi/lo
    {
        dim3 grid(3 * DD / 128, BB * SS / 128);
        gemm3x_mma<<<grid, 256, GS_TOTAL>>>(xhi, xlo, wqh, wql, b_qkv, qkv_ptr,
                                            qhp, qlp, BB * SS, 3 * DD, DD);
    }

    // 2) V^T split
    {
        dim3 gv(SS / 32, HDIM / 32, BB * HH);
        vT_kernel<<<gv, dim3(32, 8)>>>(qkv_ptr, vthp, vtlp);
    }

    // 3) fused tensorized attention
    {
        dim3 grid(SS / 32, HH, BB);
        attn_mma<<<grid, 256, AT_TOTAL>>>(qhp, qlp, vthp, vtlp, out_attn);
    }

    // 4) O-proj (tensor)
    {
        dim3 grid(DD / 128, BB * SS / 128);
        gemm3x_mma<<<grid, 256, GS_TOTAL>>>(vhi, vlo, woh, wol, b_o, out_o,
                                            (__nv_bfloat16*)nullptr, (__nv_bfloat16*)nullptr,
                                            BB * SS, DD, DD);
    }
}

// round 8
// speedup vs baseline: 1.0103x; 1.0103x over previous
#include <cuda_runtime.h>
#include <cuda_bf16.h>

#define BB 4
#define SS 1024
#define HH 16
#define HDIM 64
#define DD 1024

// ---------------------------------------------------------------------------
// scratch (device globals — no allocation allowed)
// ---------------------------------------------------------------------------
__device__ float g_qkv[BB * SS * 3 * DD];   // [B,S,3D] fp32 (for vT)
__device__ __nv_bfloat16 g_xhi[BB * SS * DD];
__device__ __nv_bfloat16 g_xlo[BB * SS * DD];
__device__ __nv_bfloat16 g_wqT_hi[3 * DD * DD];
__device__ __nv_bfloat16 g_wqT_lo[3 * DD * DD];
__device__ __nv_bfloat16 g_woT_hi[DD * DD];
__device__ __nv_bfloat16 g_woT_lo[DD * DD];
__device__ __nv_bfloat16 g_vhi[BB * SS * DD];   // values hi (attn epilogue)
__device__ __nv_bfloat16 g_vlo[BB * SS * DD];
__device__ __nv_bfloat16 g_qh[BB * SS * 3 * DD];   // qkv split hi (gemm epilogue)
__device__ __nv_bfloat16 g_ql[BB * SS * 3 * DD];
__device__ __nv_bfloat16 g_vTh[BB * HH * HDIM * SS]; // V^T per (b,h): [64][S]
__device__ __nv_bfloat16 g_vTl[BB * HH * HDIM * SS];

// ---------------------------------------------------------------------------
__device__ __forceinline__ unsigned smem_u32(const void* p) {
    unsigned a;
    asm("{ .reg .u64 t; cvta.to.shared.u64 t, %1; cvt.u32.u64 %0, t; }" : "=r"(a) : "l"(p));
    return a;
}
#define SWZ128(o) ((o) ^ (((o) >> 3) & 0x70))
#define SWZ64(o)  ((o) ^ (((o) >> 3) & 0x30))

#define CP_ASYNC16(saddr, gptr) \
    asm volatile("cp.async.cg.shared.global [%0], [%1], 16;" :: "r"(saddr), "l"(gptr) : "memory")
#define CP_COMMIT() asm volatile("cp.async.commit_group;" ::: "memory")
#define CP_WAIT1()  asm volatile("cp.async.wait_group 1;" ::: "memory")
#define CP_WAIT0()  asm volatile("cp.async.wait_group 0;" ::: "memory")

#define LDMX4(r0, r1, r2, r3, a) \
    asm volatile("ldmatrix.sync.aligned.m8n8.x4.shared.b16 {%0,%1,%2,%3}, [%4];" \
        : "=r"(r0), "=r"(r1), "=r"(r2), "=r"(r3) : "r"(a))

#define MMA16816(d, a, b0, b1) \
    asm volatile("mma.sync.aligned.m16n8k16.row.col.f32.bf16.bf16.f32 " \
        "{%0,%1,%2,%3}, {%4,%5,%6,%7}, {%8,%9}, {%0,%1,%2,%3};" \
        : "+f"((d)[0]), "+f"((d)[1]), "+f"((d)[2]), "+f"((d)[3]) \
        : "r"((a)[0]), "r"((a)[1]), "r"((a)[2]), "r"((a)[3]), "r"(b0), "r"(b1))

__device__ __forceinline__ unsigned pack_hi2(float x, float y, unsigned& lo) {
    __nv_bfloat16 hx = __float2bfloat16(x);
    __nv_bfloat16 hy = __float2bfloat16(y);
    __nv_bfloat16 lx = __float2bfloat16(x - __bfloat162float(hx));
    __nv_bfloat16 ly = __float2bfloat16(y - __bfloat162float(hy));
    lo = ((unsigned)__bfloat16_as_ushort(ly) << 16) | __bfloat16_as_ushort(lx);
    return ((unsigned)__bfloat16_as_ushort(hy) << 16) | __bfloat16_as_ushort(hx);
}
__device__ __forceinline__ float bflo(unsigned u) {
    return __bfloat162float(__ushort_as_bfloat16((unsigned short)(u & 0xFFFF)));
}
__device__ __forceinline__ float bfhi(unsigned u) {
    return __bfloat162float(__ushort_as_bfloat16((unsigned short)(u >> 16)));
}

// ---------------------------------------------------------------------------
__global__ __launch_bounds__(256) void split_kernel(
    const float* __restrict__ src, __nv_bfloat16* __restrict__ hi,
    __nv_bfloat16* __restrict__ lo, int n4)
{
    int i = blockIdx.x * 256 + threadIdx.x;
    if (i >= n4) return;
    float4 v = ((const float4*)src)[i];
    unsigned l0, l1, h0, h1;
    h0 = pack_hi2(v.x, v.y, l0);
    h1 = pack_hi2(v.z, v.w, l1);
    ((uint2*)hi)[i] = make_uint2(h0, h1);
    ((uint2*)lo)[i] = make_uint2(l0, l1);
}

__global__ __launch_bounds__(256) void tsplit_kernel(
    const float* __restrict__ W, __nv_bfloat16* __restrict__ hiT,
    __nv_bfloat16* __restrict__ loT, int K, int N)
{
    __shared__ float t[32][33];
    int k0 = blockIdx.y * 32, n0 = blockIdx.x * 32;
    int tx = threadIdx.x, ty = threadIdx.y;
    #pragma unroll
    for (int i = 0; i < 32; i += 8)
        t[ty + i][tx] = W[(size_t)(k0 + ty + i) * N + n0 + tx];
    __syncthreads();
    #pragma unroll
    for (int i = 0; i < 32; i += 8) {
        float v = t[tx][ty + i];
        __nv_bfloat16 h = __float2bfloat16(v);
        size_t o = (size_t)(n0 + ty + i) * K + k0 + tx;
        hiT[o] = h;
        loT[o] = __float2bfloat16(v - __bfloat162float(h));
    }
}

__global__ __launch_bounds__(256) void vT_kernel(
    const float* __restrict__ qkv, __nv_bfloat16* __restrict__ vTh,
    __nv_bfloat16* __restrict__ vTl)
{
    __shared__ float t[32][33];
    int s0 = blockIdx.x * 32, d0 = blockIdx.y * 32, bh = blockIdx.z;
    int b = bh >> 4, h = bh & 15;
    int tx = threadIdx.x, ty = threadIdx.y;
    #pragma unroll
    for (int i = 0; i < 32; i += 8)
        t[ty + i][tx] = qkv[(size_t)(b * SS + s0 + ty + i) * 3072 + h * 192 + 128 + d0 + tx];
    __syncthreads();
    #pragma unroll
    for (int i = 0; i < 32; i += 8) {
        float v = t[tx][ty + i];
        __nv_bfloat16 hh = __float2bfloat16(v);
        size_t o = (size_t)(bh * HDIM + d0 + ty + i) * SS + s0 + tx;
        vTh[o] = hh;
        vTl[o] = __float2bfloat16(v - __bfloat162float(hh));
    }
}

// ---------------------------------------------------------------------------
// Combined-pass GEMM: 128 threads, 4 warps, warp tile 64x64 (block 128x128).
// Per K-chunk(32) stage holds Ahi|Alo|BThi|BTlo (8KB each). SWZ64.
// 3 stages, depth-2 lookahead.
// ---------------------------------------------------------------------------
#define GS_STAGE 32768
#define GS_TOTAL 98304

__device__ __forceinline__ void gload64(const __nv_bfloat16* __restrict__ src,
                                        int rbase, int K, int kt, unsigned dst, int tid)
{
    #pragma unroll
    for (int i = 0; i < 4; i++) {
        int idx = tid + i * 128;
        int row = idx >> 2;
        int c16 = (idx & 3) * 16;
        CP_ASYNC16(dst + SWZ64((unsigned)(row * 64 + c16)),
                   (const char*)(src + (size_t)(rbase + row) * K + kt) + c16);
    }
}

__device__ __forceinline__ void prefetch_chunk(
    const __nv_bfloat16* __restrict__ Ahi, const __nv_bfloat16* __restrict__ Alo,
    const __nv_bfloat16* __restrict__ BThi, const __nv_bfloat16* __restrict__ BTlo,
    int brow, int bcol, int K, int kt, unsigned stage, int tid)
{
    gload64(Ahi, brow, K, kt, stage, tid);
    gload64(Alo, brow, K, kt, stage + 8192, tid);
    gload64(BThi, bcol, K, kt, stage + 16384, tid);
    gload64(BTlo, bcol, K, kt, stage + 24576, tid);
}

__global__ __launch_bounds__(128, 2) void gemm3x_mma(
    const __nv_bfloat16* __restrict__ Ahi, const __nv_bfloat16* __restrict__ Alo,
    const __nv_bfloat16* __restrict__ BThi, const __nv_bfloat16* __restrict__ BTlo,
    const float* __restrict__ bias, float* __restrict__ C,
    __nv_bfloat16* __restrict__ Chi, __nv_bfloat16* __restrict__ Clo,
    int M, int N, int K)
{
    extern __shared__ char smem[];
    unsigned sb = smem_u32(smem);
    const int tid = threadIdx.x, w = tid >> 5, lane = tid & 31;
    const int brow = blockIdx.y * 128, bcol = blockIdx.x * 128;
    const int wm = (w >> 1) * 64;      // 0 or 64
    const int wn = (w & 1) * 64;       // 0 or 64
    const int lrow = lane & 15;
    const int lcol = (lane >> 4) * 16;

    const int nch = K >> 5;   // 32

    float acc[4][8][4] = {};

    prefetch_chunk(Ahi, Alo, BThi, BTlo, brow, bcol, K, 0, sb, tid);
    CP_COMMIT();
    prefetch_chunk(Ahi, Alo, BThi, BTlo, brow, bcol, K, 32, sb + GS_STAGE, tid);
    CP_COMMIT();
    CP_WAIT1();
    __syncthreads();

    int s_cur = 0;
    for (int c = 0; c < nch; c++) {
        if (c + 2 < nch) {
            int s2 = s_cur + 2; if (s2 >= 3) s2 -= 3;
            prefetch_chunk(Ahi, Alo, BThi, BTlo, brow, bcol, K, (c + 2) << 5,
                           sb + s2 * GS_STAGE, tid);
            CP_COMMIT();
        }

        unsigned base = sb + s_cur * GS_STAGE;
        #pragma unroll
        for (int ks = 0; ks < 2; ks++) {
            int kb = ks * 32;
            unsigned bH[4][4], bL[4][4];
            #pragma unroll
            for (int j2 = 0; j2 < 4; j2++) {
                unsigned off = (unsigned)((wn + j2 * 16 + lrow) * 64 + kb + lcol);
                LDMX4(bH[j2][0], bH[j2][1], bH[j2][2], bH[j2][3], base + 16384 + SWZ64(off));
                LDMX4(bL[j2][0], bL[j2][1], bL[j2][2], bL[j2][3], base + 24576 + SWZ64(off));
            }
            #pragma unroll
            for (int i = 0; i < 4; i++) {
                unsigned off = (unsigned)((wm + i * 16 + lrow) * 64 + kb + lcol);
                unsigned aH[4], aL[4];
                LDMX4(aH[0], aH[1], aH[2], aH[3], base + SWZ64(off));
                LDMX4(aL[0], aL[1], aL[2], aL[3], base + 8192 + SWZ64(off));
                #pragma unroll
                for (int j = 0; j < 8; j++) {
                    unsigned h0 = (j & 1) ? bH[j >> 1][1] : bH[j >> 1][0];
                    unsigned h1 = (j & 1) ? bH[j >> 1][3] : bH[j >> 1][2];
                    unsigned l0 = (j & 1) ? bL[j >> 1][1] : bL[j >> 1][0];
                    unsigned l1 = (j & 1) ? bL[j >> 1][3] : bL[j >> 1][2];
                    MMA16816(acc[i][j], aH, h0, h1);
                    MMA16816(acc[i][j], aL, h0, h1);
                    MMA16816(acc[i][j], aH, l0, l1);
                }
            }
        }

        if (c + 1 < nch) {
            if (c + 2 < nch) { CP_WAIT1(); } else { CP_WAIT0(); }
        }
        __syncthreads();
        if (++s_cur == 3) s_cur = 0;
    }

    const int r0 = brow + wm + (lane >> 2);
    const int c0 = bcol + wn + (lane & 3) * 2;
    #pragma unroll
    for (int i = 0; i < 4; i++) {
        #pragma unroll
        for (int j = 0; j < 8; j++) {
            int col = c0 + j * 8;
            float bx = bias[col], by = bias[col + 1];
            float v00 = acc[i][j][0] + bx, v01 = acc[i][j][1] + by;
            float v10 = acc[i][j][2] + bx, v11 = acc[i][j][3] + by;
            size_t o0 = (size_t)(r0 + i * 16) * N + col;
            size_t o1 = (size_t)(r0 + i * 16 + 8) * N + col;
            *(float2*)&C[o0] = make_float2(v00, v01);
            *(float2*)&C[o1] = make_float2(v10, v11);
            if (Chi) {
                unsigned l0, l1;
                unsigned h0 = pack_hi2(v00, v01, l0);
                unsigned h1 = pack_hi2(v10, v11, l1);
                *(unsigned*)&Chi[o0] = h0;
                *(unsigned*)&Clo[o0] = l0;
                *(unsigned*)&Chi[o1] = h1;
                *(unsigned*)&Clo[o1] = l1;
            }
        }
    }
}

// ---------------------------------------------------------------------------
// Attention (unchanged from R6): packed bf16 hi/lo logits, PSTRIDE-padded.
// ---------------------------------------------------------------------------
#define AT_SPL  66048
#define AT_STAT 132096
#define AT_QH   132224
#define AT_QL   136320
#define AT_KV   140416
#define AT_TOTAL 205952
#define PSTRIDE 2064

__device__ __forceinline__ void attn_load_k(
    const __nv_bfloat16* __restrict__ qh, const __nv_bfloat16* __restrict__ ql,
    int b, int h, int kb, unsigned dstH, unsigned dstL, int tid)
{
    #pragma unroll
    for (int i = 0; i < 4; i++) {
        int idx = tid + i * 256;
        int row = idx >> 3, c16 = (idx & 7) * 16;
        unsigned so = SWZ128((unsigned)(row * 128 + c16));
        CP_ASYNC16(dstH + so, (const char*)(qh + (size_t)(b * SS + kb + row) * 3072 + h * 192 + 64) + c16);
        CP_ASYNC16(dstL + so, (const char*)(ql + (size_t)(b * SS + kb + row) * 3072 + h * 192 + 64) + c16);
    }
}

__device__ __forceinline__ void attn_load_v(
    const __nv_bfloat16* __restrict__ vTh, const __nv_bfloat16* __restrict__ vTl,
    int bh, int kb, unsigned dst, int tid)
{
    #pragma unroll
    for (int s = 0; s < 2; s++) {
        #pragma unroll
        for (int i = 0; i < 2; i++) {
            int idx = tid + i * 256;
            int row = idx >> 3, c16 = (idx & 7) * 16;
            unsigned so = SWZ128((unsigned)(row * 128 + c16));
            const char* gh = (const char*)(vTh + (size_t)(bh * HDIM + row) * SS + kb + s * 64) + c16;
            const char* gl = (const char*)(vTl + (size_t)(bh * HDIM + row) * SS + kb + s * 64) + c16;
            CP_ASYNC16(dst + s * 8192 + so, gh);
            CP_ASYNC16(dst + 16384 + s * 8192 + so, gl);
        }
    }
}

__global__ __launch_bounds__(256) void attn_mma(
    const __nv_bfloat16* __restrict__ qh, const __nv_bfloat16* __restrict__ ql,
    const __nv_bfloat16* __restrict__ vTh, const __nv_bfloat16* __restrict__ vTl,
    float* __restrict__ attn_out)
{
    extern __shared__ char smem[];
    unsigned sb = smem_u32(smem);
    float* sStat = (float*)(smem + AT_STAT);

    const int qt = blockIdx.x, h = blockIdx.y, b = blockIdx.z;
    const int bh = b * HH + h;
    const int q0 = qt * 32;
    const int tid = threadIdx.x, w = tid >> 5, lane = tid & 31;
    const int lrow = lane & 15, lcol = (lane >> 4) * 16;

    {
        int row = tid >> 3, c16 = (tid & 7) * 16;
        unsigned so = SWZ128((unsigned)(row * 128 + c16));
        CP_ASYNC16(sb + AT_QH + so, (const char*)(qh + (size_t)(b * SS + q0 + row) * 3072 + h * 192) + c16);
        CP_ASYNC16(sb + AT_QL + so, (const char*)(ql + (size_t)(b * SS + q0 + row) * 3072 + h * 192) + c16);
    }
    attn_load_k(qh, ql, b, h, 0, sb + AT_KV, sb + AT_KV + 16384, tid);
    CP_COMMIT();
    CP_WAIT0();
    __syncthreads();

    const int wm = (w >> 2) * 16;
    const int wn = (w & 3) * 32;
    for (int c = 0; c < 8; c++) {
        if (c + 1 < 8) {
            unsigned nb = sb + AT_KV + ((c + 1) & 1) * 32768;
            attn_load_k(qh, ql, b, h, (c + 1) * 128, nb, nb + 16384, tid);
            CP_COMMIT();
        }
        unsigned bufH = sb + AT_KV + (c & 1) * 32768;
        unsigned bufL = bufH + 16384;
        float acc[4][4] = {};
        #pragma unroll
        for (int ks = 0; ks < 4; ks++) {
            int kb = ks * 32;
            unsigned aoff = SWZ128((unsigned)((wm + lrow) * 128 + kb + lcol));
            unsigned aH[4], aL[4];
            LDMX4(aH[0], aH[1], aH[2], aH[3], sb + AT_QH + aoff);
            LDMX4(aL[0], aL[1], aL[2], aL[3], sb + AT_QL + aoff);
            unsigned bH[2][4], bL[2][4];
            #pragma unroll
            for (int j2 = 0; j2 < 2; j2++) {
                unsigned boff = SWZ128((unsigned)((wn + j2 * 16 + lrow) * 128 + kb + lcol));
                LDMX4(bH[j2][0], bH[j2][1], bH[j2][2], bH[j2][3], bufH + boff);
                LDMX4(bL[j2][0], bL[j2][1], bL[j2][2], bL[j2][3], bufL + boff);
            }
            #pragma unroll
            for (int j = 0; j < 4; j++) {
                unsigned h0 = (j & 1) ? bH[j >> 1][1] : bH[j >> 1][0];
                unsigned h1 = (j & 1) ? bH[j >> 1][3] : bH[j >> 1][2];
                unsigned l0 = (j & 1) ? bL[j >> 1][1] : bL[j >> 1][0];
                unsigned l1 = (j & 1) ? bL[j >> 1][3] : bL[j >> 1][2];
                MMA16816(acc[j], aH, h0, h1);
                MMA16816(acc[j], aL, h0, h1);
                MMA16816(acc[j], aH, l0, l1);
            }
        }
        int r0 = wm + (lane >> 2);
        int cb = c * 128 + wn + (lane & 3) * 2;
        #pragma unroll
        for (int j = 0; j < 4; j++) {
            int col = cb + j * 8;
            unsigned lp0, lp1;
            unsigned hp0 = pack_hi2(acc[j][0] * 0.125f, acc[j][1] * 0.125f, lp0);
            unsigned hp1 = pack_hi2(acc[j][2] * 0.125f, acc[j][3] * 0.125f, lp1);
            unsigned o0 = (unsigned)(r0 * PSTRIDE + col * 2);
            unsigned o1 = (unsigned)((r0 + 8) * PSTRIDE + col * 2);
            *(unsigned*)(smem + o0) = hp0;
            *(unsigned*)(smem + AT_SPL + o0) = lp0;
            *(unsigned*)(smem + o1) = hp1;
            *(unsigned*)(smem + AT_SPL + o1) = lp1;
        }
        if (c + 1 < 8) { CP_WAIT0(); }
        __syncthreads();
    }

    attn_load_v(vTh, vTl, bh, 0, sb + AT_KV, tid);
    CP_COMMIT();

    for (int r = w; r < 32; r += 8) {
        float m = -1e30f;
        #pragma unroll 4
        for (int it = 0; it < 16; it++) {
            unsigned o = (unsigned)(r * PSTRIDE + it * 128 + lane * 4);
            unsigned uh = *(unsigned*)(smem + o);
            unsigned ul = *(unsigned*)(smem + AT_SPL + o);
            float l0 = bflo(uh) + bflo(ul);
            float l1 = bfhi(uh) + bfhi(ul);
            m = fmaxf(m, fmaxf(l0, l1));
        }
        #pragma unroll
        for (int o = 16; o > 0; o >>= 1) m = fmaxf(m, __shfl_xor_sync(0xFFFFFFFFu, m, o));
        float sum = 0.f;
        #pragma unroll 4
        for (int it = 0; it < 16; it++) {
            unsigned o = (unsigned)(r * PSTRIDE + it * 128 + lane * 4);
            unsigned uh = *(unsigned*)(smem + o);
            unsigned ul = *(unsigned*)(smem + AT_SPL + o);
            float e0 = __expf(bflo(uh) + bflo(ul) - m);
            float e1 = __expf(bfhi(uh) + bfhi(ul) - m);
            sum += e0 + e1;
            unsigned lp;
            unsigned hp = pack_hi2(e0, e1, lp);
            *(unsigned*)(smem + o) = hp;
            *(unsigned*)(smem + AT_SPL + o) = lp;
        }
        #pragma unroll
        for (int o = 16; o > 0; o >>= 1) sum += __shfl_xor_sync(0xFFFFFFFFu, sum, o);
        float inv = 1.0f / sum;
        if (lane == 0) sStat[r] = inv;
        size_t base = ((size_t)(bh * SS) + q0 + r) * SS;
        #pragma unroll 4
        for (int it = 0; it < 16; it++) {
            unsigned o = (unsigned)(r * PSTRIDE + it * 128 + lane * 4);
            unsigned uh = *(unsigned*)(smem + o);
            unsigned ul = *(unsigned*)(smem + AT_SPL + o);
            float v0 = (bflo(uh) + bflo(ul)) * inv;
            float v1 = (bfhi(uh) + bfhi(ul)) * inv;
            *(float2*)&attn_out[base + it * 64 + lane * 2] = make_float2(v0, v1);
        }
    }
    CP_WAIT0();
    __syncthreads();

    const int wmv = (w >> 2) * 16;
    const int wnv = (w & 3) * 16;
    float vac[2][4] = {};
    for (int c = 0; c < 8; c++) {
        if (c + 1 < 8) {
            attn_load_v(vTh, vTl, bh, (c + 1) * 128, sb + AT_KV + ((c + 1) & 1) * 32768, tid);
            CP_COMMIT();
        }
        unsigned vbase = sb + AT_KV + (c & 1) * 32768;
        #pragma unroll
        for (int ks = 0; ks < 8; ks++) {
            int s = ks >> 2;
            int kb = (ks & 3) * 32;
            unsigned ao = (unsigned)((wmv + lrow) * PSTRIDE + c * 256 + ks * 32 + lcol);
            unsigned aH[4], aL[4];
            LDMX4(aH[0], aH[1], aH[2], aH[3], sb + ao);
            LDMX4(aL[0], aL[1], aL[2], aL[3], sb + AT_SPL + ao);
            unsigned bo = SWZ128((unsigned)((wnv + lrow) * 128 + kb + lcol));
            unsigned bH[4], bL[4];
            LDMX4(bH[0], bH[1], bH[2], bH[3], vbase + s * 8192 + bo);
            LDMX4(bL[0], bL[1], bL[2], bL[3], vbase + 16384 + s * 8192 + bo);
            MMA16816(vac[0], aH, bH[0], bH[2]);
            MMA16816(vac[1], aH, bH[1], bH[3]);
            MMA16816(vac[0], aL, bH[0], bH[2]);
            MMA16816(vac[1], aL, bH[1], bH[3]);
            MMA16816(vac[0], aH, bL[0], bL[2]);
            MMA16816(vac[1], aH, bL[1], bL[3]);
        }
        if (c + 1 < 8) { CP_WAIT0(); }
        __syncthreads();
    }

    {
        int r0 = wmv + (lane >> 2);
        float inv0 = sStat[r0], inv1 = sStat[r0 + 8];
        int c0 = wnv + (lane & 3) * 2;
        #pragma unroll
        for (int j = 0; j < 2; j++) {
            int col = h * 64 + c0 + j * 8;
            size_t o0 = (size_t)(b * SS + q0 + r0) * DD + col;
            size_t o1 = (size_t)(b * SS + q0 + r0 + 8) * DD + col;
            unsigned l0, l1;
            unsigned h0 = pack_hi2(vac[j][0] * inv0, vac[j][1] * inv0, l0);
            unsigned h1 = pack_hi2(vac[j][2] * inv1, vac[j][3] * inv1, l1);
            *(unsigned*)&g_vhi[o0] = h0;
            *(unsigned*)&g_vlo[o0] = l0;
            *(unsigned*)&g_vhi[o1] = h1;
            *(unsigned*)&g_vlo[o1] = l1;
        }
    }
}

// ---------------------------------------------------------------------------
extern "C" void kernel_launch(void* const* d_in, const int* in_sizes, int n_in,
                              void* d_out, int out_size)
{
    const float* x     = (const float*)d_in[0];
    const float* W_qkv = (const float*)d_in[1];
    const float* b_qkv = (const float*)d_in[2];
    const float* W_o   = (const float*)d_in[3];
    const float* b_o   = (const float*)d_in[4];

    float* out_o    = (float*)d_out;
    float* out_attn = (float*)d_out + (size_t)BB * SS * DD;

    float* qkv_ptr;
    __nv_bfloat16 *xhi, *xlo, *wqh, *wql, *woh, *wol, *vhi, *vlo;
    __nv_bfloat16 *qhp, *qlp, *vthp, *vtlp;
    cudaGetSymbolAddress((void**)&qkv_ptr, g_qkv);
    cudaGetSymbolAddress((void**)&xhi, g_xhi);
    cudaGetSymbolAddress((void**)&xlo, g_xlo);
    cudaGetSymbolAddress((void**)&wqh, g_wqT_hi);
    cudaGetSymbolAddress((void**)&wql, g_wqT_lo);
    cudaGetSymbolAddress((void**)&woh, g_woT_hi);
    cudaGetSymbolAddress((void**)&wol, g_woT_lo);
    cudaGetSymbolAddress((void**)&vhi, g_vhi);
    cudaGetSymbolAddress((void**)&vlo, g_vlo);
    cudaGetSymbolAddress((void**)&qhp, g_qh);
    cudaGetSymbolAddress((void**)&qlp, g_ql);
    cudaGetSymbolAddress((void**)&vthp, g_vTh);
    cudaGetSymbolAddress((void**)&vtlp, g_vTl);

    cudaFuncSetAttribute(gemm3x_mma, cudaFuncAttributeMaxDynamicSharedMemorySize, GS_TOTAL);
    cudaFuncSetAttribute(attn_mma, cudaFuncAttributeMaxDynamicSharedMemorySize, AT_TOTAL);

    // 0) prep
    {
        int n4 = BB * SS * DD / 4;
        split_kernel<<<(n4 + 255) / 256, 256>>>(x, xhi, xlo, n4);
        dim3 g1(3 * DD / 32, DD / 32);
        tsplit_kernel<<<g1, dim3(32, 8)>>>(W_qkv, wqh, wql, DD, 3 * DD);
        dim3 g2(DD / 32, DD / 32);
        tsplit_kernel<<<g2, dim3(32, 8)>>>(W_o, woh, wol, DD, DD);
    }

    // 1) QKV projection (tensor) — epilogue also emits bf16 hi/lo
    {
        dim3 grid(3 * DD / 128, BB * SS / 128);
        gemm3x_mma<<<grid, 128, GS_TOTAL>>>(xhi, xlo, wqh, wql, b_qkv, qkv_ptr,
                                            qhp, qlp, BB * SS, 3 * DD, DD);
    }

    // 2) V^T split
    {
        dim3 gv(SS / 32, HDIM / 32, BB * HH);
        vT_kernel<<<gv, dim3(32, 8)>>>(qkv_ptr, vthp, vtlp);
    }

    // 3) fused tensorized attention
    {
        dim3 grid(SS / 32, HH, BB);
        attn_mma<<<grid, 256, AT_TOTAL>>>(qhp, qlp, vthp, vtlp, out_attn);
    }

    // 4) O-proj (tensor)
    {
        dim3 grid(DD / 128, BB * SS / 128);
        gemm3x_mma<<<grid, 128, GS_TOTAL>>>(vhi, vlo, woh, wol, b_o, out_o,
                                            (__nv_bfloat16*)nullptr, (__nv_bfloat16*)nullptr,
                                            BB * SS, DD, DD);
    }
}

// round 9
// speedup vs baseline: 1.0419x; 1.0313x over previous
#include <cuda_runtime.h>
#include <cuda_bf16.h>
#include <cuda_fp16.h>

#define BB 4
#define SS 1024
#define HH 16
#define HDIM 64
#define DD 1024

// ---------------------------------------------------------------------------
// scratch (device globals — no allocation allowed)
// ---------------------------------------------------------------------------
__device__ float g_qkv[BB * SS * 3 * DD];   // [B,S,3D] fp32 (for vT)
__device__ __nv_bfloat16 g_xhi[BB * SS * DD];
__device__ __nv_bfloat16 g_xlo[BB * SS * DD];
__device__ __nv_bfloat16 g_wqT_hi[3 * DD * DD];
__device__ __nv_bfloat16 g_wqT_lo[3 * DD * DD];
__device__ __nv_bfloat16 g_woT_hi[DD * DD];
__device__ __nv_bfloat16 g_woT_lo[DD * DD];
__device__ __nv_bfloat16 g_vhi[BB * SS * DD];   // values hi (av epilogue)
__device__ __nv_bfloat16 g_vlo[BB * SS * DD];
__device__ __nv_bfloat16 g_qh[BB * SS * 3 * DD];   // qkv split hi (gemm epilogue)
__device__ __nv_bfloat16 g_ql[BB * SS * 3 * DD];
__device__ __half g_vTh[BB * HH * HDIM * SS]; // V^T fp16 per (b,h): [64][S]
__device__ __half g_vTl[BB * HH * HDIM * SS];
__device__ __half g_p[(size_t)BB * HH * SS * SS]; // normalized attention fp16

// ---------------------------------------------------------------------------
__device__ __forceinline__ unsigned smem_u32(const void* p) {
    unsigned a;
    asm("{ .reg .u64 t; cvta.to.shared.u64 t, %1; cvt.u32.u64 %0, t; }" : "=r"(a) : "l"(p));
    return a;
}
#define SWZ128(o) ((o) ^ (((o) >> 3) & 0x70))
#define SWZ64(o)  ((o) ^ (((o) >> 3) & 0x30))

#define CP_ASYNC16(saddr, gptr) \
    asm volatile("cp.async.cg.shared.global [%0], [%1], 16;" :: "r"(saddr), "l"(gptr) : "memory")
#define CP_COMMIT() asm volatile("cp.async.commit_group;" ::: "memory")
#define CP_WAIT1()  asm volatile("cp.async.wait_group 1;" ::: "memory")
#define CP_WAIT0()  asm volatile("cp.async.wait_group 0;" ::: "memory")

#define LDMX4(r0, r1, r2, r3, a) \
    asm volatile("ldmatrix.sync.aligned.m8n8.x4.shared.b16 {%0,%1,%2,%3}, [%4];" \
        : "=r"(r0), "=r"(r1), "=r"(r2), "=r"(r3) : "r"(a))

#define MMA16816(d, a, b0, b1) \
    asm volatile("mma.sync.aligned.m16n8k16.row.col.f32.bf16.bf16.f32 " \
        "{%0,%1,%2,%3}, {%4,%5,%6,%7}, {%8,%9}, {%0,%1,%2,%3};" \
        : "+f"((d)[0]), "+f"((d)[1]), "+f"((d)[2]), "+f"((d)[3]) \
        : "r"((a)[0]), "r"((a)[1]), "r"((a)[2]), "r"((a)[3]), "r"(b0), "r"(b1))

#define MMAF16(d, a, b0, b1) \
    asm volatile("mma.sync.aligned.m16n8k16.row.col.f32.f16.f16.f32 " \
        "{%0,%1,%2,%3}, {%4,%5,%6,%7}, {%8,%9}, {%0,%1,%2,%3};" \
        : "+f"((d)[0]), "+f"((d)[1]), "+f"((d)[2]), "+f"((d)[3]) \
        : "r"((a)[0]), "r"((a)[1]), "r"((a)[2]), "r"((a)[3]), "r"(b0), "r"(b1))

__device__ __forceinline__ unsigned pack_hi2(float x, float y, unsigned& lo) {
    __nv_bfloat16 hx = __float2bfloat16(x);
    __nv_bfloat16 hy = __float2bfloat16(y);
    __nv_bfloat16 lx = __float2bfloat16(x - __bfloat162float(hx));
    __nv_bfloat16 ly = __float2bfloat16(y - __bfloat162float(hy));
    lo = ((unsigned)__bfloat16_as_ushort(ly) << 16) | __bfloat16_as_ushort(lx);
    return ((unsigned)__bfloat16_as_ushort(hy) << 16) | __bfloat16_as_ushort(hx);
}
__device__ __forceinline__ float bflo(unsigned u) {
    return __bfloat162float(__ushort_as_bfloat16((unsigned short)(u & 0xFFFF)));
}
__device__ __forceinline__ float bfhi(unsigned u) {
    return __bfloat162float(__ushort_as_bfloat16((unsigned short)(u >> 16)));
}

// ---------------------------------------------------------------------------
__global__ __launch_bounds__(256) void split_kernel(
    const float* __restrict__ src, __nv_bfloat16* __restrict__ hi,
    __nv_bfloat16* __restrict__ lo, int n4)
{
    int i = blockIdx.x * 256 + threadIdx.x;
    if (i >= n4) return;
    float4 v = ((const float4*)src)[i];
    unsigned l0, l1, h0, h1;
    h0 = pack_hi2(v.x, v.y, l0);
    h1 = pack_hi2(v.z, v.w, l1);
    ((uint2*)hi)[i] = make_uint2(h0, h1);
    ((uint2*)lo)[i] = make_uint2(l0, l1);
}

__global__ __launch_bounds__(256) void tsplit_kernel(
    const float* __restrict__ W, __nv_bfloat16* __restrict__ hiT,
    __nv_bfloat16* __restrict__ loT, int K, int N)
{
    __shared__ float t[32][33];
    int k0 = blockIdx.y * 32, n0 = blockIdx.x * 32;
    int tx = threadIdx.x, ty = threadIdx.y;
    #pragma unroll
    for (int i = 0; i < 32; i += 8)
        t[ty + i][tx] = W[(size_t)(k0 + ty + i) * N + n0 + tx];
    __syncthreads();
    #pragma unroll
    for (int i = 0; i < 32; i += 8) {
        float v = t[tx][ty + i];
        __nv_bfloat16 h = __float2bfloat16(v);
        size_t o = (size_t)(n0 + ty + i) * K + k0 + tx;
        hiT[o] = h;
        loT[o] = __float2bfloat16(v - __bfloat162float(h));
    }
}

// V^T + split to fp16: qkv V slice -> vT hi/lo [bh][64][S]
__global__ __launch_bounds__(256) void vT_kernel(
    const float* __restrict__ qkv, __half* __restrict__ vTh,
    __half* __restrict__ vTl)
{
    __shared__ float t[32][33];
    int s0 = blockIdx.x * 32, d0 = blockIdx.y * 32, bh = blockIdx.z;
    int b = bh >> 4, h = bh & 15;
    int tx = threadIdx.x, ty = threadIdx.y;
    #pragma unroll
    for (int i = 0; i < 32; i += 8)
        t[ty + i][tx] = qkv[(size_t)(b * SS + s0 + ty + i) * 3072 + h * 192 + 128 + d0 + tx];
    __syncthreads();
    #pragma unroll
    for (int i = 0; i < 32; i += 8) {
        float v = t[tx][ty + i];
        __half hh = __float2half(v);
        size_t o = (size_t)(bh * HDIM + d0 + ty + i) * SS + s0 + tx;
        vTh[o] = hh;
        vTl[o] = __float2half(v - __half2float(hh));
    }
}

// ---------------------------------------------------------------------------
// Combined-pass GEMM (unchanged from R8): 128 threads, warp tile 64x64.
// ---------------------------------------------------------------------------
#define GS_STAGE 32768
#define GS_TOTAL 98304

__device__ __forceinline__ void gload64(const __nv_bfloat16* __restrict__ src,
                                        int rbase, int K, int kt, unsigned dst, int tid)
{
    #pragma unroll
    for (int i = 0; i < 4; i++) {
        int idx = tid + i * 128;
        int row = idx >> 2;
        int c16 = (idx & 3) * 16;
        CP_ASYNC16(dst + SWZ64((unsigned)(row * 64 + c16)),
                   (const char*)(src + (size_t)(rbase + row) * K + kt) + c16);
    }
}

__device__ __forceinline__ void prefetch_chunk(
    const __nv_bfloat16* __restrict__ Ahi, const __nv_bfloat16* __restrict__ Alo,
    const __nv_bfloat16* __restrict__ BThi, const __nv_bfloat16* __restrict__ BTlo,
    int brow, int bcol, int K, int kt, unsigned stage, int tid)
{
    gload64(Ahi, brow, K, kt, stage, tid);
    gload64(Alo, brow, K, kt, stage + 8192, tid);
    gload64(BThi, bcol, K, kt, stage + 16384, tid);
    gload64(BTlo, bcol, K, kt, stage + 24576, tid);
}

__global__ __launch_bounds__(128, 2) void gemm3x_mma(
    const __nv_bfloat16* __restrict__ Ahi, const __nv_bfloat16* __restrict__ Alo,
    const __nv_bfloat16* __restrict__ BThi, const __nv_bfloat16* __restrict__ BTlo,
    const float* __restrict__ bias, float* __restrict__ C,
    __nv_bfloat16* __restrict__ Chi, __nv_bfloat16* __restrict__ Clo,
    int M, int N, int K)
{
    extern __shared__ char smem[];
    unsigned sb = smem_u32(smem);
    const int tid = threadIdx.x, w = tid >> 5, lane = tid & 31;
    const int brow = blockIdx.y * 128, bcol = blockIdx.x * 128;
    const int wm = (w >> 1) * 64;
    const int wn = (w & 1) * 64;
    const int lrow = lane & 15;
    const int lcol = (lane >> 4) * 16;

    const int nch = K >> 5;

    float acc[4][8][4] = {};

    prefetch_chunk(Ahi, Alo, BThi, BTlo, brow, bcol, K, 0, sb, tid);
    CP_COMMIT();
    prefetch_chunk(Ahi, Alo, BThi, BTlo, brow, bcol, K, 32, sb + GS_STAGE, tid);
    CP_COMMIT();
    CP_WAIT1();
    __syncthreads();

    int s_cur = 0;
    for (int c = 0; c < nch; c++) {
        if (c + 2 < nch) {
            int s2 = s_cur + 2; if (s2 >= 3) s2 -= 3;
            prefetch_chunk(Ahi, Alo, BThi, BTlo, brow, bcol, K, (c + 2) << 5,
                           sb + s2 * GS_STAGE, tid);
            CP_COMMIT();
        }

        unsigned base = sb + s_cur * GS_STAGE;
        #pragma unroll
        for (int ks = 0; ks < 2; ks++) {
            int kb = ks * 32;
            unsigned bH[4][4], bL[4][4];
            #pragma unroll
            for (int j2 = 0; j2 < 4; j2++) {
                unsigned off = (unsigned)((wn + j2 * 16 + lrow) * 64 + kb + lcol);
                LDMX4(bH[j2][0], bH[j2][1], bH[j2][2], bH[j2][3], base + 16384 + SWZ64(off));
                LDMX4(bL[j2][0], bL[j2][1], bL[j2][2], bL[j2][3], base + 24576 + SWZ64(off));
            }
            #pragma unroll
            for (int i = 0; i < 4; i++) {
                unsigned off = (unsigned)((wm + i * 16 + lrow) * 64 + kb + lcol);
                unsigned aH[4], aL[4];
                LDMX4(aH[0], aH[1], aH[2], aH[3], base + SWZ64(off));
                LDMX4(aL[0], aL[1], aL[2], aL[3], base + 8192 + SWZ64(off));
                #pragma unroll
                for (int j = 0; j < 8; j++) {
                    unsigned h0 = (j & 1) ? bH[j >> 1][1] : bH[j >> 1][0];
                    unsigned h1 = (j & 1) ? bH[j >> 1][3] : bH[j >> 1][2];
                    unsigned l0 = (j & 1) ? bL[j >> 1][1] : bL[j >> 1][0];
                    unsigned l1 = (j & 1) ? bL[j >> 1][3] : bL[j >> 1][2];
                    MMA16816(acc[i][j], aH, h0, h1);
                    MMA16816(acc[i][j], aL, h0, h1);
                    MMA16816(acc[i][j], aH, l0, l1);
                }
            }
        }

        if (c + 1 < nch) {
            if (c + 2 < nch) { CP_WAIT1(); } else { CP_WAIT0(); }
        }
        __syncthreads();
        if (++s_cur == 3) s_cur = 0;
    }

    const int r0 = brow + wm + (lane >> 2);
    const int c0 = bcol + wn + (lane & 3) * 2;
    #pragma unroll
    for (int i = 0; i < 4; i++) {
        #pragma unroll
        for (int j = 0; j < 8; j++) {
            int col = c0 + j * 8;
            float bx = bias[col], by = bias[col + 1];
            float v00 = acc[i][j][0] + bx, v01 = acc[i][j][1] + by;
            float v10 = acc[i][j][2] + bx, v11 = acc[i][j][3] + by;
            size_t o0 = (size_t)(r0 + i * 16) * N + col;
            size_t o1 = (size_t)(r0 + i * 16 + 8) * N + col;
            *(float2*)&C[o0] = make_float2(v00, v01);
            *(float2*)&C[o1] = make_float2(v10, v11);
            if (Chi) {
                unsigned l0, l1;
                unsigned h0 = pack_hi2(v00, v01, l0);
                unsigned h1 = pack_hi2(v10, v11, l1);
                *(unsigned*)&Chi[o0] = h0;
                *(unsigned*)&Clo[o0] = l0;
                *(unsigned*)&Chi[o1] = h1;
                *(unsigned*)&Clo[o1] = l1;
            }
        }
    }
}

// ---------------------------------------------------------------------------
// Kernel A: QK^T (3-pass bf16) + softmax. QT=16, 128 threads, ~100.5KB smem
// -> 2 CTA/SM. Writes attention fp32 to out AND normalized P fp16 to g_p.
// smem: QH@0(2KB) QL@2048 K@4096(hi16K lo16K) Lhi@36864 Llo@69888; tot 102912
// ---------------------------------------------------------------------------
#define LA_QH 0
#define LA_QL 2048
#define LA_K  4096
#define LA_LH 36864
#define LA_LL 69888
#define LA_TOTAL 102912
#define PSTRIDE 2064

__global__ __launch_bounds__(128, 2) void attn_logits(
    const __nv_bfloat16* __restrict__ qh, const __nv_bfloat16* __restrict__ ql,
    float* __restrict__ attn_out, __half* __restrict__ pOut)
{
    extern __shared__ char smem[];
    unsigned sb = smem_u32(smem);

    const int qt = blockIdx.x, h = blockIdx.y, b = blockIdx.z;
    const int bh = b * HH + h;
    const int q0 = qt * 16;
    const int tid = threadIdx.x, w = tid >> 5, lane = tid & 31;
    const int lrow = lane & 15, lcol = (lane >> 4) * 16;
    const int wn = w * 32;

    // Q tile (16 rows x 128B) hi+lo
    {
        int row = tid >> 3, c16 = (tid & 7) * 16;
        unsigned so = SWZ128((unsigned)(row * 128 + c16));
        CP_ASYNC16(sb + LA_QH + so, (const char*)(qh + (size_t)(b * SS + q0 + row) * 3072 + h * 192) + c16);
        CP_ASYNC16(sb + LA_QL + so, (const char*)(ql + (size_t)(b * SS + q0 + row) * 3072 + h * 192) + c16);
    }
    // K chunk 0 (128 keys, hi+lo)
    #pragma unroll
    for (int i = 0; i < 8; i++) {
        int idx = tid + i * 128;
        int row = idx >> 3, c16 = (idx & 7) * 16;
        unsigned so = SWZ128((unsigned)(row * 128 + c16));
        CP_ASYNC16(sb + LA_K + so, (const char*)(qh + (size_t)(b * SS + row) * 3072 + h * 192 + 64) + c16);
        CP_ASYNC16(sb + LA_K + 16384 + so, (const char*)(ql + (size_t)(b * SS + row) * 3072 + h * 192 + 64) + c16);
    }
    CP_COMMIT();
    CP_WAIT0();
    __syncthreads();

    for (int c = 0; c < 8; c++) {
        float acc[4][4] = {};
        #pragma unroll
        for (int ks = 0; ks < 4; ks++) {
            int kb = ks * 32;
            unsigned aoff = SWZ128((unsigned)(lrow * 128 + kb + lcol));
            unsigned aH[4], aL[4];
            LDMX4(aH[0], aH[1], aH[2], aH[3], sb + LA_QH + aoff);
            LDMX4(aL[0], aL[1], aL[2], aL[3], sb + LA_QL + aoff);
            unsigned bH[2][4], bL[2][4];
            #pragma unroll
            for (int j2 = 0; j2 < 2; j2++) {
                unsigned boff = SWZ128((unsigned)((wn + j2 * 16 + lrow) * 128 + kb + lcol));
                LDMX4(bH[j2][0], bH[j2][1], bH[j2][2], bH[j2][3], sb + LA_K + boff);
                LDMX4(bL[j2][0], bL[j2][1], bL[j2][2], bL[j2][3], sb + LA_K + 16384 + boff);
            }
            #pragma unroll
            for (int j = 0; j < 4; j++) {
                unsigned h0 = (j & 1) ? bH[j >> 1][1] : bH[j >> 1][0];
                unsigned h1 = (j & 1) ? bH[j >> 1][3] : bH[j >> 1][2];
                unsigned l0 = (j & 1) ? bL[j >> 1][1] : bL[j >> 1][0];
                unsigned l1 = (j & 1) ? bL[j >> 1][3] : bL[j >> 1][2];
                MMA16816(acc[j], aH, h0, h1);
                MMA16816(acc[j], aL, h0, h1);
                MMA16816(acc[j], aH, l0, l1);
            }
        }
        // store logits (x0.125) packed hi/lo
        int r0 = lane >> 2;
        int cb = c * 128 + wn + (lane & 3) * 2;
        #pragma unroll
        for (int j = 0; j < 4; j++) {
            int col = cb + j * 8;
            unsigned lp0, lp1;
            unsigned hp0 = pack_hi2(acc[j][0] * 0.125f, acc[j][1] * 0.125f, lp0);
            unsigned hp1 = pack_hi2(acc[j][2] * 0.125f, acc[j][3] * 0.125f, lp1);
            unsigned o0 = (unsigned)(r0 * PSTRIDE + col * 2);
            unsigned o1 = (unsigned)((r0 + 8) * PSTRIDE + col * 2);
            *(unsigned*)(smem + LA_LH + o0) = hp0;
            *(unsigned*)(smem + LA_LL + o0) = lp0;
            *(unsigned*)(smem + LA_LH + o1) = hp1;
            *(unsigned*)(smem + LA_LL + o1) = lp1;
        }
        __syncthreads();         // all MMA reads of K buffer done
        if (c + 1 < 8) {
            int kb0 = (c + 1) * 128;
            #pragma unroll
            for (int i = 0; i < 8; i++) {
                int idx = tid + i * 128;
                int row = idx >> 3, c16 = (idx & 7) * 16;
                unsigned so = SWZ128((unsigned)(row * 128 + c16));
                CP_ASYNC16(sb + LA_K + so, (const char*)(qh + (size_t)(b * SS + kb0 + row) * 3072 + h * 192 + 64) + c16);
                CP_ASYNC16(sb + LA_K + 16384 + so, (const char*)(ql + (size_t)(b * SS + kb0 + row) * 3072 + h * 192 + 64) + c16);
            }
            CP_COMMIT();
            CP_WAIT0();
            __syncthreads();
        }
    }
    __syncthreads();   // logits complete

    // softmax; write attention fp32 + normalized P fp16
    for (int r = w; r < 16; r += 4) {
        float m = -1e30f;
        #pragma unroll 4
        for (int it = 0; it < 16; it++) {
            unsigned o = (unsigned)(r * PSTRIDE + it * 128 + lane * 4);
            unsigned uh = *(unsigned*)(smem + LA_LH + o);
            unsigned ul = *(unsigned*)(smem + LA_LL + o);
            float l0 = bflo(uh) + bflo(ul);
            float l1 = bfhi(uh) + bfhi(ul);
            m = fmaxf(m, fmaxf(l0, l1));
        }
        #pragma unroll
        for (int o = 16; o > 0; o >>= 1) m = fmaxf(m, __shfl_xor_sync(0xFFFFFFFFu, m, o));
        float sum = 0.f;
        #pragma unroll 4
        for (int it = 0; it < 16; it++) {
            unsigned o = (unsigned)(r * PSTRIDE + it * 128 + lane * 4);
            unsigned uh = *(unsigned*)(smem + LA_LH + o);
            unsigned ul = *(unsigned*)(smem + LA_LL + o);
            float e0 = __expf(bflo(uh) + bflo(ul) - m);
            float e1 = __expf(bfhi(uh) + bfhi(ul) - m);
            sum += e0 + e1;
            *(float2*)(smem + LA_LH + 0) = *(float2*)(smem + LA_LH + 0); // no-op keep
            unsigned lp;
            unsigned hp = pack_hi2(e0, e1, lp);
            *(unsigned*)(smem + LA_LH + o) = hp;
            *(unsigned*)(smem + LA_LL + o) = lp;
        }
        #pragma unroll
        for (int o = 16; o > 0; o >>= 1) sum += __shfl_xor_sync(0xFFFFFFFFu, sum, o);
        float inv = 1.0f / sum;
        size_t base = ((size_t)(bh * SS) + q0 + r) * SS;
        #pragma unroll 4
        for (int it = 0; it < 16; it++) {
            unsigned o = (unsigned)(r * PSTRIDE + it * 128 + lane * 4);
            unsigned uh = *(unsigned*)(smem + LA_LH + o);
            unsigned ul = *(unsigned*)(smem + LA_LL + o);
            float v0 = (bflo(uh) + bflo(ul)) * inv;
            float v1 = (bfhi(uh) + bfhi(ul)) * inv;
            *(float2*)&attn_out[base + it * 64 + lane * 2] = make_float2(v0, v1);
            __half p0 = __float2half(v0), p1 = __float2half(v1);
            unsigned pu = ((unsigned)__half_as_ushort(p1) << 16) | __half_as_ushort(p0);
            *(unsigned*)&pOut[base + it * 64 + lane * 2] = pu;
        }
    }
}

// ---------------------------------------------------------------------------
// Kernel B: values = P(fp16) @ V^T (fp16 hi/lo, 2-pass). Per-(b,h) M=128 block,
// N=64, K=1024. 128 threads, warp tile 64x32. 3 stages.
// stage: P 16KB @0, Vh 8KB @16384, Vl 8KB @24576.
// ---------------------------------------------------------------------------
#define AV_STAGE 32768
#define AV_TOTAL 98304

__device__ __forceinline__ void av_load(
    const __half* __restrict__ P, const __half* __restrict__ vTh,
    const __half* __restrict__ vTl, int bh, int brow, int kt,
    unsigned stage, int tid)
{
    #pragma unroll
    for (int i = 0; i < 8; i++) {
        int idx = tid + i * 128;
        int row = idx >> 3, c16 = (idx & 7) * 16;
        unsigned so = SWZ128((unsigned)(row * 128 + c16));
        CP_ASYNC16(stage + so, (const char*)(P + ((size_t)(bh * SS + brow + row)) * SS + kt) + c16);
    }
    #pragma unroll
    for (int i = 0; i < 4; i++) {
        int idx = tid + i * 128;
        int row = idx >> 3, c16 = (idx & 7) * 16;
        unsigned so = SWZ128((unsigned)(row * 128 + c16));
        CP_ASYNC16(stage + 16384 + so, (const char*)(vTh + (size_t)(bh * HDIM + row) * SS + kt) + c16);
        CP_ASYNC16(stage + 24576 + so, (const char*)(vTl + (size_t)(bh * HDIM + row) * SS + kt) + c16);
    }
}

__global__ __launch_bounds__(128, 2) void av_gemm(
    const __half* __restrict__ P, const __half* __restrict__ vTh,
    const __half* __restrict__ vTl,
    __nv_bfloat16* __restrict__ Vhi, __nv_bfloat16* __restrict__ Vlo)
{
    extern __shared__ char smem[];
    unsigned sb = smem_u32(smem);
    const int tid = threadIdx.x, w = tid >> 5, lane = tid & 31;
    const int brow = blockIdx.x * 128;
    const int bh = blockIdx.y;
    const int b = bh >> 4, h = bh & 15;
    const int wm = (w >> 1) * 64;
    const int wn = (w & 1) * 32;
    const int lrow = lane & 15;
    const int lcol = (lane >> 4) * 16;

    const int nch = 16;   // K=1024, chunk 64

    float acc[4][4][4] = {};

    av_load(P, vTh, vTl, bh, brow, 0, sb, tid);
    CP_COMMIT();
    av_load(P, vTh, vTl, bh, brow, 64, sb + AV_STAGE, tid);
    CP_COMMIT();
    CP_WAIT1();
    __syncthreads();

    int s_cur = 0;
    for (int c = 0; c < nch; c++) {
        if (c + 2 < nch) {
            int s2 = s_cur + 2; if (s2 >= 3) s2 -= 3;
            av_load(P, vTh, vTl, bh, brow, (c + 2) * 64, sb + s2 * AV_STAGE, tid);
            CP_COMMIT();
        }

        unsigned base = sb + s_cur * AV_STAGE;
        #pragma unroll
        for (int ks = 0; ks < 4; ks++) {
            int kb = ks * 32;
            unsigned vh[2][4], vl[2][4];
            #pragma unroll
            for (int j2 = 0; j2 < 2; j2++) {
                unsigned off = SWZ128((unsigned)((wn + j2 * 16 + lrow) * 128 + kb + lcol));
                LDMX4(vh[j2][0], vh[j2][1], vh[j2][2], vh[j2][3], base + 16384 + off);
                LDMX4(vl[j2][0], vl[j2][1], vl[j2][2], vl[j2][3], base + 24576 + off);
            }
            #pragma unroll
            for (int i = 0; i < 4; i++) {
                unsigned off = SWZ128((unsigned)((wm + i * 16 + lrow) * 128 + kb + lcol));
                unsigned aF[4];
                LDMX4(aF[0], aF[1], aF[2], aF[3], base + off);
                #pragma unroll
                for (int j = 0; j < 4; j++) {
                    unsigned h0 = (j & 1) ? vh[j >> 1][1] : vh[j >> 1][0];
                    unsigned h1 = (j & 1) ? vh[j >> 1][3] : vh[j >> 1][2];
                    unsigned l0 = (j & 1) ? vl[j >> 1][1] : vl[j >> 1][0];
                    unsigned l1 = (j & 1) ? vl[j >> 1][3] : vl[j >> 1][2];
                    MMAF16(acc[i][j], aF, h0, h1);
                    MMAF16(acc[i][j], aF, l0, l1);
                }
            }
        }

        if (c + 1 < nch) {
            if (c + 2 < nch) { CP_WAIT1(); } else { CP_WAIT0(); }
        }
        __syncthreads();
        if (++s_cur == 3) s_cur = 0;
    }

    // epilogue: write values bf16 hi/lo (head-interleaved for O-proj)
    const int r0 = brow + wm + (lane >> 2);
    const int c0 = wn + (lane & 3) * 2;
    #pragma unroll
    for (int i = 0; i < 4; i++) {
        #pragma unroll
        for (int j = 0; j < 4; j++) {
            int col = h * 64 + c0 + j * 8;
            size_t o0 = (size_t)(b * SS + r0 + i * 16) * DD + col;
            size_t o1 = (size_t)(b * SS + r0 + i * 16 + 8) * DD + col;
            unsigned l0, l1;
            unsigned h0 = pack_hi2(acc[i][j][0], acc[i][j][1], l0);
            unsigned h1 = pack_hi2(acc[i][j][2], acc[i][j][3], l1);
            *(unsigned*)&Vhi[o0] = h0;
            *(unsigned*)&Vlo[o0] = l0;
            *(unsigned*)&Vhi[o1] = h1;
            *(unsigned*)&Vlo[o1] = l1;
        }
    }
}

// ---------------------------------------------------------------------------
extern "C" void kernel_launch(void* const* d_in, const int* in_sizes, int n_in,
                              void* d_out, int out_size)
{
    const float* x     = (const float*)d_in[0];
    const float* W_qkv = (const float*)d_in[1];
    const float* b_qkv = (const float*)d_in[2];
    const float* W_o   = (const float*)d_in[3];
    const float* b_o   = (const float*)d_in[4];

    float* out_o    = (float*)d_out;
    float* out_attn = (float*)d_out + (size_t)BB * SS * DD;

    float* qkv_ptr;
    __nv_bfloat16 *xhi, *xlo, *wqh, *wql, *woh, *wol, *vhi, *vlo, *qhp, *qlp;
    __half *vthp, *vtlp, *pp;
    cudaGetSymbolAddress((void**)&qkv_ptr, g_qkv);
    cudaGetSymbolAddress((void**)&xhi, g_xhi);
    cudaGetSymbolAddress((void**)&xlo, g_xlo);
    cudaGetSymbolAddress((void**)&wqh, g_wqT_hi);
    cudaGetSymbolAddress((void**)&wql, g_wqT_lo);
    cudaGetSymbolAddress((void**)&woh, g_woT_hi);
    cudaGetSymbolAddress((void**)&wol, g_woT_lo);
    cudaGetSymbolAddress((void**)&vhi, g_vhi);
    cudaGetSymbolAddress((void**)&vlo, g_vlo);
    cudaGetSymbolAddress((void**)&qhp, g_qh);
    cudaGetSymbolAddress((void**)&qlp, g_ql);
    cudaGetSymbolAddress((void**)&vthp, g_vTh);
    cudaGetSymbolAddress((void**)&vtlp, g_vTl);
    cudaGetSymbolAddress((void**)&pp, g_p);

    cudaFuncSetAttribute(gemm3x_mma, cudaFuncAttributeMaxDynamicSharedMemorySize, GS_TOTAL);
    cudaFuncSetAttribute(attn_logits, cudaFuncAttributeMaxDynamicSharedMemorySize, LA_TOTAL);
    cudaFuncSetAttribute(av_gemm, cudaFuncAttributeMaxDynamicSharedMemorySize, AV_TOTAL);

    // 0) prep
    {
        int n4 = BB * SS * DD / 4;
        split_kernel<<<(n4 + 255) / 256, 256>>>(x, xhi, xlo, n4);
        dim3 g1(3 * DD / 32, DD / 32);
        tsplit_kernel<<<g1, dim3(32, 8)>>>(W_qkv, wqh, wql, DD, 3 * DD);
        dim3 g2(DD / 32, DD / 32);
        tsplit_kernel<<<g2, dim3(32, 8)>>>(W_o, woh, wol, DD, DD);
    }

    // 1) QKV projection (tensor)
    {
        dim3 grid(3 * DD / 128, BB * SS / 128);
        gemm3x_mma<<<grid, 128, GS_TOTAL>>>(xhi, xlo, wqh, wql, b_qkv, qkv_ptr,
                                            qhp, qlp, BB * SS, 3 * DD, DD);
    }

    // 2) V^T split (fp16)
    {
        dim3 gv(SS / 32, HDIM / 32, BB * HH);
        vT_kernel<<<gv, dim3(32, 8)>>>(qkv_ptr, vthp, vtlp);
    }

    // 3a) QK^T + softmax (occ 2), writes attention + P fp16
    {
        dim3 grid(SS / 16, HH, BB);
        attn_logits<<<grid, 128, LA_TOTAL>>>(qhp, qlp, out_attn, pp);
    }

    // 3b) AV gemm (occ 2)
    {
        dim3 grid(SS / 128, BB * HH);
        av_gemm<<<grid, 128, AV_TOTAL>>>(pp, vthp, vtlp, vhi, vlo);
    }

    // 4) O-proj (tensor)
    {
        dim3 grid(DD / 128, BB * SS / 128);
        gemm3x_mma<<<grid, 128, GS_TOTAL>>>(vhi, vlo, woh, wol, b_o, out_o,
                                            (__nv_bfloat16*)nullptr, (__nv_bfloat16*)nullptr,
                                            BB * SS, DD, DD);
    }
}

// round 10
// speedup vs baseline: 1.2588x; 1.2082x over previous
#include <cuda_runtime.h>
#include <cuda_bf16.h>
#include <cuda_fp16.h>

#define BB 4
#define SS 1024
#define HH 16
#define HDIM 64
#define DD 1024

// ---------------------------------------------------------------------------
// scratch (device globals — no allocation allowed)
// ---------------------------------------------------------------------------
__device__ float g_qkv[BB * SS * 3 * DD];       // [B,S,3D] fp32 (for vT)
__device__ __half g_xhi[BB * SS * DD];
__device__ __half g_xlo[BB * SS * DD];
__device__ __half g_wqT[3 * DD * DD];           // W_qkv^T fp16 single
__device__ __half g_woT[DD * DD];               // W_o^T fp16 single
__device__ __half g_vhi[BB * SS * DD];          // values hi (av epilogue)
__device__ __half g_vlo[BB * SS * DD];
__device__ __half g_qh[BB * SS * 3 * DD];       // qkv hi (gemm epilogue)
__device__ __half g_ql[BB * SS * 3 * DD];       // qkv lo
__device__ __half g_vTh[BB * HH * HDIM * SS];   // V^T fp16 per (b,h): [64][S]
__device__ __half g_vTl[BB * HH * HDIM * SS];
__device__ __half g_p[(size_t)BB * HH * SS * SS]; // normalized attention fp16

// ---------------------------------------------------------------------------
__device__ __forceinline__ unsigned smem_u32(const void* p) {
    unsigned a;
    asm("{ .reg .u64 t; cvta.to.shared.u64 t, %1; cvt.u32.u64 %0, t; }" : "=r"(a) : "l"(p));
    return a;
}
#define SWZ128(o) ((o) ^ (((o) >> 3) & 0x70))
#define SWZ64(o)  ((o) ^ (((o) >> 3) & 0x30))

#define CP_ASYNC16(saddr, gptr) \
    asm volatile("cp.async.cg.shared.global [%0], [%1], 16;" :: "r"(saddr), "l"(gptr) : "memory")
#define CP_COMMIT() asm volatile("cp.async.commit_group;" ::: "memory")
#define CP_WAIT1()  asm volatile("cp.async.wait_group 1;" ::: "memory")
#define CP_WAIT0()  asm volatile("cp.async.wait_group 0;" ::: "memory")

#define LDMX4(r0, r1, r2, r3, a) \
    asm volatile("ldmatrix.sync.aligned.m8n8.x4.shared.b16 {%0,%1,%2,%3}, [%4];" \
        : "=r"(r0), "=r"(r1), "=r"(r2), "=r"(r3) : "r"(a))

#define MMAF16(d, a, b0, b1) \
    asm volatile("mma.sync.aligned.m16n8k16.row.col.f32.f16.f16.f32 " \
        "{%0,%1,%2,%3}, {%4,%5,%6,%7}, {%8,%9}, {%0,%1,%2,%3};" \
        : "+f"((d)[0]), "+f"((d)[1]), "+f"((d)[2]), "+f"((d)[3]) \
        : "r"((a)[0]), "r"((a)[1]), "r"((a)[2]), "r"((a)[3]), "r"(b0), "r"(b1))

// fp16 hi/lo pack
__device__ __forceinline__ unsigned packh2(float x, float y, unsigned& lo) {
    __half hx = __float2half(x);
    __half hy = __float2half(y);
    __half lx = __float2half(x - __half2float(hx));
    __half ly = __float2half(y - __half2float(hy));
    lo = ((unsigned)__half_as_ushort(ly) << 16) | __half_as_ushort(lx);
    return ((unsigned)__half_as_ushort(hy) << 16) | __half_as_ushort(hx);
}
// bf16 hi/lo pack for logits smem buffer
__device__ __forceinline__ unsigned pack_hi2(float x, float y, unsigned& lo) {
    __nv_bfloat16 hx = __float2bfloat16(x);
    __nv_bfloat16 hy = __float2bfloat16(y);
    __nv_bfloat16 lx = __float2bfloat16(x - __bfloat162float(hx));
    __nv_bfloat16 ly = __float2bfloat16(y - __bfloat162float(hy));
    lo = ((unsigned)__bfloat16_as_ushort(ly) << 16) | __bfloat16_as_ushort(lx);
    return ((unsigned)__bfloat16_as_ushort(hy) << 16) | __bfloat16_as_ushort(hx);
}
__device__ __forceinline__ float bflo(unsigned u) {
    return __bfloat162float(__ushort_as_bfloat16((unsigned short)(u & 0xFFFF)));
}
__device__ __forceinline__ float bfhi(unsigned u) {
    return __bfloat162float(__ushort_as_bfloat16((unsigned short)(u >> 16)));
}

// ---------------------------------------------------------------------------
__global__ __launch_bounds__(256) void split_kernel(
    const float* __restrict__ src, __half* __restrict__ hi,
    __half* __restrict__ lo, int n4)
{
    int i = blockIdx.x * 256 + threadIdx.x;
    if (i >= n4) return;
    float4 v = ((const float4*)src)[i];
    unsigned l0, l1, h0, h1;
    h0 = packh2(v.x, v.y, l0);
    h1 = packh2(v.z, v.w, l1);
    ((uint2*)hi)[i] = make_uint2(h0, h1);
    ((uint2*)lo)[i] = make_uint2(l0, l1);
}

// transpose W[K,N] fp32 -> WT[N,K] fp16 single
__global__ __launch_bounds__(256) void tsingle_kernel(
    const float* __restrict__ W, __half* __restrict__ WT, int K, int N)
{
    __shared__ float t[32][33];
    int k0 = blockIdx.y * 32, n0 = blockIdx.x * 32;
    int tx = threadIdx.x, ty = threadIdx.y;
    #pragma unroll
    for (int i = 0; i < 32; i += 8)
        t[ty + i][tx] = W[(size_t)(k0 + ty + i) * N + n0 + tx];
    __syncthreads();
    #pragma unroll
    for (int i = 0; i < 32; i += 8)
        WT[(size_t)(n0 + ty + i) * K + k0 + tx] = __float2half(t[tx][ty + i]);
}

// V^T + split to fp16: qkv V slice -> vT hi/lo [bh][64][S]
__global__ __launch_bounds__(256) void vT_kernel(
    const float* __restrict__ qkv, __half* __restrict__ vTh,
    __half* __restrict__ vTl)
{
    __shared__ float t[32][33];
    int s0 = blockIdx.x * 32, d0 = blockIdx.y * 32, bh = blockIdx.z;
    int b = bh >> 4, h = bh & 15;
    int tx = threadIdx.x, ty = threadIdx.y;
    #pragma unroll
    for (int i = 0; i < 32; i += 8)
        t[ty + i][tx] = qkv[(size_t)(b * SS + s0 + ty + i) * 3072 + h * 192 + 128 + d0 + tx];
    __syncthreads();
    #pragma unroll
    for (int i = 0; i < 32; i += 8) {
        float v = t[tx][ty + i];
        __half hh = __float2half(v);
        size_t o = (size_t)(bh * HDIM + d0 + ty + i) * SS + s0 + tx;
        vTh[o] = hh;
        vTl[o] = __float2half(v - __half2float(hh));
    }
}

// ---------------------------------------------------------------------------
// 2-pass fp16 GEMM: C = Ah@BT^T + Al@BT^T + bias. 128 threads, warp 64x64.
// K-chunk 32; stage = Ah(8K)|Al(8K)|B(8K) = 24KB; 3 stages.
// ---------------------------------------------------------------------------
#define GS_STAGE 24576
#define GS_TOTAL 73728

__device__ __forceinline__ void gload64h(const __half* __restrict__ src,
                                         int rbase, int K, int kt, unsigned dst, int tid)
{
    #pragma unroll
    for (int i = 0; i < 4; i++) {
        int idx = tid + i * 128;
        int row = idx >> 2;
        int c16 = (idx & 3) * 16;
        CP_ASYNC16(dst + SWZ64((unsigned)(row * 64 + c16)),
                   (const char*)(src + (size_t)(rbase + row) * K + kt) + c16);
    }
}

__device__ __forceinline__ void prefetch_chunk2(
    const __half* __restrict__ Ahi, const __half* __restrict__ Alo,
    const __half* __restrict__ BT,
    int brow, int bcol, int K, int kt, unsigned stage, int tid)
{
    gload64h(Ahi, brow, K, kt, stage, tid);
    gload64h(Alo, brow, K, kt, stage + 8192, tid);
    gload64h(BT, bcol, K, kt, stage + 16384, tid);
}

__global__ __launch_bounds__(128, 2) void gemm2x_mma(
    const __half* __restrict__ Ahi, const __half* __restrict__ Alo,
    const __half* __restrict__ BT,
    const float* __restrict__ bias, float* __restrict__ C,
    __half* __restrict__ Chi, __half* __restrict__ Clo,
    int M, int N, int K)
{
    extern __shared__ char smem[];
    unsigned sb = smem_u32(smem);
    const int tid = threadIdx.x, w = tid >> 5, lane = tid & 31;
    const int brow = blockIdx.y * 128, bcol = blockIdx.x * 128;
    const int wm = (w >> 1) * 64;
    const int wn = (w & 1) * 64;
    const int lrow = lane & 15;
    const int lcol = (lane >> 4) * 16;

    const int nch = K >> 5;

    float acc[4][8][4] = {};

    prefetch_chunk2(Ahi, Alo, BT, brow, bcol, K, 0, sb, tid);
    CP_COMMIT();
    prefetch_chunk2(Ahi, Alo, BT, brow, bcol, K, 32, sb + GS_STAGE, tid);
    CP_COMMIT();
    CP_WAIT1();
    __syncthreads();

    int s_cur = 0;
    for (int c = 0; c < nch; c++) {
        if (c + 2 < nch) {
            int s2 = s_cur + 2; if (s2 >= 3) s2 -= 3;
            prefetch_chunk2(Ahi, Alo, BT, brow, bcol, K, (c + 2) << 5,
                            sb + s2 * GS_STAGE, tid);
            CP_COMMIT();
        }

        unsigned base = sb + s_cur * GS_STAGE;
        #pragma unroll
        for (int ks = 0; ks < 2; ks++) {
            int kb = ks * 32;
            unsigned bF[4][4];
            #pragma unroll
            for (int j2 = 0; j2 < 4; j2++) {
                unsigned off = (unsigned)((wn + j2 * 16 + lrow) * 64 + kb + lcol);
                LDMX4(bF[j2][0], bF[j2][1], bF[j2][2], bF[j2][3], base + 16384 + SWZ64(off));
            }
            #pragma unroll
            for (int i = 0; i < 4; i++) {
                unsigned off = (unsigned)((wm + i * 16 + lrow) * 64 + kb + lcol);
                unsigned aH[4], aL[4];
                LDMX4(aH[0], aH[1], aH[2], aH[3], base + SWZ64(off));
                LDMX4(aL[0], aL[1], aL[2], aL[3], base + 8192 + SWZ64(off));
                #pragma unroll
                for (int j = 0; j < 8; j++) {
                    unsigned b0 = (j & 1) ? bF[j >> 1][1] : bF[j >> 1][0];
                    unsigned b1 = (j & 1) ? bF[j >> 1][3] : bF[j >> 1][2];
                    MMAF16(acc[i][j], aH, b0, b1);
                    MMAF16(acc[i][j], aL, b0, b1);
                }
            }
        }

        if (c + 1 < nch) {
            if (c + 2 < nch) { CP_WAIT1(); } else { CP_WAIT0(); }
        }
        __syncthreads();
        if (++s_cur == 3) s_cur = 0;
    }

    const int r0 = brow + wm + (lane >> 2);
    const int c0 = bcol + wn + (lane & 3) * 2;
    #pragma unroll
    for (int i = 0; i < 4; i++) {
        #pragma unroll
        for (int j = 0; j < 8; j++) {
            int col = c0 + j * 8;
            float bx = bias[col], by = bias[col + 1];
            float v00 = acc[i][j][0] + bx, v01 = acc[i][j][1] + by;
            float v10 = acc[i][j][2] + bx, v11 = acc[i][j][3] + by;
            size_t o0 = (size_t)(r0 + i * 16) * N + col;
            size_t o1 = (size_t)(r0 + i * 16 + 8) * N + col;
            *(float2*)&C[o0] = make_float2(v00, v01);
            *(float2*)&C[o1] = make_float2(v10, v11);
            if (Chi) {
                unsigned l0, l1;
                unsigned h0 = packh2(v00, v01, l0);
                unsigned h1 = packh2(v10, v11, l1);
                *(unsigned*)&Chi[o0] = h0;
                *(unsigned*)&Clo[o0] = l0;
                *(unsigned*)&Chi[o1] = h1;
                *(unsigned*)&Clo[o1] = l1;
            }
        }
    }
}

// ---------------------------------------------------------------------------
// Kernel A: QK^T (2-pass: Qhi/Qlo x Khi) + softmax. QT=16, 128 threads.
// smem: QH@0(2K) QL@2048 K@4096(16K) LH@20480(33024) LL@53504(33024) = 86528
// -> 2 CTA/SM. Writes attention fp32 + normalized P fp16.
// ---------------------------------------------------------------------------
#define LA_QH 0
#define LA_QL 2048
#define LA_K  4096
#define LA_LH 20480
#define LA_LL 53504
#define LA_TOTAL 86528
#define PSTRIDE 2064

__global__ __launch_bounds__(128, 2) void attn_logits(
    const __half* __restrict__ qh, const __half* __restrict__ ql,
    float* __restrict__ attn_out, __half* __restrict__ pOut)
{
    extern __shared__ char smem[];
    unsigned sb = smem_u32(smem);

    const int qt = blockIdx.x, h = blockIdx.y, b = blockIdx.z;
    const int bh = b * HH + h;
    const int q0 = qt * 16;
    const int tid = threadIdx.x, w = tid >> 5, lane = tid & 31;
    const int lrow = lane & 15, lcol = (lane >> 4) * 16;
    const int wn = w * 32;

    // Q tile (16 rows x 128B) hi+lo
    {
        int row = tid >> 3, c16 = (tid & 7) * 16;
        unsigned so = SWZ128((unsigned)(row * 128 + c16));
        CP_ASYNC16(sb + LA_QH + so, (const char*)(qh + (size_t)(b * SS + q0 + row) * 3072 + h * 192) + c16);
        CP_ASYNC16(sb + LA_QL + so, (const char*)(ql + (size_t)(b * SS + q0 + row) * 3072 + h * 192) + c16);
    }
    // K chunk 0 (128 keys, hi only)
    #pragma unroll
    for (int i = 0; i < 8; i++) {
        int idx = tid + i * 128;
        int row = idx >> 3, c16 = (idx & 7) * 16;
        unsigned so = SWZ128((unsigned)(row * 128 + c16));
        CP_ASYNC16(sb + LA_K + so, (const char*)(qh + (size_t)(b * SS + row) * 3072 + h * 192 + 64) + c16);
    }
    CP_COMMIT();
    CP_WAIT0();
    __syncthreads();

    for (int c = 0; c < 8; c++) {
        float acc[4][4] = {};
        #pragma unroll
        for (int ks = 0; ks < 4; ks++) {
            int kb = ks * 32;
            unsigned aoff = SWZ128((unsigned)(lrow * 128 + kb + lcol));
            unsigned aH[4], aL[4];
            LDMX4(aH[0], aH[1], aH[2], aH[3], sb + LA_QH + aoff);
            LDMX4(aL[0], aL[1], aL[2], aL[3], sb + LA_QL + aoff);
            unsigned bF[2][4];
            #pragma unroll
            for (int j2 = 0; j2 < 2; j2++) {
                unsigned boff = SWZ128((unsigned)((wn + j2 * 16 + lrow) * 128 + kb + lcol));
                LDMX4(bF[j2][0], bF[j2][1], bF[j2][2], bF[j2][3], sb + LA_K + boff);
            }
            #pragma unroll
            for (int j = 0; j < 4; j++) {
                unsigned b0 = (j & 1) ? bF[j >> 1][1] : bF[j >> 1][0];
                unsigned b1 = (j & 1) ? bF[j >> 1][3] : bF[j >> 1][2];
                MMAF16(acc[j], aH, b0, b1);
                MMAF16(acc[j], aL, b0, b1);
            }
        }
        // store logits (x0.125) packed bf16 hi/lo
        int r0 = lane >> 2;
        int cb = c * 128 + wn + (lane & 3) * 2;
        #pragma unroll
        for (int j = 0; j < 4; j++) {
            int col = cb + j * 8;
            unsigned lp0, lp1;
            unsigned hp0 = pack_hi2(acc[j][0] * 0.125f, acc[j][1] * 0.125f, lp0);
            unsigned hp1 = pack_hi2(acc[j][2] * 0.125f, acc[j][3] * 0.125f, lp1);
            unsigned o0 = (unsigned)(r0 * PSTRIDE + col * 2);
            unsigned o1 = (unsigned)((r0 + 8) * PSTRIDE + col * 2);
            *(unsigned*)(smem + LA_LH + o0) = hp0;
            *(unsigned*)(smem + LA_LL + o0) = lp0;
            *(unsigned*)(smem + LA_LH + o1) = hp1;
            *(unsigned*)(smem + LA_LL + o1) = lp1;
        }
        __syncthreads();
        if (c + 1 < 8) {
            int kb0 = (c + 1) * 128;
            #pragma unroll
            for (int i = 0; i < 8; i++) {
                int idx = tid + i * 128;
                int row = idx >> 3, c16 = (idx & 7) * 16;
                unsigned so = SWZ128((unsigned)(row * 128 + c16));
                CP_ASYNC16(sb + LA_K + so, (const char*)(qh + (size_t)(b * SS + kb0 + row) * 3072 + h * 192 + 64) + c16);
            }
            CP_COMMIT();
            CP_WAIT0();
            __syncthreads();
        }
    }
    __syncthreads();

    // softmax; write attention fp32 + normalized P fp16
    for (int r = w; r < 16; r += 4) {
        float m = -1e30f;
        #pragma unroll 4
        for (int it = 0; it < 16; it++) {
            unsigned o = (unsigned)(r * PSTRIDE + it * 128 + lane * 4);
            unsigned uh = *(unsigned*)(smem + LA_LH + o);
            unsigned ul = *(unsigned*)(smem + LA_LL + o);
            float l0 = bflo(uh) + bflo(ul);
            float l1 = bfhi(uh) + bfhi(ul);
            m = fmaxf(m, fmaxf(l0, l1));
        }
        #pragma unroll
        for (int o = 16; o > 0; o >>= 1) m = fmaxf(m, __shfl_xor_sync(0xFFFFFFFFu, m, o));
        float sum = 0.f;
        #pragma unroll 4
        for (int it = 0; it < 16; it++) {
            unsigned o = (unsigned)(r * PSTRIDE + it * 128 + lane * 4);
            unsigned uh = *(unsigned*)(smem + LA_LH + o);
            unsigned ul = *(unsigned*)(smem + LA_LL + o);
            float e0 = __expf(bflo(uh) + bflo(ul) - m);
            float e1 = __expf(bfhi(uh) + bfhi(ul) - m);
            sum += e0 + e1;
            unsigned lp;
            unsigned hp = pack_hi2(e0, e1, lp);
            *(unsigned*)(smem + LA_LH + o) = hp;
            *(unsigned*)(smem + LA_LL + o) = lp;
        }
        #pragma unroll
        for (int o = 16; o > 0; o >>= 1) sum += __shfl_xor_sync(0xFFFFFFFFu, sum, o);
        float inv = 1.0f / sum;
        size_t base = ((size_t)(bh * SS) + q0 + r) * SS;
        #pragma unroll 4
        for (int it = 0; it < 16; it++) {
            unsigned o = (unsigned)(r * PSTRIDE + it * 128 + lane * 4);
            unsigned uh = *(unsigned*)(smem + LA_LH + o);
            unsigned ul = *(unsigned*)(smem + LA_LL + o);
            float v0 = (bflo(uh) + bflo(ul)) * inv;
            float v1 = (bfhi(uh) + bfhi(ul)) * inv;
            *(float2*)&attn_out[base + it * 64 + lane * 2] = make_float2(v0, v1);
            __half p0 = __float2half(v0), p1 = __float2half(v1);
            unsigned pu = ((unsigned)__half_as_ushort(p1) << 16) | __half_as_ushort(p0);
            *(unsigned*)&pOut[base + it * 64 + lane * 2] = pu;
        }
    }
}

// ---------------------------------------------------------------------------
// Kernel B: values = P(fp16) @ V^T (fp16 hi/lo, 2-pass). Unchanged from R9.
// ---------------------------------------------------------------------------
#define AV_STAGE 32768
#define AV_TOTAL 98304

__device__ __forceinline__ void av_load(
    const __half* __restrict__ P, const __half* __restrict__ vTh,
    const __half* __restrict__ vTl, int bh, int brow, int kt,
    unsigned stage, int tid)
{
    #pragma unroll
    for (int i = 0; i < 8; i++) {
        int idx = tid + i * 128;
        int row = idx >> 3, c16 = (idx & 7) * 16;
        unsigned so = SWZ128((unsigned)(row * 128 + c16));
        CP_ASYNC16(stage + so, (const char*)(P + ((size_t)(bh * SS + brow + row)) * SS + kt) + c16);
    }
    #pragma unroll
    for (int i = 0; i < 4; i++) {
        int idx = tid + i * 128;
        int row = idx >> 3, c16 = (idx & 7) * 16;
        unsigned so = SWZ128((unsigned)(row * 128 + c16));
        CP_ASYNC16(stage + 16384 + so, (const char*)(vTh + (size_t)(bh * HDIM + row) * SS + kt) + c16);
        CP_ASYNC16(stage + 24576 + so, (const char*)(vTl + (size_t)(bh * HDIM + row) * SS + kt) + c16);
    }
}

__global__ __launch_bounds__(128, 2) void av_gemm(
    const __half* __restrict__ P, const __half* __restrict__ vTh,
    const __half* __restrict__ vTl,
    __half* __restrict__ Vhi, __half* __restrict__ Vlo)
{
    extern __shared__ char smem[];
    unsigned sb = smem_u32(smem);
    const int tid = threadIdx.x, w = tid >> 5, lane = tid & 31;
    const int brow = blockIdx.x * 128;
    const int bh = blockIdx.y;
    const int b = bh >> 4, h = bh & 15;
    const int wm = (w >> 1) * 64;
    const int wn = (w & 1) * 32;
    const int lrow = lane & 15;
    const int lcol = (lane >> 4) * 16;

    const int nch = 16;

    float acc[4][4][4] = {};

    av_load(P, vTh, vTl, bh, brow, 0, sb, tid);
    CP_COMMIT();
    av_load(P, vTh, vTl, bh, brow, 64, sb + AV_STAGE, tid);
    CP_COMMIT();
    CP_WAIT1();
    __syncthreads();

    int s_cur = 0;
    for (int c = 0; c < nch; c++) {
        if (c + 2 < nch) {
            int s2 = s_cur + 2; if (s2 >= 3) s2 -= 3;
            av_load(P, vTh, vTl, bh, brow, (c + 2) * 64, sb + s2 * AV_STAGE, tid);
            CP_COMMIT();
        }

        unsigned base = sb + s_cur * AV_STAGE;
        #pragma unroll
        for (int ks = 0; ks < 4; ks++) {
            int kb = ks * 32;
            unsigned vh[2][4], vl[2][4];
            #pragma unroll
            for (int j2 = 0; j2 < 2; j2++) {
                unsigned off = SWZ128((unsigned)((wn + j2 * 16 + lrow) * 128 + kb + lcol));
                LDMX4(vh[j2][0], vh[j2][1], vh[j2][2], vh[j2][3], base + 16384 + off);
                LDMX4(vl[j2][0], vl[j2][1], vl[j2][2], vl[j2][3], base + 24576 + off);
            }
            #pragma unroll
            for (int i = 0; i < 4; i++) {
                unsigned off = SWZ128((unsigned)((wm + i * 16 + lrow) * 128 + kb + lcol));
                unsigned aF[4];
                LDMX4(aF[0], aF[1], aF[2], aF[3], base + off);
                #pragma unroll
                for (int j = 0; j < 4; j++) {
                    unsigned h0 = (j & 1) ? vh[j >> 1][1] : vh[j >> 1][0];
                    unsigned h1 = (j & 1) ? vh[j >> 1][3] : vh[j >> 1][2];
                    unsigned l0 = (j & 1) ? vl[j >> 1][1] : vl[j >> 1][0];
                    unsigned l1 = (j & 1) ? vl[j >> 1][3] : vl[j >> 1][2];
                    MMAF16(acc[i][j], aF, h0, h1);
                    MMAF16(acc[i][j], aF, l0, l1);
                }
            }
        }

        if (c + 1 < nch) {
            if (c + 2 < nch) { CP_WAIT1(); } else { CP_WAIT0(); }
        }
        __syncthreads();
        if (++s_cur == 3) s_cur = 0;
    }

    const int r0 = brow + wm + (lane >> 2);
    const int c0 = wn + (lane & 3) * 2;
    #pragma unroll
    for (int i = 0; i < 4; i++) {
        #pragma unroll
        for (int j = 0; j < 4; j++) {
            int col = h * 64 + c0 + j * 8;
            size_t o0 = (size_t)(b * SS + r0 + i * 16) * DD + col;
            size_t o1 = (size_t)(b * SS + r0 + i * 16 + 8) * DD + col;
            unsigned l0, l1;
            unsigned h0 = packh2(acc[i][j][0], acc[i][j][1], l0);
            unsigned h1 = packh2(acc[i][j][2], acc[i][j][3], l1);
            *(unsigned*)&Vhi[o0] = h0;
            *(unsigned*)&Vlo[o0] = l0;
            *(unsigned*)&Vhi[o1] = h1;
            *(unsigned*)&Vlo[o1] = l1;
        }
    }
}

// ---------------------------------------------------------------------------
extern "C" void kernel_launch(void* const* d_in, const int* in_sizes, int n_in,
                              void* d_out, int out_size)
{
    const float* x     = (const float*)d_in[0];
    const float* W_qkv = (const float*)d_in[1];
    const float* b_qkv = (const float*)d_in[2];
    const float* W_o   = (const float*)d_in[3];
    const float* b_o   = (const float*)d_in[4];

    float* out_o    = (float*)d_out;
    float* out_attn = (float*)d_out + (size_t)BB * SS * DD;

    float* qkv_ptr;
    __half *xhi, *xlo, *wqT, *woT, *vhi, *vlo, *qhp, *qlp, *vthp, *vtlp, *pp;
    cudaGetSymbolAddress((void**)&qkv_ptr, g_qkv);
    cudaGetSymbolAddress((void**)&xhi, g_xhi);
    cudaGetSymbolAddress((void**)&xlo, g_xlo);
    cudaGetSymbolAddress((void**)&wqT, g_wqT);
    cudaGetSymbolAddress((void**)&woT, g_woT);
    cudaGetSymbolAddress((void**)&vhi, g_vhi);
    cudaGetSymbolAddress((void**)&vlo, g_vlo);
    cudaGetSymbolAddress((void**)&qhp, g_qh);
    cudaGetSymbolAddress((void**)&qlp, g_ql);
    cudaGetSymbolAddress((void**)&vthp, g_vTh);
    cudaGetSymbolAddress((void**)&vtlp, g_vTl);
    cudaGetSymbolAddress((void**)&pp, g_p);

    cudaFuncSetAttribute(gemm2x_mma, cudaFuncAttributeMaxDynamicSharedMemorySize, GS_TOTAL);
    cudaFuncSetAttribute(attn_logits, cudaFuncAttributeMaxDynamicSharedMemorySize, LA_TOTAL);
    cudaFuncSetAttribute(av_gemm, cudaFuncAttributeMaxDynamicSharedMemorySize, AV_TOTAL);

    // 0) prep: split x (fp16 hi/lo), transpose weights to fp16 single
    {
        int n4 = BB * SS * DD / 4;
        split_kernel<<<(n4 + 255) / 256, 256>>>(x, xhi, xlo, n4);
        dim3 g1(3 * DD / 32, DD / 32);
        tsingle_kernel<<<g1, dim3(32, 8)>>>(W_qkv, wqT, DD, 3 * DD);
        dim3 g2(DD / 32, DD / 32);
        tsingle_kernel<<<g2, dim3(32, 8)>>>(W_o, woT, DD, DD);
    }

    // 1) QKV projection (2-pass fp16), epilogue emits fp16 hi/lo
    {
        dim3 grid(3 * DD / 128, BB * SS / 128);
        gemm2x_mma<<<grid, 128, GS_TOTAL>>>(xhi, xlo, wqT, b_qkv, qkv_ptr,
                                            qhp, qlp, BB * SS, 3 * DD, DD);
    }

    // 2) V^T split (fp16)
    {
        dim3 gv(SS / 32, HDIM / 32, BB * HH);
        vT_kernel<<<gv, dim3(32, 8)>>>(qkv_ptr, vthp, vtlp);
    }

    // 3a) QK^T (2-pass) + softmax, writes attention + P fp16
    {
        dim3 grid(SS / 16, HH, BB);
        attn_logits<<<grid, 128, LA_TOTAL>>>(qhp, qlp, out_attn, pp);
    }

    // 3b) AV gemm (2-pass)
    {
        dim3 grid(SS / 128, BB * HH);
        av_gemm<<<grid, 128, AV_TOTAL>>>(pp, vthp, vtlp, vhi, vlo);
    }

    // 4) O-proj (2-pass fp16)
    {
        dim3 grid(DD / 128, BB * SS / 128);
        gemm2x_mma<<<grid, 128, GS_TOTAL>>>(vhi, vlo, woT, b_o, out_o,
                                            (__half*)nullptr, (__half*)nullptr,
                                            BB * SS, DD, DD);
    }
}

// round 11
// speedup vs baseline: 1.3838x; 1.0992x over previous
#include <cuda_runtime.h>
#include <cuda_bf16.h>
#include <cuda_fp16.h>

#define BB 4
#define SS 1024
#define HH 16
#define HDIM 64
#define DD 1024

// ---------------------------------------------------------------------------
// scratch (device globals — no allocation allowed)
// ---------------------------------------------------------------------------
__device__ __half g_xhi[BB * SS * DD];
__device__ __half g_xlo[BB * SS * DD];
__device__ __half g_wqT[3 * DD * DD];           // W_qkv^T fp16 single
__device__ __half g_woT[DD * DD];               // W_o^T fp16 single
__device__ __half g_vhi[BB * SS * DD];          // values hi (av epilogue)
__device__ __half g_vlo[BB * SS * DD];
__device__ __half g_qh[BB * SS * 3 * DD];       // qkv hi (gemm epilogue)
__device__ __half g_ql[BB * SS * 3 * DD];       // qkv lo
__device__ __half g_vTh[BB * HH * HDIM * SS];   // V^T fp16 per (b,h): [64][S]
__device__ __half g_vTl[BB * HH * HDIM * SS];
__device__ __half g_p[(size_t)BB * HH * SS * SS]; // normalized attention fp16

// ---------------------------------------------------------------------------
__device__ __forceinline__ unsigned smem_u32(const void* p) {
    unsigned a;
    asm("{ .reg .u64 t; cvta.to.shared.u64 t, %1; cvt.u32.u64 %0, t; }" : "=r"(a) : "l"(p));
    return a;
}
#define SWZ128(o) ((o) ^ (((o) >> 3) & 0x70))
#define SWZ64(o)  ((o) ^ (((o) >> 3) & 0x30))

#define CP_ASYNC16(saddr, gptr) \
    asm volatile("cp.async.cg.shared.global [%0], [%1], 16;" :: "r"(saddr), "l"(gptr) : "memory")
#define CP_COMMIT() asm volatile("cp.async.commit_group;" ::: "memory")
#define CP_WAIT1()  asm volatile("cp.async.wait_group 1;" ::: "memory")
#define CP_WAIT0()  asm volatile("cp.async.wait_group 0;" ::: "memory")

#define LDMX4(r0, r1, r2, r3, a) \
    asm volatile("ldmatrix.sync.aligned.m8n8.x4.shared.b16 {%0,%1,%2,%3}, [%4];" \
        : "=r"(r0), "=r"(r1), "=r"(r2), "=r"(r3) : "r"(a))

#define MMAF16(d, a, b0, b1) \
    asm volatile("mma.sync.aligned.m16n8k16.row.col.f32.f16.f16.f32 " \
        "{%0,%1,%2,%3}, {%4,%5,%6,%7}, {%8,%9}, {%0,%1,%2,%3};" \
        : "+f"((d)[0]), "+f"((d)[1]), "+f"((d)[2]), "+f"((d)[3]) \
        : "r"((a)[0]), "r"((a)[1]), "r"((a)[2]), "r"((a)[3]), "r"(b0), "r"(b1))

__device__ __forceinline__ unsigned packh2(float x, float y, unsigned& lo) {
    __half hx = __float2half(x);
    __half hy = __float2half(y);
    __half lx = __float2half(x - __half2float(hx));
    __half ly = __float2half(y - __half2float(hy));
    lo = ((unsigned)__half_as_ushort(ly) << 16) | __half_as_ushort(lx);
    return ((unsigned)__half_as_ushort(hy) << 16) | __half_as_ushort(hx);
}
__device__ __forceinline__ unsigned pack_hi2(float x, float y, unsigned& lo) {
    __nv_bfloat16 hx = __float2bfloat16(x);
    __nv_bfloat16 hy = __float2bfloat16(y);
    __nv_bfloat16 lx = __float2bfloat16(x - __bfloat162float(hx));
    __nv_bfloat16 ly = __float2bfloat16(y - __bfloat162float(hy));
    lo = ((unsigned)__bfloat16_as_ushort(ly) << 16) | __bfloat16_as_ushort(lx);
    return ((unsigned)__bfloat16_as_ushort(hy) << 16) | __bfloat16_as_ushort(hx);
}
__device__ __forceinline__ float bflo(unsigned u) {
    return __bfloat162float(__ushort_as_bfloat16((unsigned short)(u & 0xFFFF)));
}
__device__ __forceinline__ float bfhi(unsigned u) {
    return __bfloat162float(__ushort_as_bfloat16((unsigned short)(u >> 16)));
}

// ---------------------------------------------------------------------------
__global__ __launch_bounds__(256) void split_kernel(
    const float* __restrict__ src, __half* __restrict__ hi,
    __half* __restrict__ lo, int n4)
{
    int i = blockIdx.x * 256 + threadIdx.x;
    if (i >= n4) return;
    float4 v = ((const float4*)src)[i];
    unsigned l0, l1, h0, h1;
    h0 = packh2(v.x, v.y, l0);
    h1 = packh2(v.z, v.w, l1);
    ((uint2*)hi)[i] = make_uint2(h0, h1);
    ((uint2*)lo)[i] = make_uint2(l0, l1);
}

__global__ __launch_bounds__(256) void tsingle_kernel(
    const float* __restrict__ W, __half* __restrict__ WT, int K, int N)
{
    __shared__ float t[32][33];
    int k0 = blockIdx.y * 32, n0 = blockIdx.x * 32;
    int tx = threadIdx.x, ty = threadIdx.y;
    #pragma unroll
    for (int i = 0; i < 32; i += 8)
        t[ty + i][tx] = W[(size_t)(k0 + ty + i) * N + n0 + tx];
    __syncthreads();
    #pragma unroll
    for (int i = 0; i < 32; i += 8)
        WT[(size_t)(n0 + ty + i) * K + k0 + tx] = __float2half(t[tx][ty + i]);
}

// V^T + split: reconstruct fp32 from qh+ql, emit vT hi/lo [bh][64][S]
__global__ __launch_bounds__(256) void vT_kernel(
    const __half* __restrict__ qh, const __half* __restrict__ ql,
    __half* __restrict__ vTh, __half* __restrict__ vTl)
{
    __shared__ float t[32][33];
    int s0 = blockIdx.x * 32, d0 = blockIdx.y * 32, bh = blockIdx.z;
    int b = bh >> 4, h = bh & 15;
    int tx = threadIdx.x, ty = threadIdx.y;
    #pragma unroll
    for (int i = 0; i < 32; i += 8) {
        size_t idx = (size_t)(b * SS + s0 + ty + i) * 3072 + h * 192 + 128 + d0 + tx;
        t[ty + i][tx] = __half2float(qh[idx]) + __half2float(ql[idx]);
    }
    __syncthreads();
    #pragma unroll
    for (int i = 0; i < 32; i += 8) {
        float v = t[tx][ty + i];
        __half hh = __float2half(v);
        size_t o = (size_t)(bh * HDIM + d0 + ty + i) * SS + s0 + tx;
        vTh[o] = hh;
        vTl[o] = __float2half(v - __half2float(hh));
    }
}

// ---------------------------------------------------------------------------
// 2-pass fp16 GEMM (unchanged structure; fp32 C now optional)
// ---------------------------------------------------------------------------
#define GS_STAGE 24576
#define GS_TOTAL 73728

__device__ __forceinline__ void gload64h(const __half* __restrict__ src,
                                         int rbase, int K, int kt, unsigned dst, int tid)
{
    #pragma unroll
    for (int i = 0; i < 4; i++) {
        int idx = tid + i * 128;
        int row = idx >> 2;
        int c16 = (idx & 3) * 16;
        CP_ASYNC16(dst + SWZ64((unsigned)(row * 64 + c16)),
                   (const char*)(src + (size_t)(rbase + row) * K + kt) + c16);
    }
}

__device__ __forceinline__ void prefetch_chunk2(
    const __half* __restrict__ Ahi, const __half* __restrict__ Alo,
    const __half* __restrict__ BT,
    int brow, int bcol, int K, int kt, unsigned stage, int tid)
{
    gload64h(Ahi, brow, K, kt, stage, tid);
    gload64h(Alo, brow, K, kt, stage + 8192, tid);
    gload64h(BT, bcol, K, kt, stage + 16384, tid);
}

__global__ __launch_bounds__(128, 2) void gemm2x_mma(
    const __half* __restrict__ Ahi, const __half* __restrict__ Alo,
    const __half* __restrict__ BT,
    const float* __restrict__ bias, float* __restrict__ C,
    __half* __restrict__ Chi, __half* __restrict__ Clo,
    int M, int N, int K)
{
    extern __shared__ char smem[];
    unsigned sb = smem_u32(smem);
    const int tid = threadIdx.x, w = tid >> 5, lane = tid & 31;
    const int brow = blockIdx.y * 128, bcol = blockIdx.x * 128;
    const int wm = (w >> 1) * 64;
    const int wn = (w & 1) * 64;
    const int lrow = lane & 15;
    const int lcol = (lane >> 4) * 16;

    const int nch = K >> 5;

    float acc[4][8][4] = {};

    prefetch_chunk2(Ahi, Alo, BT, brow, bcol, K, 0, sb, tid);
    CP_COMMIT();
    prefetch_chunk2(Ahi, Alo, BT, brow, bcol, K, 32, sb + GS_STAGE, tid);
    CP_COMMIT();
    CP_WAIT1();
    __syncthreads();

    int s_cur = 0;
    for (int c = 0; c < nch; c++) {
        if (c + 2 < nch) {
            int s2 = s_cur + 2; if (s2 >= 3) s2 -= 3;
            prefetch_chunk2(Ahi, Alo, BT, brow, bcol, K, (c + 2) << 5,
                            sb + s2 * GS_STAGE, tid);
            CP_COMMIT();
        }

        unsigned base = sb + s_cur * GS_STAGE;
        #pragma unroll
        for (int ks = 0; ks < 2; ks++) {
            int kb = ks * 32;
            unsigned bF[4][4];
            #pragma unroll
            for (int j2 = 0; j2 < 4; j2++) {
                unsigned off = (unsigned)((wn + j2 * 16 + lrow) * 64 + kb + lcol);
                LDMX4(bF[j2][0], bF[j2][1], bF[j2][2], bF[j2][3], base + 16384 + SWZ64(off));
            }
            #pragma unroll
            for (int i = 0; i < 4; i++) {
                unsigned off = (unsigned)((wm + i * 16 + lrow) * 64 + kb + lcol);
                unsigned aH[4], aL[4];
                LDMX4(aH[0], aH[1], aH[2], aH[3], base + SWZ64(off));
                LDMX4(aL[0], aL[1], aL[2], aL[3], base + 8192 + SWZ64(off));
                #pragma unroll
                for (int j = 0; j < 8; j++) {
                    unsigned b0 = (j & 1) ? bF[j >> 1][1] : bF[j >> 1][0];
                    unsigned b1 = (j & 1) ? bF[j >> 1][3] : bF[j >> 1][2];
                    MMAF16(acc[i][j], aH, b0, b1);
                    MMAF16(acc[i][j], aL, b0, b1);
                }
            }
        }

        if (c + 1 < nch) {
            if (c + 2 < nch) { CP_WAIT1(); } else { CP_WAIT0(); }
        }
        __syncthreads();
        if (++s_cur == 3) s_cur = 0;
    }

    const int r0 = brow + wm + (lane >> 2);
    const int c0 = bcol + wn + (lane & 3) * 2;
    #pragma unroll
    for (int i = 0; i < 4; i++) {
        #pragma unroll
        for (int j = 0; j < 8; j++) {
            int col = c0 + j * 8;
            float bx = bias[col], by = bias[col + 1];
            float v00 = acc[i][j][0] + bx, v01 = acc[i][j][1] + by;
            float v10 = acc[i][j][2] + bx, v11 = acc[i][j][3] + by;
            size_t o0 = (size_t)(r0 + i * 16) * N + col;
            size_t o1 = (size_t)(r0 + i * 16 + 8) * N + col;
            if (C) {
                *(float2*)&C[o0] = make_float2(v00, v01);
                *(float2*)&C[o1] = make_float2(v10, v11);
            }
            if (Chi) {
                unsigned l0, l1;
                unsigned h0 = packh2(v00, v01, l0);
                unsigned h1 = packh2(v10, v11, l1);
                *(unsigned*)&Chi[o0] = h0;
                *(unsigned*)&Clo[o0] = l0;
                *(unsigned*)&Chi[o1] = h1;
                *(unsigned*)&Clo[o1] = l1;
            }
        }
    }
}

// ---------------------------------------------------------------------------
// Kernel A: QK^T (2-pass) + softmax. QT=16, 128 threads.
// Q fragments hoisted to registers; K triple-buffered (prefetch-ahead-2).
// smem: K 3x16384 @0, LH@49152(33024), LL@82176(33024) = 115200 -> 2 CTA/SM.
// ---------------------------------------------------------------------------
#define LA_K0 0
#define LA_LH 49152
#define LA_LL 82176
#define LA_TOTAL 115200
#define PSTRIDE 2064

__device__ __forceinline__ void la_load_k(
    const __half* __restrict__ qh, int b, int h, int kb, unsigned dst, int tid)
{
    #pragma unroll
    for (int i = 0; i < 8; i++) {
        int idx = tid + i * 128;
        int row = idx >> 3, c16 = (idx & 7) * 16;
        unsigned so = SWZ128((unsigned)(row * 128 + c16));
        CP_ASYNC16(dst + so, (const char*)(qh + (size_t)(b * SS + kb + row) * 3072 + h * 192 + 64) + c16);
    }
}

__global__ __launch_bounds__(128, 2) void attn_logits(
    const __half* __restrict__ qh, const __half* __restrict__ ql,
    float* __restrict__ attn_out, __half* __restrict__ pOut)
{
    extern __shared__ char smem[];
    unsigned sb = smem_u32(smem);

    const int qt = blockIdx.x, h = blockIdx.y, b = blockIdx.z;
    const int bh = b * HH + h;
    const int q0 = qt * 16;
    const int tid = threadIdx.x, w = tid >> 5, lane = tid & 31;
    const int lrow = lane & 15, lcol = (lane >> 4) * 16;
    const int wn = w * 32;

    // ---- prologue: Q (into LH temp) + K chunks 0,1
    {
        int row = tid >> 3, c16 = (tid & 7) * 16;
        unsigned so = SWZ128((unsigned)(row * 128 + c16));
        CP_ASYNC16(sb + LA_LH + so, (const char*)(qh + (size_t)(b * SS + q0 + row) * 3072 + h * 192) + c16);
        CP_ASYNC16(sb + LA_LH + 2048 + so, (const char*)(ql + (size_t)(b * SS + q0 + row) * 3072 + h * 192) + c16);
    }
    la_load_k(qh, b, h, 0, sb + LA_K0, tid);
    CP_COMMIT();                               // group: Q + K0
    la_load_k(qh, b, h, 128, sb + LA_K0 + 16384, tid);
    CP_COMMIT();                               // group: K1
    CP_WAIT1();                                // Q + K0 arrived
    __syncthreads();

    // ---- Q fragments -> registers (16 regs hi + 16 lo)
    unsigned qHf[4][4], qLf[4][4];
    #pragma unroll
    for (int ks = 0; ks < 4; ks++) {
        unsigned aoff = SWZ128((unsigned)(lrow * 128 + ks * 32 + lcol));
        LDMX4(qHf[ks][0], qHf[ks][1], qHf[ks][2], qHf[ks][3], sb + LA_LH + aoff);
        LDMX4(qLf[ks][0], qLf[ks][1], qLf[ks][2], qLf[ks][3], sb + LA_LH + 2048 + aoff);
    }
    __syncthreads();   // everyone has Q in regs; LH free for logits

    // ---- phase 1: 8 chunks of 128 keys, triple-buffered
    for (int c = 0; c < 8; c++) {
        if (c + 2 < 8) {
            int s2 = (c + 2) % 3;
            la_load_k(qh, b, h, (c + 2) * 128, sb + LA_K0 + s2 * 16384, tid);
            CP_COMMIT();
        }
        unsigned base = sb + LA_K0 + (c % 3) * 16384;
        float acc[4][4] = {};
        #pragma unroll
        for (int ks = 0; ks < 4; ks++) {
            int kb = ks * 32;
            unsigned bF[2][4];
            #pragma unroll
            for (int j2 = 0; j2 < 2; j2++) {
                unsigned boff = SWZ128((unsigned)((wn + j2 * 16 + lrow) * 128 + kb + lcol));
                LDMX4(bF[j2][0], bF[j2][1], bF[j2][2], bF[j2][3], base + boff);
            }
            #pragma unroll
            for (int j = 0; j < 4; j++) {
                unsigned b0 = (j & 1) ? bF[j >> 1][1] : bF[j >> 1][0];
                unsigned b1 = (j & 1) ? bF[j >> 1][3] : bF[j >> 1][2];
                MMAF16(acc[j], qHf[ks], b0, b1);
                MMAF16(acc[j], qLf[ks], b0, b1);
            }
        }
        // store logits (x0.125) packed bf16 hi/lo
        int r0 = lane >> 2;
        int cb = c * 128 + wn + (lane & 3) * 2;
        #pragma unroll
        for (int j = 0; j < 4; j++) {
            int col = cb + j * 8;
            unsigned lp0, lp1;
            unsigned hp0 = pack_hi2(acc[j][0] * 0.125f, acc[j][1] * 0.125f, lp0);
            unsigned hp1 = pack_hi2(acc[j][2] * 0.125f, acc[j][3] * 0.125f, lp1);
            unsigned o0 = (unsigned)(r0 * PSTRIDE + col * 2);
            unsigned o1 = (unsigned)((r0 + 8) * PSTRIDE + col * 2);
            *(unsigned*)(smem + LA_LH + o0) = hp0;
            *(unsigned*)(smem + LA_LL + o0) = lp0;
            *(unsigned*)(smem + LA_LH + o1) = hp1;
            *(unsigned*)(smem + LA_LL + o1) = lp1;
        }
        if (c + 1 < 8) {
            if (c + 2 < 8) { CP_WAIT1(); } else { CP_WAIT0(); }
        }
        __syncthreads();
    }

    // ---- softmax; write attention fp32 + normalized P fp16
    for (int r = w; r < 16; r += 4) {
        float m = -1e30f;
        #pragma unroll 4
        for (int it = 0; it < 16; it++) {
            unsigned o = (unsigned)(r * PSTRIDE + it * 128 + lane * 4);
            unsigned uh = *(unsigned*)(smem + LA_LH + o);
            unsigned ul = *(unsigned*)(smem + LA_LL + o);
            float l0 = bflo(uh) + bflo(ul);
            float l1 = bfhi(uh) + bfhi(ul);
            m = fmaxf(m, fmaxf(l0, l1));
        }
        #pragma unroll
        for (int o = 16; o > 0; o >>= 1) m = fmaxf(m, __shfl_xor_sync(0xFFFFFFFFu, m, o));
        float sum = 0.f;
        #pragma unroll 4
        for (int it = 0; it < 16; it++) {
            unsigned o = (unsigned)(r * PSTRIDE + it * 128 + lane * 4);
            unsigned uh = *(unsigned*)(smem + LA_LH + o);
            unsigned ul = *(unsigned*)(smem + LA_LL + o);
            float e0 = __expf(bflo(uh) + bflo(ul) - m);
            float e1 = __expf(bfhi(uh) + bfhi(ul) - m);
            sum += e0 + e1;
            unsigned lp;
            unsigned hp = pack_hi2(e0, e1, lp);
            *(unsigned*)(smem + LA_LH + o) = hp;
            *(unsigned*)(smem + LA_LL + o) = lp;
        }
        #pragma unroll
        for (int o = 16; o > 0; o >>= 1) sum += __shfl_xor_sync(0xFFFFFFFFu, sum, o);
        float inv = 1.0f / sum;
        size_t base = ((size_t)(bh * SS) + q0 + r) * SS;
        #pragma unroll 4
        for (int it = 0; it < 16; it++) {
            unsigned o = (unsigned)(r * PSTRIDE + it * 128 + lane * 4);
            unsigned uh = *(unsigned*)(smem + LA_LH + o);
            unsigned ul = *(unsigned*)(smem + LA_LL + o);
            float v0 = (bflo(uh) + bflo(ul)) * inv;
            float v1 = (bfhi(uh) + bfhi(ul)) * inv;
            *(float2*)&attn_out[base + it * 64 + lane * 2] = make_float2(v0, v1);
            __half p0 = __float2half(v0), p1 = __float2half(v1);
            unsigned pu = ((unsigned)__half_as_ushort(p1) << 16) | __half_as_ushort(p0);
            *(unsigned*)&pOut[base + it * 64 + lane * 2] = pu;
        }
    }
}

// ---------------------------------------------------------------------------
// Kernel B: values = P(fp16) @ V^T (fp16 hi/lo, 2-pass). Unchanged from R10.
// ---------------------------------------------------------------------------
#define AV_STAGE 32768
#define AV_TOTAL 98304

__device__ __forceinline__ void av_load(
    const __half* __restrict__ P, const __half* __restrict__ vTh,
    const __half* __restrict__ vTl, int bh, int brow, int kt,
    unsigned stage, int tid)
{
    #pragma unroll
    for (int i = 0; i < 8; i++) {
        int idx = tid + i * 128;
        int row = idx >> 3, c16 = (idx & 7) * 16;
        unsigned so = SWZ128((unsigned)(row * 128 + c16));
        CP_ASYNC16(stage + so, (const char*)(P + ((size_t)(bh * SS + brow + row)) * SS + kt) + c16);
    }
    #pragma unroll
    for (int i = 0; i < 4; i++) {
        int idx = tid + i * 128;
        int row = idx >> 3, c16 = (idx & 7) * 16;
        unsigned so = SWZ128((unsigned)(row * 128 + c16));
        CP_ASYNC16(stage + 16384 + so, (const char*)(vTh + (size_t)(bh * HDIM + row) * SS + kt) + c16);
        CP_ASYNC16(stage + 24576 + so, (const char*)(vTl + (size_t)(bh * HDIM + row) * SS + kt) + c16);
    }
}

__global__ __launch_bounds__(128, 2) void av_gemm(
    const __half* __restrict__ P, const __half* __restrict__ vTh,
    const __half* __restrict__ vTl,
    __half* __restrict__ Vhi, __half* __restrict__ Vlo)
{
    extern __shared__ char smem[];
    unsigned sb = smem_u32(smem);
    const int tid = threadIdx.x, w = tid >> 5, lane = tid & 31;
    const int brow = blockIdx.x * 128;
    const int bh = blockIdx.y;
    const int b = bh >> 4, h = bh & 15;
    const int wm = (w >> 1) * 64;
    const int wn = (w & 1) * 32;
    const int lrow = lane & 15;
    const int lcol = (lane >> 4) * 16;

    const int nch = 16;

    float acc[4][4][4] = {};

    av_load(P, vTh, vTl, bh, brow, 0, sb, tid);
    CP_COMMIT();
    av_load(P, vTh, vTl, bh, brow, 64, sb + AV_STAGE, tid);
    CP_COMMIT();
    CP_WAIT1();
    __syncthreads();

    int s_cur = 0;
    for (int c = 0; c < nch; c++) {
        if (c + 2 < nch) {
            int s2 = s_cur + 2; if (s2 >= 3) s2 -= 3;
            av_load(P, vTh, vTl, bh, brow, (c + 2) * 64, sb + s2 * AV_STAGE, tid);
            CP_COMMIT();
        }

        unsigned base = sb + s_cur * AV_STAGE;
        #pragma unroll
        for (int ks = 0; ks < 4; ks++) {
            int kb = ks * 32;
            unsigned vh[2][4], vl[2][4];
            #pragma unroll
            for (int j2 = 0; j2 < 2; j2++) {
                unsigned off = SWZ128((unsigned)((wn + j2 * 16 + lrow) * 128 + kb + lcol));
                LDMX4(vh[j2][0], vh[j2][1], vh[j2][2], vh[j2][3], base + 16384 + off);
                LDMX4(vl[j2][0], vl[j2][1], vl[j2][2], vl[j2][3], base + 24576 + off);
            }
            #pragma unroll
            for (int i = 0; i < 4; i++) {
                unsigned off = SWZ128((unsigned)((wm + i * 16 + lrow) * 128 + kb + lcol));
                unsigned aF[4];
                LDMX4(aF[0], aF[1], aF[2], aF[3], base + off);
                #pragma unroll
                for (int j = 0; j < 4; j++) {
                    unsigned h0 = (j & 1) ? vh[j >> 1][1] : vh[j >> 1][0];
                    unsigned h1 = (j & 1) ? vh[j >> 1][3] : vh[j >> 1][2];
                    unsigned l0 = (j & 1) ? vl[j >> 1][1] : vl[j >> 1][0];
                    unsigned l1 = (j & 1) ? vl[j >> 1][3] : vl[j >> 1][2];
                    MMAF16(acc[i][j], aF, h0, h1);
                    MMAF16(acc[i][j], aF, l0, l1);
                }
            }
        }

        if (c + 1 < nch) {
            if (c + 2 < nch) { CP_WAIT1(); } else { CP_WAIT0(); }
        }
        __syncthreads();
        if (++s_cur == 3) s_cur = 0;
    }

    const int r0 = brow + wm + (lane >> 2);
    const int c0 = wn + (lane & 3) * 2;
    #pragma unroll
    for (int i = 0; i < 4; i++) {
        #pragma unroll
        for (int j = 0; j < 4; j++) {
            int col = h * 64 + c0 + j * 8;
            size_t o0 = (size_t)(b * SS + r0 + i * 16) * DD + col;
            size_t o1 = (size_t)(b * SS + r0 + i * 16 + 8) * DD + col;
            unsigned l0, l1;
            unsigned h0 = packh2(acc[i][j][0], acc[i][j][1], l0);
            unsigned h1 = packh2(acc[i][j][2], acc[i][j][3], l1);
            *(unsigned*)&Vhi[o0] = h0;
            *(unsigned*)&Vlo[o0] = l0;
            *(unsigned*)&Vhi[o1] = h1;
            *(unsigned*)&Vlo[o1] = l1;
        }
    }
}

// ---------------------------------------------------------------------------
extern "C" void kernel_launch(void* const* d_in, const int* in_sizes, int n_in,
                              void* d_out, int out_size)
{
    const float* x     = (const float*)d_in[0];
    const float* W_qkv = (const float*)d_in[1];
    const float* b_qkv = (const float*)d_in[2];
    const float* W_o   = (const float*)d_in[3];
    const float* b_o   = (const float*)d_in[4];

    float* out_o    = (float*)d_out;
    float* out_attn = (float*)d_out + (size_t)BB * SS * DD;

    __half *xhi, *xlo, *wqT, *woT, *vhi, *vlo, *qhp, *qlp, *vthp, *vtlp, *pp;
    cudaGetSymbolAddress((void**)&xhi, g_xhi);
    cudaGetSymbolAddress((void**)&xlo, g_xlo);
    cudaGetSymbolAddress((void**)&wqT, g_wqT);
    cudaGetSymbolAddress((void**)&woT, g_woT);
    cudaGetSymbolAddress((void**)&vhi, g_vhi);
    cudaGetSymbolAddress((void**)&vlo, g_vlo);
    cudaGetSymbolAddress((void**)&qhp, g_qh);
    cudaGetSymbolAddress((void**)&qlp, g_ql);
    cudaGetSymbolAddress((void**)&vthp, g_vTh);
    cudaGetSymbolAddress((void**)&vtlp, g_vTl);
    cudaGetSymbolAddress((void**)&pp, g_p);

    cudaFuncSetAttribute(gemm2x_mma, cudaFuncAttributeMaxDynamicSharedMemorySize, GS_TOTAL);
    cudaFuncSetAttribute(attn_logits, cudaFuncAttributeMaxDynamicSharedMemorySize, LA_TOTAL);
    cudaFuncSetAttribute(av_gemm, cudaFuncAttributeMaxDynamicSharedMemorySize, AV_TOTAL);

    // 0) prep
    {
        int n4 = BB * SS * DD / 4;
        split_kernel<<<(n4 + 255) / 256, 256>>>(x, xhi, xlo, n4);
        dim3 g1(3 * DD / 32, DD / 32);
        tsingle_kernel<<<g1, dim3(32, 8)>>>(W_qkv, wqT, DD, 3 * DD);
        dim3 g2(DD / 32, DD / 32);
        tsingle_kernel<<<g2, dim3(32, 8)>>>(W_o, woT, DD, DD);
    }

    // 1) QKV projection (2-pass fp16), epilogue emits fp16 hi/lo only
    {
        dim3 grid(3 * DD / 128, BB * SS / 128);
        gemm2x_mma<<<grid, 128, GS_TOTAL>>>(xhi, xlo, wqT, b_qkv, (float*)nullptr,
                                            qhp, qlp, BB * SS, 3 * DD, DD);
    }

    // 2) V^T split (reconstructs fp32 from qh+ql)
    {
        dim3 gv(SS / 32, HDIM / 32, BB * HH);
        vT_kernel<<<gv, dim3(32, 8)>>>(qhp, qlp, vthp, vtlp);
    }

    // 3a) QK^T (2-pass, pipelined) + softmax, writes attention + P fp16
    {
        dim3 grid(SS / 16, HH, BB);
        attn_logits<<<grid, 128, LA_TOTAL>>>(qhp, qlp, out_attn, pp);
    }

    // 3b) AV gemm (2-pass)
    {
        dim3 grid(SS / 128, BB * HH);
        av_gemm<<<grid, 128, AV_TOTAL>>>(pp, vthp, vtlp, vhi, vlo);
    }

    // 4) O-proj (2-pass fp16)
    {
        dim3 grid(DD / 128, BB * SS / 128);
        gemm2x_mma<<<grid, 128, GS_TOTAL>>>(vhi, vlo, woT, b_o, out_o,
                                            (__half*)nullptr, (__half*)nullptr,
                                            BB * SS, DD, DD);
    }
}

// round 12
// speedup vs baseline: 1.6118x; 1.1648x over previous
#include <cuda_runtime.h>
#include <cuda_bf16.h>
#include <cuda_fp16.h>

#define BB 4
#define SS 1024
#define HH 16
#define HDIM 64
#define DD 1024

// ---------------------------------------------------------------------------
// scratch (device globals — no allocation allowed)
// ---------------------------------------------------------------------------
__device__ __half g_xhi[BB * SS * DD];
__device__ __half g_xlo[BB * SS * DD];
__device__ __half g_wqT[3 * DD * DD];           // W_qkv^T fp16 single
__device__ __half g_woT[DD * DD];               // W_o^T fp16 single
__device__ __half g_vhi[BB * SS * DD];          // values hi (av epilogue)
__device__ __half g_vlo[BB * SS * DD];
__device__ __half g_qh[BB * SS * 3 * DD];       // qkv hi (gemm epilogue)
__device__ __half g_ql[BB * SS * 3 * DD];       // qkv lo
__device__ __half g_vTh[BB * HH * HDIM * SS];   // V^T fp16 per (b,h): [64][S]
__device__ __half g_p[(size_t)BB * HH * SS * SS]; // normalized attention fp16

// ---------------------------------------------------------------------------
__device__ __forceinline__ unsigned smem_u32(const void* p) {
    unsigned a;
    asm("{ .reg .u64 t; cvta.to.shared.u64 t, %1; cvt.u32.u64 %0, t; }" : "=r"(a) : "l"(p));
    return a;
}
#define SWZ128(o) ((o) ^ (((o) >> 3) & 0x70))
#define SWZ64(o)  ((o) ^ (((o) >> 3) & 0x30))

#define CP_ASYNC16(saddr, gptr) \
    asm volatile("cp.async.cg.shared.global [%0], [%1], 16;" :: "r"(saddr), "l"(gptr) : "memory")
#define CP_COMMIT() asm volatile("cp.async.commit_group;" ::: "memory")
#define CP_WAIT1()  asm volatile("cp.async.wait_group 1;" ::: "memory")
#define CP_WAIT0()  asm volatile("cp.async.wait_group 0;" ::: "memory")

#define LDMX4(r0, r1, r2, r3, a) \
    asm volatile("ldmatrix.sync.aligned.m8n8.x4.shared.b16 {%0,%1,%2,%3}, [%4];" \
        : "=r"(r0), "=r"(r1), "=r"(r2), "=r"(r3) : "r"(a))

#define MMAF16(d, a, b0, b1) \
    asm volatile("mma.sync.aligned.m16n8k16.row.col.f32.f16.f16.f32 " \
        "{%0,%1,%2,%3}, {%4,%5,%6,%7}, {%8,%9}, {%0,%1,%2,%3};" \
        : "+f"((d)[0]), "+f"((d)[1]), "+f"((d)[2]), "+f"((d)[3]) \
        : "r"((a)[0]), "r"((a)[1]), "r"((a)[2]), "r"((a)[3]), "r"(b0), "r"(b1))

__device__ __forceinline__ unsigned packh2(float x, float y, unsigned& lo) {
    __half hx = __float2half(x);
    __half hy = __float2half(y);
    __half lx = __float2half(x - __half2float(hx));
    __half ly = __float2half(y - __half2float(hy));
    lo = ((unsigned)__half_as_ushort(ly) << 16) | __half_as_ushort(lx);
    return ((unsigned)__half_as_ushort(hy) << 16) | __half_as_ushort(hx);
}

// ---------------------------------------------------------------------------
__global__ __launch_bounds__(256) void split_kernel(
    const float* __restrict__ src, __half* __restrict__ hi,
    __half* __restrict__ lo, int n4)
{
    int i = blockIdx.x * 256 + threadIdx.x;
    if (i >= n4) return;
    float4 v = ((const float4*)src)[i];
    unsigned l0, l1, h0, h1;
    h0 = packh2(v.x, v.y, l0);
    h1 = packh2(v.z, v.w, l1);
    ((uint2*)hi)[i] = make_uint2(h0, h1);
    ((uint2*)lo)[i] = make_uint2(l0, l1);
}

__global__ __launch_bounds__(256) void tsingle_kernel(
    const float* __restrict__ W, __half* __restrict__ WT, int K, int N)
{
    __shared__ float t[32][33];
    int k0 = blockIdx.y * 32, n0 = blockIdx.x * 32;
    int tx = threadIdx.x, ty = threadIdx.y;
    #pragma unroll
    for (int i = 0; i < 32; i += 8)
        t[ty + i][tx] = W[(size_t)(k0 + ty + i) * N + n0 + tx];
    __syncthreads();
    #pragma unroll
    for (int i = 0; i < 32; i += 8)
        WT[(size_t)(n0 + ty + i) * K + k0 + tx] = __float2half(t[tx][ty + i]);
}

// V^T: pure fp16 transpose of qh V-slice -> vTh [bh][64][S]
__global__ __launch_bounds__(256) void vT_kernel(
    const __half* __restrict__ qh, __half* __restrict__ vTh)
{
    __shared__ __half t[32][33];
    int s0 = blockIdx.x * 32, d0 = blockIdx.y * 32, bh = blockIdx.z;
    int b = bh >> 4, h = bh & 15;
    int tx = threadIdx.x, ty = threadIdx.y;
    #pragma unroll
    for (int i = 0; i < 32; i += 8)
        t[ty + i][tx] = qh[(size_t)(b * SS + s0 + ty + i) * 3072 + h * 192 + 128 + d0 + tx];
    __syncthreads();
    #pragma unroll
    for (int i = 0; i < 32; i += 8)
        vTh[(size_t)(bh * HDIM + d0 + ty + i) * SS + s0 + tx] = t[tx][ty + i];
}

// ---------------------------------------------------------------------------
// 2-pass fp16 GEMM (unchanged from R11)
// ---------------------------------------------------------------------------
#define GS_STAGE 24576
#define GS_TOTAL 73728

__device__ __forceinline__ void gload64h(const __half* __restrict__ src,
                                         int rbase, int K, int kt, unsigned dst, int tid)
{
    #pragma unroll
    for (int i = 0; i < 4; i++) {
        int idx = tid + i * 128;
        int row = idx >> 2;
        int c16 = (idx & 3) * 16;
        CP_ASYNC16(dst + SWZ64((unsigned)(row * 64 + c16)),
                   (const char*)(src + (size_t)(rbase + row) * K + kt) + c16);
    }
}

__device__ __forceinline__ void prefetch_chunk2(
    const __half* __restrict__ Ahi, const __half* __restrict__ Alo,
    const __half* __restrict__ BT,
    int brow, int bcol, int K, int kt, unsigned stage, int tid)
{
    gload64h(Ahi, brow, K, kt, stage, tid);
    gload64h(Alo, brow, K, kt, stage + 8192, tid);
    gload64h(BT, bcol, K, kt, stage + 16384, tid);
}

__global__ __launch_bounds__(128, 2) void gemm2x_mma(
    const __half* __restrict__ Ahi, const __half* __restrict__ Alo,
    const __half* __restrict__ BT,
    const float* __restrict__ bias, float* __restrict__ C,
    __half* __restrict__ Chi, __half* __restrict__ Clo,
    int M, int N, int K)
{
    extern __shared__ char smem[];
    unsigned sb = smem_u32(smem);
    const int tid = threadIdx.x, w = tid >> 5, lane = tid & 31;
    const int brow = blockIdx.y * 128, bcol = blockIdx.x * 128;
    const int wm = (w >> 1) * 64;
    const int wn = (w & 1) * 64;
    const int lrow = lane & 15;
    const int lcol = (lane >> 4) * 16;

    const int nch = K >> 5;

    float acc[4][8][4] = {};

    prefetch_chunk2(Ahi, Alo, BT, brow, bcol, K, 0, sb, tid);
    CP_COMMIT();
    prefetch_chunk2(Ahi, Alo, BT, brow, bcol, K, 32, sb + GS_STAGE, tid);
    CP_COMMIT();
    CP_WAIT1();
    __syncthreads();

    int s_cur = 0;
    for (int c = 0; c < nch; c++) {
        if (c + 2 < nch) {
            int s2 = s_cur + 2; if (s2 >= 3) s2 -= 3;
            prefetch_chunk2(Ahi, Alo, BT, brow, bcol, K, (c + 2) << 5,
                            sb + s2 * GS_STAGE, tid);
            CP_COMMIT();
        }

        unsigned base = sb + s_cur * GS_STAGE;
        #pragma unroll
        for (int ks = 0; ks < 2; ks++) {
            int kb = ks * 32;
            unsigned bF[4][4];
            #pragma unroll
            for (int j2 = 0; j2 < 4; j2++) {
                unsigned off = (unsigned)((wn + j2 * 16 + lrow) * 64 + kb + lcol);
                LDMX4(bF[j2][0], bF[j2][1], bF[j2][2], bF[j2][3], base + 16384 + SWZ64(off));
            }
            #pragma unroll
            for (int i = 0; i < 4; i++) {
                unsigned off = (unsigned)((wm + i * 16 + lrow) * 64 + kb + lcol);
                unsigned aH[4], aL[4];
                LDMX4(aH[0], aH[1], aH[2], aH[3], base + SWZ64(off));
                LDMX4(aL[0], aL[1], aL[2], aL[3], base + 8192 + SWZ64(off));
                #pragma unroll
                for (int j = 0; j < 8; j++) {
                    unsigned b0 = (j & 1) ? bF[j >> 1][1] : bF[j >> 1][0];
                    unsigned b1 = (j & 1) ? bF[j >> 1][3] : bF[j >> 1][2];
                    MMAF16(acc[i][j], aH, b0, b1);
                    MMAF16(acc[i][j], aL, b0, b1);
                }
            }
        }

        if (c + 1 < nch) {
            if (c + 2 < nch) { CP_WAIT1(); } else { CP_WAIT0(); }
        }
        __syncthreads();
        if (++s_cur == 3) s_cur = 0;
    }

    const int r0 = brow + wm + (lane >> 2);
    const int c0 = bcol + wn + (lane & 3) * 2;
    #pragma unroll
    for (int i = 0; i < 4; i++) {
        #pragma unroll
        for (int j = 0; j < 8; j++) {
            int col = c0 + j * 8;
            float bx = bias[col], by = bias[col + 1];
            float v00 = acc[i][j][0] + bx, v01 = acc[i][j][1] + by;
            float v10 = acc[i][j][2] + bx, v11 = acc[i][j][3] + by;
            size_t o0 = (size_t)(r0 + i * 16) * N + col;
            size_t o1 = (size_t)(r0 + i * 16 + 8) * N + col;
            if (C) {
                *(float2*)&C[o0] = make_float2(v00, v01);
                *(float2*)&C[o1] = make_float2(v10, v11);
            }
            if (Chi) {
                unsigned l0, l1;
                unsigned h0 = packh2(v00, v01, l0);
                unsigned h1 = packh2(v10, v11, l1);
                *(unsigned*)&Chi[o0] = h0;
                *(unsigned*)&Clo[o0] = l0;
                *(unsigned*)&Chi[o1] = h1;
                *(unsigned*)&Clo[o1] = l1;
            }
        }
    }
}

// ---------------------------------------------------------------------------
// Kernel A: QK^T (2-pass) + softmax. QT=16, 128 threads.
// Q fragments in registers; K triple-buffered. Logits stored fp32 single.
// smem: K 3x16384 @0, LF fp32 @49152 (16 x 4128B = 66048) = 115200 total.
// ---------------------------------------------------------------------------
#define LA_K0 0
#define LA_LF 49152
#define LA_TOTAL 115200
#define PSTRB 4128   // bytes per logit row (1032 floats)

__device__ __forceinline__ void la_load_k(
    const __half* __restrict__ qh, int b, int h, int kb, unsigned dst, int tid)
{
    #pragma unroll
    for (int i = 0; i < 8; i++) {
        int idx = tid + i * 128;
        int row = idx >> 3, c16 = (idx & 7) * 16;
        unsigned so = SWZ128((unsigned)(row * 128 + c16));
        CP_ASYNC16(dst + so, (const char*)(qh + (size_t)(b * SS + kb + row) * 3072 + h * 192 + 64) + c16);
    }
}

__global__ __launch_bounds__(128, 2) void attn_logits(
    const __half* __restrict__ qh, const __half* __restrict__ ql,
    float* __restrict__ attn_out, __half* __restrict__ pOut)
{
    extern __shared__ char smem[];
    unsigned sb = smem_u32(smem);

    const int qt = blockIdx.x, h = blockIdx.y, b = blockIdx.z;
    const int bh = b * HH + h;
    const int q0 = qt * 16;
    const int tid = threadIdx.x, w = tid >> 5, lane = tid & 31;
    const int lrow = lane & 15, lcol = (lane >> 4) * 16;
    const int wn = w * 32;

    // ---- prologue: Q (into LF temp) + K chunks 0,1
    {
        int row = tid >> 3, c16 = (tid & 7) * 16;
        unsigned so = SWZ128((unsigned)(row * 128 + c16));
        CP_ASYNC16(sb + LA_LF + so, (const char*)(qh + (size_t)(b * SS + q0 + row) * 3072 + h * 192) + c16);
        CP_ASYNC16(sb + LA_LF + 2048 + so, (const char*)(ql + (size_t)(b * SS + q0 + row) * 3072 + h * 192) + c16);
    }
    la_load_k(qh, b, h, 0, sb + LA_K0, tid);
    CP_COMMIT();
    la_load_k(qh, b, h, 128, sb + LA_K0 + 16384, tid);
    CP_COMMIT();
    CP_WAIT1();
    __syncthreads();

    // ---- Q fragments -> registers
    unsigned qHf[4][4], qLf[4][4];
    #pragma unroll
    for (int ks = 0; ks < 4; ks++) {
        unsigned aoff = SWZ128((unsigned)(lrow * 128 + ks * 32 + lcol));
        LDMX4(qHf[ks][0], qHf[ks][1], qHf[ks][2], qHf[ks][3], sb + LA_LF + aoff);
        LDMX4(qLf[ks][0], qLf[ks][1], qLf[ks][2], qLf[ks][3], sb + LA_LF + 2048 + aoff);
    }
    __syncthreads();

    // ---- phase 1: 8 chunks of 128 keys, triple-buffered
    for (int c = 0; c < 8; c++) {
        if (c + 2 < 8) {
            int s2 = (c + 2) % 3;
            la_load_k(qh, b, h, (c + 2) * 128, sb + LA_K0 + s2 * 16384, tid);
            CP_COMMIT();
        }
        unsigned base = sb + LA_K0 + (c % 3) * 16384;
        float acc[4][4] = {};
        #pragma unroll
        for (int ks = 0; ks < 4; ks++) {
            int kb = ks * 32;
            unsigned bF[2][4];
            #pragma unroll
            for (int j2 = 0; j2 < 2; j2++) {
                unsigned boff = SWZ128((unsigned)((wn + j2 * 16 + lrow) * 128 + kb + lcol));
                LDMX4(bF[j2][0], bF[j2][1], bF[j2][2], bF[j2][3], base + boff);
            }
            #pragma unroll
            for (int j = 0; j < 4; j++) {
                unsigned b0 = (j & 1) ? bF[j >> 1][1] : bF[j >> 1][0];
                unsigned b1 = (j & 1) ? bF[j >> 1][3] : bF[j >> 1][2];
                MMAF16(acc[j], qHf[ks], b0, b1);
                MMAF16(acc[j], qLf[ks], b0, b1);
            }
        }
        // store logits (x0.125) fp32
        int r0 = lane >> 2;
        int cb = c * 128 + wn + (lane & 3) * 2;
        #pragma unroll
        for (int j = 0; j < 4; j++) {
            int col = cb + j * 8;
            *(float2*)(smem + LA_LF + r0 * PSTRB + col * 4) =
                make_float2(acc[j][0] * 0.125f, acc[j][1] * 0.125f);
            *(float2*)(smem + LA_LF + (r0 + 8) * PSTRB + col * 4) =
                make_float2(acc[j][2] * 0.125f, acc[j][3] * 0.125f);
        }
        if (c + 1 < 8) {
            if (c + 2 < 8) { CP_WAIT1(); } else { CP_WAIT0(); }
        }
        __syncthreads();
    }

    // ---- softmax over fp32 logits; write attention fp32 + P fp16
    for (int r = w; r < 16; r += 4) {
        const char* rowp = smem + LA_LF + r * PSTRB;
        float m = -1e30f;
        #pragma unroll 4
        for (int it = 0; it < 16; it++) {
            float2 v = *(const float2*)(rowp + it * 256 + lane * 8);
            m = fmaxf(m, fmaxf(v.x, v.y));
        }
        #pragma unroll
        for (int o = 16; o > 0; o >>= 1) m = fmaxf(m, __shfl_xor_sync(0xFFFFFFFFu, m, o));
        float sum = 0.f;
        #pragma unroll 4
        for (int it = 0; it < 16; it++) {
            float2* vp = (float2*)(rowp + it * 256 + lane * 8);
            float2 v = *vp;
            float e0 = __expf(v.x - m);
            float e1 = __expf(v.y - m);
            sum += e0 + e1;
            *vp = make_float2(e0, e1);
        }
        #pragma unroll
        for (int o = 16; o > 0; o >>= 1) sum += __shfl_xor_sync(0xFFFFFFFFu, sum, o);
        float inv = 1.0f / sum;
        size_t base = ((size_t)(bh * SS) + q0 + r) * SS;
        #pragma unroll 4
        for (int it = 0; it < 16; it++) {
            float2 v = *(const float2*)(rowp + it * 256 + lane * 8);
            float v0 = v.x * inv, v1 = v.y * inv;
            *(float2*)&attn_out[base + it * 64 + lane * 2] = make_float2(v0, v1);
            __half p0 = __float2half(v0), p1 = __float2half(v1);
            unsigned pu = ((unsigned)__half_as_ushort(p1) << 16) | __half_as_ushort(p0);
            *(unsigned*)&pOut[base + it * 64 + lane * 2] = pu;
        }
    }
}

// ---------------------------------------------------------------------------
// Kernel B: values = P(fp16) @ V^T (fp16 single pass). M=128/N=64/K=1024.
// stage: P 16KB @0, Vh 8KB @16384 = 24KB; 3 stages.
// ---------------------------------------------------------------------------
#define AV_STAGE 24576
#define AV_TOTAL 73728

__device__ __forceinline__ void av_load(
    const __half* __restrict__ P, const __half* __restrict__ vTh,
    int bh, int brow, int kt, unsigned stage, int tid)
{
    #pragma unroll
    for (int i = 0; i < 8; i++) {
        int idx = tid + i * 128;
        int row = idx >> 3, c16 = (idx & 7) * 16;
        unsigned so = SWZ128((unsigned)(row * 128 + c16));
        CP_ASYNC16(stage + so, (const char*)(P + ((size_t)(bh * SS + brow + row)) * SS + kt) + c16);
    }
    #pragma unroll
    for (int i = 0; i < 4; i++) {
        int idx = tid + i * 128;
        int row = idx >> 3, c16 = (idx & 7) * 16;
        unsigned so = SWZ128((unsigned)(row * 128 + c16));
        CP_ASYNC16(stage + 16384 + so, (const char*)(vTh + (size_t)(bh * HDIM + row) * SS + kt) + c16);
    }
}

__global__ __launch_bounds__(128, 2) void av_gemm(
    const __half* __restrict__ P, const __half* __restrict__ vTh,
    __half* __restrict__ Vhi, __half* __restrict__ Vlo)
{
    extern __shared__ char smem[];
    unsigned sb = smem_u32(smem);
    const int tid = threadIdx.x, w = tid >> 5, lane = tid & 31;
    const int brow = blockIdx.x * 128;
    const int bh = blockIdx.y;
    const int b = bh >> 4, h = bh & 15;
    const int wm = (w >> 1) * 64;
    const int wn = (w & 1) * 32;
    const int lrow = lane & 15;
    const int lcol = (lane >> 4) * 16;

    const int nch = 16;

    float acc[4][4][4] = {};

    av_load(P, vTh, bh, brow, 0, sb, tid);
    CP_COMMIT();
    av_load(P, vTh, bh, brow, 64, sb + AV_STAGE, tid);
    CP_COMMIT();
    CP_WAIT1();
    __syncthreads();

    int s_cur = 0;
    for (int c = 0; c < nch; c++) {
        if (c + 2 < nch) {
            int s2 = s_cur + 2; if (s2 >= 3) s2 -= 3;
            av_load(P, vTh, bh, brow, (c + 2) * 64, sb + s2 * AV_STAGE, tid);
            CP_COMMIT();
        }

        unsigned base = sb + s_cur * AV_STAGE;
        #pragma unroll
        for (int ks = 0; ks < 4; ks++) {
            int kb = ks * 32;
            unsigned vh[2][4];
            #pragma unroll
            for (int j2 = 0; j2 < 2; j2++) {
                unsigned off = SWZ128((unsigned)((wn + j2 * 16 + lrow) * 128 + kb + lcol));
                LDMX4(vh[j2][0], vh[j2][1], vh[j2][2], vh[j2][3], base + 16384 + off);
            }
            #pragma unroll
            for (int i = 0; i < 4; i++) {
                unsigned off = SWZ128((unsigned)((wm + i * 16 + lrow) * 128 + kb + lcol));
                unsigned aF[4];
                LDMX4(aF[0], aF[1], aF[2], aF[3], base + off);
                #pragma unroll
                for (int j = 0; j < 4; j++) {
                    unsigned h0 = (j & 1) ? vh[j >> 1][1] : vh[j >> 1][0];
                    unsigned h1 = (j & 1) ? vh[j >> 1][3] : vh[j >> 1][2];
                    MMAF16(acc[i][j], aF, h0, h1);
                }
            }
        }

        if (c + 1 < nch) {
            if (c + 2 < nch) { CP_WAIT1(); } else { CP_WAIT0(); }
        }
        __syncthreads();
        if (++s_cur == 3) s_cur = 0;
    }

    const int r0 = brow + wm + (lane >> 2);
    const int c0 = wn + (lane & 3) * 2;
    #pragma unroll
    for (int i = 0; i < 4; i++) {
        #pragma unroll
        for (int j = 0; j < 4; j++) {
            int col = h * 64 + c0 + j * 8;
            size_t o0 = (size_t)(b * SS + r0 + i * 16) * DD + col;
            size_t o1 = (size_t)(b * SS + r0 + i * 16 + 8) * DD + col;
            unsigned l0, l1;
            unsigned h0 = packh2(acc[i][j][0], acc[i][j][1], l0);
            unsigned h1 = packh2(acc[i][j][2], acc[i][j][3], l1);
            *(unsigned*)&Vhi[o0] = h0;
            *(unsigned*)&Vlo[o0] = l0;
            *(unsigned*)&Vhi[o1] = h1;
            *(unsigned*)&Vlo[o1] = l1;
        }
    }
}

// ---------------------------------------------------------------------------
extern "C" void kernel_launch(void* const* d_in, const int* in_sizes, int n_in,
                              void* d_out, int out_size)
{
    const float* x     = (const float*)d_in[0];
    const float* W_qkv = (const float*)d_in[1];
    const float* b_qkv = (const float*)d_in[2];
    const float* W_o   = (const float*)d_in[3];
    const float* b_o   = (const float*)d_in[4];

    float* out_o    = (float*)d_out;
    float* out_attn = (float*)d_out + (size_t)BB * SS * DD;

    __half *xhi, *xlo, *wqT, *woT, *vhi, *vlo, *qhp, *qlp, *vthp, *pp;
    cudaGetSymbolAddress((void**)&xhi, g_xhi);
    cudaGetSymbolAddress((void**)&xlo, g_xlo);
    cudaGetSymbolAddress((void**)&wqT, g_wqT);
    cudaGetSymbolAddress((void**)&woT, g_woT);
    cudaGetSymbolAddress((void**)&vhi, g_vhi);
    cudaGetSymbolAddress((void**)&vlo, g_vlo);
    cudaGetSymbolAddress((void**)&qhp, g_qh);
    cudaGetSymbolAddress((void**)&qlp, g_ql);
    cudaGetSymbolAddress((void**)&vthp, g_vTh);
    cudaGetSymbolAddress((void**)&pp, g_p);

    cudaFuncSetAttribute(gemm2x_mma, cudaFuncAttributeMaxDynamicSharedMemorySize, GS_TOTAL);
    cudaFuncSetAttribute(attn_logits, cudaFuncAttributeMaxDynamicSharedMemorySize, LA_TOTAL);
    cudaFuncSetAttribute(av_gemm, cudaFuncAttributeMaxDynamicSharedMemorySize, AV_TOTAL);

    // 0) prep
    {
        int n4 = BB * SS * DD / 4;
        split_kernel<<<(n4 + 255) / 256, 256>>>(x, xhi, xlo, n4);
        dim3 g1(3 * DD / 32, DD / 32);
        tsingle_kernel<<<g1, dim3(32, 8)>>>(W_qkv, wqT, DD, 3 * DD);
        dim3 g2(DD / 32, DD / 32);
        tsingle_kernel<<<g2, dim3(32, 8)>>>(W_o, woT, DD, DD);
    }

    // 1) QKV projection (2-pass fp16), epilogue emits fp16 hi/lo only
    {
        dim3 grid(3 * DD / 128, BB * SS / 128);
        gemm2x_mma<<<grid, 128, GS_TOTAL>>>(xhi, xlo, wqT, b_qkv, (float*)nullptr,
                                            qhp, qlp, BB * SS, 3 * DD, DD);
    }

    // 2) V^T (pure fp16 transpose of qh V-slice)
    {
        dim3 gv(SS / 32, HDIM / 32, BB * HH);
        vT_kernel<<<gv, dim3(32, 8)>>>(qhp, vthp);
    }

    // 3a) QK^T (2-pass, pipelined) + softmax, writes attention + P fp16
    {
        dim3 grid(SS / 16, HH, BB);
        attn_logits<<<grid, 128, LA_TOTAL>>>(qhp, qlp, out_attn, pp);
    }

    // 3b) AV gemm (single-pass V)
    {
        dim3 grid(SS / 128, BB * HH);
        av_gemm<<<grid, 128, AV_TOTAL>>>(pp, vthp, vhi, vlo);
    }

    // 4) O-proj (2-pass fp16)
    {
        dim3 grid(DD / 128, BB * SS / 128);
        gemm2x_mma<<<grid, 128, GS_TOTAL>>>(vhi, vlo, woT, b_o, out_o,
                                            (__half*)nullptr, (__half*)nullptr,
                                            BB * SS, DD, DD);
    }
}

// round 13
// speedup vs baseline: 1.7414x; 1.0804x over previous
#include <cuda_runtime.h>
#include <cuda_bf16.h>
#include <cuda_fp16.h>

#define BB 4
#define SS 1024
#define HH 16
#define HDIM 64
#define DD 1024

// ---------------------------------------------------------------------------
// scratch (device globals — no allocation allowed)
// ---------------------------------------------------------------------------
__device__ __half g_xhi[BB * SS * DD];
__device__ __half g_xlo[BB * SS * DD];
__device__ __half g_wqT[3 * DD * DD];           // W_qkv^T fp16 single
__device__ __half g_woT[DD * DD];               // W_o^T fp16 single
__device__ __half g_vh[BB * SS * DD];           // values fp16 single (av epilogue)
__device__ __half g_qh[BB * SS * 3 * DD];       // qkv hi (gemm epilogue)
__device__ __half g_ql[BB * SS * 3 * DD];       // qkv lo
__device__ __half g_vTh[BB * HH * HDIM * SS];   // V^T fp16 per (b,h): [64][S]
__device__ __half g_p[(size_t)BB * HH * SS * SS]; // normalized attention fp16

// ---------------------------------------------------------------------------
__device__ __forceinline__ unsigned smem_u32(const void* p) {
    unsigned a;
    asm("{ .reg .u64 t; cvta.to.shared.u64 t, %1; cvt.u32.u64 %0, t; }" : "=r"(a) : "l"(p));
    return a;
}
#define SWZ128(o) ((o) ^ (((o) >> 3) & 0x70))
#define SWZ64(o)  ((o) ^ (((o) >> 3) & 0x30))

#define CP_ASYNC16(saddr, gptr) \
    asm volatile("cp.async.cg.shared.global [%0], [%1], 16;" :: "r"(saddr), "l"(gptr) : "memory")
#define CP_COMMIT() asm volatile("cp.async.commit_group;" ::: "memory")
#define CP_WAIT1()  asm volatile("cp.async.wait_group 1;" ::: "memory")
#define CP_WAIT0()  asm volatile("cp.async.wait_group 0;" ::: "memory")

#define LDMX4(r0, r1, r2, r3, a) \
    asm volatile("ldmatrix.sync.aligned.m8n8.x4.shared.b16 {%0,%1,%2,%3}, [%4];" \
        : "=r"(r0), "=r"(r1), "=r"(r2), "=r"(r3) : "r"(a))

#define MMAF16(d, a, b0, b1) \
    asm volatile("mma.sync.aligned.m16n8k16.row.col.f32.f16.f16.f32 " \
        "{%0,%1,%2,%3}, {%4,%5,%6,%7}, {%8,%9}, {%0,%1,%2,%3};" \
        : "+f"((d)[0]), "+f"((d)[1]), "+f"((d)[2]), "+f"((d)[3]) \
        : "r"((a)[0]), "r"((a)[1]), "r"((a)[2]), "r"((a)[3]), "r"(b0), "r"(b1))

__device__ __forceinline__ unsigned packh2(float x, float y, unsigned& lo) {
    __half hx = __float2half(x);
    __half hy = __float2half(y);
    __half lx = __float2half(x - __half2float(hx));
    __half ly = __float2half(y - __half2float(hy));
    lo = ((unsigned)__half_as_ushort(ly) << 16) | __half_as_ushort(lx);
    return ((unsigned)__half_as_ushort(hy) << 16) | __half_as_ushort(hx);
}
__device__ __forceinline__ unsigned packs2(float x, float y) {
    return ((unsigned)__half_as_ushort(__float2half(y)) << 16) |
           __half_as_ushort(__float2half(x));
}

// ---------------------------------------------------------------------------
__global__ __launch_bounds__(256) void split_kernel(
    const float* __restrict__ src, __half* __restrict__ hi,
    __half* __restrict__ lo, int n4)
{
    int i = blockIdx.x * 256 + threadIdx.x;
    if (i >= n4) return;
    float4 v = ((const float4*)src)[i];
    unsigned l0, l1, h0, h1;
    h0 = packh2(v.x, v.y, l0);
    h1 = packh2(v.z, v.w, l1);
    ((uint2*)hi)[i] = make_uint2(h0, h1);
    ((uint2*)lo)[i] = make_uint2(l0, l1);
}

__global__ __launch_bounds__(256) void tsingle_kernel(
    const float* __restrict__ W, __half* __restrict__ WT, int K, int N)
{
    __shared__ float t[32][33];
    int k0 = blockIdx.y * 32, n0 = blockIdx.x * 32;
    int tx = threadIdx.x, ty = threadIdx.y;
    #pragma unroll
    for (int i = 0; i < 32; i += 8)
        t[ty + i][tx] = W[(size_t)(k0 + ty + i) * N + n0 + tx];
    __syncthreads();
    #pragma unroll
    for (int i = 0; i < 32; i += 8)
        WT[(size_t)(n0 + ty + i) * K + k0 + tx] = __float2half(t[tx][ty + i]);
}

// V^T: pure fp16 transpose of qh V-slice -> vTh [bh][64][S]
__global__ __launch_bounds__(256) void vT_kernel(
    const __half* __restrict__ qh, __half* __restrict__ vTh)
{
    __shared__ __half t[32][33];
    int s0 = blockIdx.x * 32, d0 = blockIdx.y * 32, bh = blockIdx.z;
    int b = bh >> 4, h = bh & 15;
    int tx = threadIdx.x, ty = threadIdx.y;
    #pragma unroll
    for (int i = 0; i < 32; i += 8)
        t[ty + i][tx] = qh[(size_t)(b * SS + s0 + ty + i) * 3072 + h * 192 + 128 + d0 + tx];
    __syncthreads();
    #pragma unroll
    for (int i = 0; i < 32; i += 8)
        vTh[(size_t)(bh * HDIM + d0 + ty + i) * SS + s0 + tx] = t[tx][ty + i];
}

// ---------------------------------------------------------------------------
// 2-pass fp16 GEMM (QKV only; unchanged)
// ---------------------------------------------------------------------------
#define GS_STAGE 24576
#define GS_TOTAL 73728

__device__ __forceinline__ void gload64h(const __half* __restrict__ src,
                                         int rbase, int K, int kt, unsigned dst, int tid)
{
    #pragma unroll
    for (int i = 0; i < 4; i++) {
        int idx = tid + i * 128;
        int row = idx >> 2;
        int c16 = (idx & 3) * 16;
        CP_ASYNC16(dst + SWZ64((unsigned)(row * 64 + c16)),
                   (const char*)(src + (size_t)(rbase + row) * K + kt) + c16);
    }
}

__device__ __forceinline__ void prefetch_chunk2(
    const __half* __restrict__ Ahi, const __half* __restrict__ Alo,
    const __half* __restrict__ BT,
    int brow, int bcol, int K, int kt, unsigned stage, int tid)
{
    gload64h(Ahi, brow, K, kt, stage, tid);
    gload64h(Alo, brow, K, kt, stage + 8192, tid);
    gload64h(BT, bcol, K, kt, stage + 16384, tid);
}

__global__ __launch_bounds__(128, 2) void gemm2x_mma(
    const __half* __restrict__ Ahi, const __half* __restrict__ Alo,
    const __half* __restrict__ BT,
    const float* __restrict__ bias,
    __half* __restrict__ Chi, __half* __restrict__ Clo,
    int M, int N, int K)
{
    extern __shared__ char smem[];
    unsigned sb = smem_u32(smem);
    const int tid = threadIdx.x, w = tid >> 5, lane = tid & 31;
    const int brow = blockIdx.y * 128, bcol = blockIdx.x * 128;
    const int wm = (w >> 1) * 64;
    const int wn = (w & 1) * 64;
    const int lrow = lane & 15;
    const int lcol = (lane >> 4) * 16;

    const int nch = K >> 5;

    float acc[4][8][4] = {};

    prefetch_chunk2(Ahi, Alo, BT, brow, bcol, K, 0, sb, tid);
    CP_COMMIT();
    prefetch_chunk2(Ahi, Alo, BT, brow, bcol, K, 32, sb + GS_STAGE, tid);
    CP_COMMIT();
    CP_WAIT1();
    __syncthreads();

    int s_cur = 0;
    for (int c = 0; c < nch; c++) {
        if (c + 2 < nch) {
            int s2 = s_cur + 2; if (s2 >= 3) s2 -= 3;
            prefetch_chunk2(Ahi, Alo, BT, brow, bcol, K, (c + 2) << 5,
                            sb + s2 * GS_STAGE, tid);
            CP_COMMIT();
        }

        unsigned base = sb + s_cur * GS_STAGE;
        #pragma unroll
        for (int ks = 0; ks < 2; ks++) {
            int kb = ks * 32;
            unsigned bF[4][4];
            #pragma unroll
            for (int j2 = 0; j2 < 4; j2++) {
                unsigned off = (unsigned)((wn + j2 * 16 + lrow) * 64 + kb + lcol);
                LDMX4(bF[j2][0], bF[j2][1], bF[j2][2], bF[j2][3], base + 16384 + SWZ64(off));
            }
            #pragma unroll
            for (int i = 0; i < 4; i++) {
                unsigned off = (unsigned)((wm + i * 16 + lrow) * 64 + kb + lcol);
                unsigned aH[4], aL[4];
                LDMX4(aH[0], aH[1], aH[2], aH[3], base + SWZ64(off));
                LDMX4(aL[0], aL[1], aL[2], aL[3], base + 8192 + SWZ64(off));
                #pragma unroll
                for (int j = 0; j < 8; j++) {
                    unsigned b0 = (j & 1) ? bF[j >> 1][1] : bF[j >> 1][0];
                    unsigned b1 = (j & 1) ? bF[j >> 1][3] : bF[j >> 1][2];
                    MMAF16(acc[i][j], aH, b0, b1);
                    MMAF16(acc[i][j], aL, b0, b1);
                }
            }
        }

        if (c + 1 < nch) {
            if (c + 2 < nch) { CP_WAIT1(); } else { CP_WAIT0(); }
        }
        __syncthreads();
        if (++s_cur == 3) s_cur = 0;
    }

    const int r0 = brow + wm + (lane >> 2);
    const int c0 = bcol + wn + (lane & 3) * 2;
    #pragma unroll
    for (int i = 0; i < 4; i++) {
        #pragma unroll
        for (int j = 0; j < 8; j++) {
            int col = c0 + j * 8;
            float bx = bias[col], by = bias[col + 1];
            float v00 = acc[i][j][0] + bx, v01 = acc[i][j][1] + by;
            float v10 = acc[i][j][2] + bx, v11 = acc[i][j][3] + by;
            size_t o0 = (size_t)(r0 + i * 16) * N + col;
            size_t o1 = (size_t)(r0 + i * 16 + 8) * N + col;
            unsigned l0, l1;
            unsigned h0 = packh2(v00, v01, l0);
            unsigned h1 = packh2(v10, v11, l1);
            *(unsigned*)&Chi[o0] = h0;
            *(unsigned*)&Clo[o0] = l0;
            *(unsigned*)&Chi[o1] = h1;
            *(unsigned*)&Clo[o1] = l1;
        }
    }
}

// ---------------------------------------------------------------------------
// 1-pass fp16 GEMM (O-proj): C = A@BT^T + bias, fp32 out.
// stage: A 8KB @0, B 8KB @8192 = 16KB; 3 stages = 48KB.
// ---------------------------------------------------------------------------
#define G1_STAGE 16384
#define G1_TOTAL 49152

__device__ __forceinline__ void prefetch_chunk1(
    const __half* __restrict__ A, const __half* __restrict__ BT,
    int brow, int bcol, int K, int kt, unsigned stage, int tid)
{
    gload64h(A, brow, K, kt, stage, tid);
    gload64h(BT, bcol, K, kt, stage + 8192, tid);
}

__global__ __launch_bounds__(128, 2) void gemm1x_mma(
    const __half* __restrict__ A, const __half* __restrict__ BT,
    const float* __restrict__ bias, float* __restrict__ C,
    int M, int N, int K)
{
    extern __shared__ char smem[];
    unsigned sb = smem_u32(smem);
    const int tid = threadIdx.x, w = tid >> 5, lane = tid & 31;
    const int brow = blockIdx.y * 128, bcol = blockIdx.x * 128;
    const int wm = (w >> 1) * 64;
    const int wn = (w & 1) * 64;
    const int lrow = lane & 15;
    const int lcol = (lane >> 4) * 16;

    const int nch = K >> 5;

    float acc[4][8][4] = {};

    prefetch_chunk1(A, BT, brow, bcol, K, 0, sb, tid);
    CP_COMMIT();
    prefetch_chunk1(A, BT, brow, bcol, K, 32, sb + G1_STAGE, tid);
    CP_COMMIT();
    CP_WAIT1();
    __syncthreads();

    int s_cur = 0;
    for (int c = 0; c < nch; c++) {
        if (c + 2 < nch) {
            int s2 = s_cur + 2; if (s2 >= 3) s2 -= 3;
            prefetch_chunk1(A, BT, brow, bcol, K, (c + 2) << 5,
                            sb + s2 * G1_STAGE, tid);
            CP_COMMIT();
        }

        unsigned base = sb + s_cur * G1_STAGE;
        #pragma unroll
        for (int ks = 0; ks < 2; ks++) {
            int kb = ks * 32;
            unsigned bF[4][4];
            #pragma unroll
            for (int j2 = 0; j2 < 4; j2++) {
                unsigned off = (unsigned)((wn + j2 * 16 + lrow) * 64 + kb + lcol);
                LDMX4(bF[j2][0], bF[j2][1], bF[j2][2], bF[j2][3], base + 8192 + SWZ64(off));
            }
            #pragma unroll
            for (int i = 0; i < 4; i++) {
                unsigned off = (unsigned)((wm + i * 16 + lrow) * 64 + kb + lcol);
                unsigned aF[4];
                LDMX4(aF[0], aF[1], aF[2], aF[3], base + SWZ64(off));
                #pragma unroll
                for (int j = 0; j < 8; j++) {
                    unsigned b0 = (j & 1) ? bF[j >> 1][1] : bF[j >> 1][0];
                    unsigned b1 = (j & 1) ? bF[j >> 1][3] : bF[j >> 1][2];
                    MMAF16(acc[i][j], aF, b0, b1);
                }
            }
        }

        if (c + 1 < nch) {
            if (c + 2 < nch) { CP_WAIT1(); } else { CP_WAIT0(); }
        }
        __syncthreads();
        if (++s_cur == 3) s_cur = 0;
    }

    const int r0 = brow + wm + (lane >> 2);
    const int c0 = bcol + wn + (lane & 3) * 2;
    #pragma unroll
    for (int i = 0; i < 4; i++) {
        #pragma unroll
        for (int j = 0; j < 8; j++) {
            int col = c0 + j * 8;
            float bx = bias[col], by = bias[col + 1];
            size_t o0 = (size_t)(r0 + i * 16) * N + col;
            size_t o1 = (size_t)(r0 + i * 16 + 8) * N + col;
            *(float2*)&C[o0] = make_float2(acc[i][j][0] + bx, acc[i][j][1] + by);
            *(float2*)&C[o1] = make_float2(acc[i][j][2] + bx, acc[i][j][3] + by);
        }
    }
}

// ---------------------------------------------------------------------------
// Kernel A: QK^T (2-pass) + register-resident softmax. QT=16, 128 threads.
// smem: K 3x16384 @0, LF fp32 @49152 (16 x 4128B) = 115200 -> 2 CTA/SM.
// ---------------------------------------------------------------------------
#define LA_K0 0
#define LA_LF 49152
#define LA_TOTAL 115200
#define PSTRB 4128

__device__ __forceinline__ void la_load_k(
    const __half* __restrict__ qh, int b, int h, int kb, unsigned dst, int tid)
{
    #pragma unroll
    for (int i = 0; i < 8; i++) {
        int idx = tid + i * 128;
        int row = idx >> 3, c16 = (idx & 7) * 16;
        unsigned so = SWZ128((unsigned)(row * 128 + c16));
        CP_ASYNC16(dst + so, (const char*)(qh + (size_t)(b * SS + kb + row) * 3072 + h * 192 + 64) + c16);
    }
}

__global__ __launch_bounds__(128, 2) void attn_logits(
    const __half* __restrict__ qh, const __half* __restrict__ ql,
    float* __restrict__ attn_out, __half* __restrict__ pOut)
{
    extern __shared__ char smem[];
    unsigned sb = smem_u32(smem);

    const int qt = blockIdx.x, h = blockIdx.y, b = blockIdx.z;
    const int bh = b * HH + h;
    const int q0 = qt * 16;
    const int tid = threadIdx.x, w = tid >> 5, lane = tid & 31;
    const int lrow = lane & 15, lcol = (lane >> 4) * 16;
    const int wn = w * 32;

    // ---- prologue: Q (into LF temp) + K chunks 0,1
    {
        int row = tid >> 3, c16 = (tid & 7) * 16;
        unsigned so = SWZ128((unsigned)(row * 128 + c16));
        CP_ASYNC16(sb + LA_LF + so, (const char*)(qh + (size_t)(b * SS + q0 + row) * 3072 + h * 192) + c16);
        CP_ASYNC16(sb + LA_LF + 2048 + so, (const char*)(ql + (size_t)(b * SS + q0 + row) * 3072 + h * 192) + c16);
    }
    la_load_k(qh, b, h, 0, sb + LA_K0, tid);
    CP_COMMIT();
    la_load_k(qh, b, h, 128, sb + LA_K0 + 16384, tid);
    CP_COMMIT();
    CP_WAIT1();
    __syncthreads();

    // ---- Q fragments -> registers
    unsigned qHf[4][4], qLf[4][4];
    #pragma unroll
    for (int ks = 0; ks < 4; ks++) {
        unsigned aoff = SWZ128((unsigned)(lrow * 128 + ks * 32 + lcol));
        LDMX4(qHf[ks][0], qHf[ks][1], qHf[ks][2], qHf[ks][3], sb + LA_LF + aoff);
        LDMX4(qLf[ks][0], qLf[ks][1], qLf[ks][2], qLf[ks][3], sb + LA_LF + 2048 + aoff);
    }
    __syncthreads();

    // ---- phase 1: 8 chunks of 128 keys, triple-buffered
    for (int c = 0; c < 8; c++) {
        if (c + 2 < 8) {
            int s2 = (c + 2) % 3;
            la_load_k(qh, b, h, (c + 2) * 128, sb + LA_K0 + s2 * 16384, tid);
            CP_COMMIT();
        }
        unsigned base = sb + LA_K0 + (c % 3) * 16384;
        float acc[4][4] = {};
        #pragma unroll
        for (int ks = 0; ks < 4; ks++) {
            int kb = ks * 32;
            unsigned bF[2][4];
            #pragma unroll
            for (int j2 = 0; j2 < 2; j2++) {
                unsigned boff = SWZ128((unsigned)((wn + j2 * 16 + lrow) * 128 + kb + lcol));
                LDMX4(bF[j2][0], bF[j2][1], bF[j2][2], bF[j2][3], base + boff);
            }
            #pragma unroll
            for (int j = 0; j < 4; j++) {
                unsigned b0 = (j & 1) ? bF[j >> 1][1] : bF[j >> 1][0];
                unsigned b1 = (j & 1) ? bF[j >> 1][3] : bF[j >> 1][2];
                MMAF16(acc[j], qHf[ks], b0, b1);
                MMAF16(acc[j], qLf[ks], b0, b1);
            }
        }
        int r0 = lane >> 2;
        int cb = c * 128 + wn + (lane & 3) * 2;
        #pragma unroll
        for (int j = 0; j < 4; j++) {
            int col = cb + j * 8;
            *(float2*)(smem + LA_LF + r0 * PSTRB + col * 4) =
                make_float2(acc[j][0] * 0.125f, acc[j][1] * 0.125f);
            *(float2*)(smem + LA_LF + (r0 + 8) * PSTRB + col * 4) =
                make_float2(acc[j][2] * 0.125f, acc[j][3] * 0.125f);
        }
        if (c + 1 < 8) {
            if (c + 2 < 8) { CP_WAIT1(); } else { CP_WAIT0(); }
        }
        __syncthreads();
    }

    // ---- register-resident softmax (one row at a time per warp)
    for (int r = w; r < 16; r += 4) {
        const char* rowp = smem + LA_LF + r * PSTRB;
        float e[32];
        float m = -1e30f;
        #pragma unroll
        for (int it = 0; it < 16; it++) {
            float2 v = *(const float2*)(rowp + it * 256 + lane * 8);
            e[it * 2] = v.x;
            e[it * 2 + 1] = v.y;
            m = fmaxf(m, fmaxf(v.x, v.y));
        }
        #pragma unroll
        for (int o = 16; o > 0; o >>= 1) m = fmaxf(m, __shfl_xor_sync(0xFFFFFFFFu, m, o));
        float sum = 0.f;
        #pragma unroll
        for (int i = 0; i < 32; i++) {
            e[i] = __expf(e[i] - m);
            sum += e[i];
        }
        #pragma unroll
        for (int o = 16; o > 0; o >>= 1) sum += __shfl_xor_sync(0xFFFFFFFFu, sum, o);
        float inv = 1.0f / sum;
        size_t base = ((size_t)(bh * SS) + q0 + r) * SS;
        #pragma unroll
        for (int it = 0; it < 16; it++) {
            float v0 = e[it * 2] * inv, v1 = e[it * 2 + 1] * inv;
            *(float2*)&attn_out[base + it * 64 + lane * 2] = make_float2(v0, v1);
            *(unsigned*)&pOut[base + it * 64 + lane * 2] = packs2(v0, v1);
        }
    }
}

// ---------------------------------------------------------------------------
// Kernel B: values = P(fp16) @ V^T (fp16 single). Writes single fp16 values.
// ---------------------------------------------------------------------------
#define AV_STAGE 24576
#define AV_TOTAL 73728

__device__ __forceinline__ void av_load(
    const __half* __restrict__ P, const __half* __restrict__ vTh,
    int bh, int brow, int kt, unsigned stage, int tid)
{
    #pragma unroll
    for (int i = 0; i < 8; i++) {
        int idx = tid + i * 128;
        int row = idx >> 3, c16 = (idx & 7) * 16;
        unsigned so = SWZ128((unsigned)(row * 128 + c16));
        CP_ASYNC16(stage + so, (const char*)(P + ((size_t)(bh * SS + brow + row)) * SS + kt) + c16);
    }
    #pragma unroll
    for (int i = 0; i < 4; i++) {
        int idx = tid + i * 128;
        int row = idx >> 3, c16 = (idx & 7) * 16;
        unsigned so = SWZ128((unsigned)(row * 128 + c16));
        CP_ASYNC16(stage + 16384 + so, (const char*)(vTh + (size_t)(bh * HDIM + row) * SS + kt) + c16);
    }
}

__global__ __launch_bounds__(128, 2) void av_gemm(
    const __half* __restrict__ P, const __half* __restrict__ vTh,
    __half* __restrict__ Vh)
{
    extern __shared__ char smem[];
    unsigned sb = smem_u32(smem);
    const int tid = threadIdx.x, w = tid >> 5, lane = tid & 31;
    const int brow = blockIdx.x * 128;
    const int bh = blockIdx.y;
    const int b = bh >> 4, h = bh & 15;
    const int wm = (w >> 1) * 64;
    const int wn = (w & 1) * 32;
    const int lrow = lane & 15;
    const int lcol = (lane >> 4) * 16;

    const int nch = 16;

    float acc[4][4][4] = {};

    av_load(P, vTh, bh, brow, 0, sb, tid);
    CP_COMMIT();
    av_load(P, vTh, bh, brow, 64, sb + AV_STAGE, tid);
    CP_COMMIT();
    CP_WAIT1();
    __syncthreads();

    int s_cur = 0;
    for (int c = 0; c < nch; c++) {
        if (c + 2 < nch) {
            int s2 = s_cur + 2; if (s2 >= 3) s2 -= 3;
            av_load(P, vTh, bh, brow, (c + 2) * 64, sb + s2 * AV_STAGE, tid);
            CP_COMMIT();
        }

        unsigned base = sb + s_cur * AV_STAGE;
        #pragma unroll
        for (int ks = 0; ks < 4; ks++) {
            int kb = ks * 32;
            unsigned vh[2][4];
            #pragma unroll
            for (int j2 = 0; j2 < 2; j2++) {
                unsigned off = SWZ128((unsigned)((wn + j2 * 16 + lrow) * 128 + kb + lcol));
                LDMX4(vh[j2][0], vh[j2][1], vh[j2][2], vh[j2][3], base + 16384 + off);
            }
            #pragma unroll
            for (int i = 0; i < 4; i++) {
                unsigned off = SWZ128((unsigned)((wm + i * 16 + lrow) * 128 + kb + lcol));
                unsigned aF[4];
                LDMX4(aF[0], aF[1], aF[2], aF[3], base + off);
                #pragma unroll
                for (int j = 0; j < 4; j++) {
                    unsigned h0 = (j & 1) ? vh[j >> 1][1] : vh[j >> 1][0];
                    unsigned h1 = (j & 1) ? vh[j >> 1][3] : vh[j >> 1][2];
                    MMAF16(acc[i][j], aF, h0, h1);
                }
            }
        }

        if (c + 1 < nch) {
            if (c + 2 < nch) { CP_WAIT1(); } else { CP_WAIT0(); }
        }
        __syncthreads();
        if (++s_cur == 3) s_cur = 0;
    }

    const int r0 = brow + wm + (lane >> 2);
    const int c0 = wn + (lane & 3) * 2;
    #pragma unroll
    for (int i = 0; i < 4; i++) {
        #pragma unroll
        for (int j = 0; j < 4; j++) {
            int col = h * 64 + c0 + j * 8;
            size_t o0 = (size_t)(b * SS + r0 + i * 16) * DD + col;
            size_t o1 = (size_t)(b * SS + r0 + i * 16 + 8) * DD + col;
            *(unsigned*)&Vh[o0] = packs2(acc[i][j][0], acc[i][j][1]);
            *(unsigned*)&Vh[o1] = packs2(acc[i][j][2], acc[i][j][3]);
        }
    }
}

// ---------------------------------------------------------------------------
extern "C" void kernel_launch(void* const* d_in, const int* in_sizes, int n_in,
                              void* d_out, int out_size)
{
    const float* x     = (const float*)d_in[0];
    const float* W_qkv = (const float*)d_in[1];
    const float* b_qkv = (const float*)d_in[2];
    const float* W_o   = (const float*)d_in[3];
    const float* b_o   = (const float*)d_in[4];

    float* out_o    = (float*)d_out;
    float* out_attn = (float*)d_out + (size_t)BB * SS * DD;

    __half *xhi, *xlo, *wqT, *woT, *vh, *qhp, *qlp, *vthp, *pp;
    cudaGetSymbolAddress((void**)&xhi, g_xhi);
    cudaGetSymbolAddress((void**)&xlo, g_xlo);
    cudaGetSymbolAddress((void**)&wqT, g_wqT);
    cudaGetSymbolAddress((void**)&woT, g_woT);
    cudaGetSymbolAddress((void**)&vh, g_vh);
    cudaGetSymbolAddress((void**)&qhp, g_qh);
    cudaGetSymbolAddress((void**)&qlp, g_ql);
    cudaGetSymbolAddress((void**)&vthp, g_vTh);
    cudaGetSymbolAddress((void**)&pp, g_p);

    cudaFuncSetAttribute(gemm2x_mma, cudaFuncAttributeMaxDynamicSharedMemorySize, GS_TOTAL);
    cudaFuncSetAttribute(gemm1x_mma, cudaFuncAttributeMaxDynamicSharedMemorySize, G1_TOTAL);
    cudaFuncSetAttribute(attn_logits, cudaFuncAttributeMaxDynamicSharedMemorySize, LA_TOTAL);
    cudaFuncSetAttribute(av_gemm, cudaFuncAttributeMaxDynamicSharedMemorySize, AV_TOTAL);

    // 0) prep
    {
        int n4 = BB * SS * DD / 4;
        split_kernel<<<(n4 + 255) / 256, 256>>>(x, xhi, xlo, n4);
        dim3 g1(3 * DD / 32, DD / 32);
        tsingle_kernel<<<g1, dim3(32, 8)>>>(W_qkv, wqT, DD, 3 * DD);
        dim3 g2(DD / 32, DD / 32);
        tsingle_kernel<<<g2, dim3(32, 8)>>>(W_o, woT, DD, DD);
    }

    // 1) QKV projection (2-pass fp16) -> qkv fp16 hi/lo
    {
        dim3 grid(3 * DD / 128, BB * SS / 128);
        gemm2x_mma<<<grid, 128, GS_TOTAL>>>(xhi, xlo, wqT, b_qkv,
                                            qhp, qlp, BB * SS, 3 * DD, DD);
    }

    // 2) V^T (pure fp16 transpose of qh V-slice)
    {
        dim3 gv(SS / 32, HDIM / 32, BB * HH);
        vT_kernel<<<gv, dim3(32, 8)>>>(qhp, vthp);
    }

    // 3a) QK^T + register-resident softmax -> attention + P fp16
    {
        dim3 grid(SS / 16, HH, BB);
        attn_logits<<<grid, 128, LA_TOTAL>>>(qhp, qlp, out_attn, pp);
    }

    // 3b) AV gemm (single-pass) -> values fp16 single
    {
        dim3 grid(SS / 128, BB * HH);
        av_gemm<<<grid, 128, AV_TOTAL>>>(pp, vthp, vh);
    }

    // 4) O-proj (single-pass fp16)
    {
        dim3 grid(DD / 128, BB * SS / 128);
        gemm1x_mma<<<grid, 128, G1_TOTAL>>>(vh, woT, b_o, out_o,
                                            BB * SS, DD, DD);
    }
}

// round 14
// speedup vs baseline: 1.9778x; 1.1358x over previous
#include <cuda_runtime.h>
#include <cuda_bf16.h>
#include <cuda_fp16.h>

#define BB 4
#define SS 1024
#define HH 16
#define HDIM 64
#define DD 1024

// ---------------------------------------------------------------------------
// scratch (device globals — no allocation allowed)
// ---------------------------------------------------------------------------
__device__ __half g_xhi[BB * SS * DD];
__device__ __half g_xlo[BB * SS * DD];
__device__ __half g_wqT[3 * DD * DD];           // W_qkv^T fp16, PERMUTED rows: Q|K|V blocks
__device__ float  g_bq[3 * DD];                 // permuted bias
__device__ __half g_woT[DD * DD];               // W_o^T fp16
__device__ __half g_vh[BB * SS * DD];           // values fp16 (av epilogue)
__device__ __half g_qh[BB * SS * 3 * DD];       // qkv hi, permuted cols [Q|K|V]
__device__ __half g_ql[BB * SS * 3 * DD];       // qkv lo (only Q cols written/used)
__device__ __half g_vTh[BB * HH * HDIM * SS];   // V^T fp16 per (b,h): [64][S]
__device__ __half g_p[(size_t)BB * HH * SS * SS]; // normalized attention fp16

// ---------------------------------------------------------------------------
__device__ __forceinline__ unsigned smem_u32(const void* p) {
    unsigned a;
    asm("{ .reg .u64 t; cvta.to.shared.u64 t, %1; cvt.u32.u64 %0, t; }" : "=r"(a) : "l"(p));
    return a;
}
#define SWZ128(o) ((o) ^ (((o) >> 3) & 0x70))
#define SWZ64(o)  ((o) ^ (((o) >> 3) & 0x30))

#define CP_ASYNC16(saddr, gptr) \
    asm volatile("cp.async.cg.shared.global [%0], [%1], 16;" :: "r"(saddr), "l"(gptr) : "memory")
#define CP_COMMIT() asm volatile("cp.async.commit_group;" ::: "memory")
#define CP_WAIT1()  asm volatile("cp.async.wait_group 1;" ::: "memory")
#define CP_WAIT0()  asm volatile("cp.async.wait_group 0;" ::: "memory")

#define LDMX4(r0, r1, r2, r3, a) \
    asm volatile("ldmatrix.sync.aligned.m8n8.x4.shared.b16 {%0,%1,%2,%3}, [%4];" \
        : "=r"(r0), "=r"(r1), "=r"(r2), "=r"(r3) : "r"(a))

#define MMAF16(d, a, b0, b1) \
    asm volatile("mma.sync.aligned.m16n8k16.row.col.f32.f16.f16.f32 " \
        "{%0,%1,%2,%3}, {%4,%5,%6,%7}, {%8,%9}, {%0,%1,%2,%3};" \
        : "+f"((d)[0]), "+f"((d)[1]), "+f"((d)[2]), "+f"((d)[3]) \
        : "r"((a)[0]), "r"((a)[1]), "r"((a)[2]), "r"((a)[3]), "r"(b0), "r"(b1))

__device__ __forceinline__ unsigned packh2(float x, float y, unsigned& lo) {
    __half hx = __float2half(x);
    __half hy = __float2half(y);
    __half lx = __float2half(x - __half2float(hx));
    __half ly = __float2half(y - __half2float(hy));
    lo = ((unsigned)__half_as_ushort(ly) << 16) | __half_as_ushort(lx);
    return ((unsigned)__half_as_ushort(hy) << 16) | __half_as_ushort(hx);
}
__device__ __forceinline__ unsigned packs2(float x, float y) {
    return ((unsigned)__half_as_ushort(__float2half(y)) << 16) |
           __half_as_ushort(__float2half(x));
}
// column permutation: interleaved head layout -> [Q(1024)|K(1024)|V(1024)]
__device__ __forceinline__ int qkv_perm(int n) {
    int head = n / 192, wi = n % 192;
    return (wi / 64) * 1024 + head * 64 + (wi % 64);
}

// ---------------------------------------------------------------------------
__global__ __launch_bounds__(256) void split_kernel(
    const float* __restrict__ src, __half* __restrict__ hi,
    __half* __restrict__ lo, int n4)
{
    int i = blockIdx.x * 256 + threadIdx.x;
    if (i >= n4) return;
    float4 v = ((const float4*)src)[i];
    unsigned l0, l1, h0, h1;
    h0 = packh2(v.x, v.y, l0);
    h1 = packh2(v.z, v.w, l1);
    ((uint2*)hi)[i] = make_uint2(h0, h1);
    ((uint2*)lo)[i] = make_uint2(l0, l1);
}

__global__ __launch_bounds__(256) void tsingle_kernel(
    const float* __restrict__ W, __half* __restrict__ WT, int K, int N, int permute)
{
    __shared__ float t[32][33];
    int k0 = blockIdx.y * 32, n0 = blockIdx.x * 32;
    int tx = threadIdx.x, ty = threadIdx.y;
    #pragma unroll
    for (int i = 0; i < 32; i += 8)
        t[ty + i][tx] = W[(size_t)(k0 + ty + i) * N + n0 + tx];
    __syncthreads();
    #pragma unroll
    for (int i = 0; i < 32; i += 8) {
        int n = n0 + ty + i;
        int np = permute ? qkv_perm(n) : n;
        WT[(size_t)np * K + k0 + tx] = __float2half(t[tx][ty + i]);
    }
}

__global__ __launch_bounds__(256) void bperm_kernel(
    const float* __restrict__ b, float* __restrict__ bp)
{
    int n = blockIdx.x * 256 + threadIdx.x;
    if (n >= 3 * DD) return;
    bp[qkv_perm(n)] = b[n];
}

// V^T: fp16 transpose of qh V-block -> vTh [bh][64][S]
__global__ __launch_bounds__(256) void vT_kernel(
    const __half* __restrict__ qh, __half* __restrict__ vTh)
{
    __shared__ __half t[32][33];
    int s0 = blockIdx.x * 32, d0 = blockIdx.y * 32, bh = blockIdx.z;
    int b = bh >> 4, h = bh & 15;
    int tx = threadIdx.x, ty = threadIdx.y;
    #pragma unroll
    for (int i = 0; i < 32; i += 8)
        t[ty + i][tx] = qh[(size_t)(b * SS + s0 + ty + i) * 3072 + 2048 + h * 64 + d0 + tx];
    __syncthreads();
    #pragma unroll
    for (int i = 0; i < 32; i += 8)
        vTh[(size_t)(bh * HDIM + d0 + ty + i) * SS + s0 + tx] = t[tx][ty + i];
}

// ---------------------------------------------------------------------------
// shared loader
__device__ __forceinline__ void gload64h(const __half* __restrict__ src,
                                         int rbase, int K, int kt, unsigned dst, int tid)
{
    #pragma unroll
    for (int i = 0; i < 4; i++) {
        int idx = tid + i * 128;
        int row = idx >> 2;
        int c16 = (idx & 3) * 16;
        CP_ASYNC16(dst + SWZ64((unsigned)(row * 64 + c16)),
                   (const char*)(src + (size_t)(rbase + row) * K + kt) + c16);
    }
}

// ---------------------------------------------------------------------------
// 2-pass fp16 GEMM (Q-part): Chi/Clo = split(Ah@BT^T + Al@BT^T + bias)
// Nstr = C row stride (elements). Columns covered by grid.x*128.
// ---------------------------------------------------------------------------
#define GS_STAGE 24576
#define GS_TOTAL 73728

__device__ __forceinline__ void prefetch_chunk2(
    const __half* __restrict__ Ahi, const __half* __restrict__ Alo,
    const __half* __restrict__ BT,
    int brow, int bcol, int K, int kt, unsigned stage, int tid)
{
    gload64h(Ahi, brow, K, kt, stage, tid);
    gload64h(Alo, brow, K, kt, stage + 8192, tid);
    gload64h(BT, bcol, K, kt, stage + 16384, tid);
}

__global__ __launch_bounds__(128, 2) void gemm2x_mma(
    const __half* __restrict__ Ahi, const __half* __restrict__ Alo,
    const __half* __restrict__ BT,
    const float* __restrict__ bias,
    __half* __restrict__ Chi, __half* __restrict__ Clo,
    int M, int Nstr, int K)
{
    extern __shared__ char smem[];
    unsigned sb = smem_u32(smem);
    const int tid = threadIdx.x, w = tid >> 5, lane = tid & 31;
    const int brow = blockIdx.y * 128, bcol = blockIdx.x * 128;
    const int wm = (w >> 1) * 64;
    const int wn = (w & 1) * 64;
    const int lrow = lane & 15;
    const int lcol = (lane >> 4) * 16;

    const int nch = K >> 5;

    float acc[4][8][4] = {};

    prefetch_chunk2(Ahi, Alo, BT, brow, bcol, K, 0, sb, tid);
    CP_COMMIT();
    prefetch_chunk2(Ahi, Alo, BT, brow, bcol, K, 32, sb + GS_STAGE, tid);
    CP_COMMIT();
    CP_WAIT1();
    __syncthreads();

    int s_cur = 0;
    for (int c = 0; c < nch; c++) {
        if (c + 2 < nch) {
            int s2 = s_cur + 2; if (s2 >= 3) s2 -= 3;
            prefetch_chunk2(Ahi, Alo, BT, brow, bcol, K, (c + 2) << 5,
                            sb + s2 * GS_STAGE, tid);
            CP_COMMIT();
        }

        unsigned base = sb + s_cur * GS_STAGE;
        #pragma unroll
        for (int ks = 0; ks < 2; ks++) {
            int kb = ks * 32;
            unsigned bF[4][4];
            #pragma unroll
            for (int j2 = 0; j2 < 4; j2++) {
                unsigned off = (unsigned)((wn + j2 * 16 + lrow) * 64 + kb + lcol);
                LDMX4(bF[j2][0], bF[j2][1], bF[j2][2], bF[j2][3], base + 16384 + SWZ64(off));
            }
            #pragma unroll
            for (int i = 0; i < 4; i++) {
                unsigned off = (unsigned)((wm + i * 16 + lrow) * 64 + kb + lcol);
                unsigned aH[4], aL[4];
                LDMX4(aH[0], aH[1], aH[2], aH[3], base + SWZ64(off));
                LDMX4(aL[0], aL[1], aL[2], aL[3], base + 8192 + SWZ64(off));
                #pragma unroll
                for (int j = 0; j < 8; j++) {
                    unsigned b0 = (j & 1) ? bF[j >> 1][1] : bF[j >> 1][0];
                    unsigned b1 = (j & 1) ? bF[j >> 1][3] : bF[j >> 1][2];
                    MMAF16(acc[i][j], aH, b0, b1);
                    MMAF16(acc[i][j], aL, b0, b1);
                }
            }
        }

        if (c + 1 < nch) {
            if (c + 2 < nch) { CP_WAIT1(); } else { CP_WAIT0(); }
        }
        __syncthreads();
        if (++s_cur == 3) s_cur = 0;
    }

    const int r0 = brow + wm + (lane >> 2);
    const int c0 = bcol + wn + (lane & 3) * 2;
    #pragma unroll
    for (int i = 0; i < 4; i++) {
        #pragma unroll
        for (int j = 0; j < 8; j++) {
            int col = c0 + j * 8;
            float bx = bias[col], by = bias[col + 1];
            float v00 = acc[i][j][0] + bx, v01 = acc[i][j][1] + by;
            float v10 = acc[i][j][2] + bx, v11 = acc[i][j][3] + by;
            size_t o0 = (size_t)(r0 + i * 16) * Nstr + col;
            size_t o1 = (size_t)(r0 + i * 16 + 8) * Nstr + col;
            unsigned l0, l1;
            unsigned h0 = packh2(v00, v01, l0);
            unsigned h1 = packh2(v10, v11, l1);
            *(unsigned*)&Chi[o0] = h0;
            *(unsigned*)&Clo[o0] = l0;
            *(unsigned*)&Chi[o1] = h1;
            *(unsigned*)&Clo[o1] = l1;
        }
    }
}

// ---------------------------------------------------------------------------
// 1-pass fp16 GEMM: C fp32 (if C) else Ch fp16. Nstr = C row stride.
// ---------------------------------------------------------------------------
#define G1_STAGE 16384
#define G1_TOTAL 49152

__device__ __forceinline__ void prefetch_chunk1(
    const __half* __restrict__ A, const __half* __restrict__ BT,
    int brow, int bcol, int K, int kt, unsigned stage, int tid)
{
    gload64h(A, brow, K, kt, stage, tid);
    gload64h(BT, bcol, K, kt, stage + 8192, tid);
}

__global__ __launch_bounds__(128, 2) void gemm1x_mma(
    const __half* __restrict__ A, const __half* __restrict__ BT,
    const float* __restrict__ bias, float* __restrict__ C,
    __half* __restrict__ Ch,
    int M, int Nstr, int K)
{
    extern __shared__ char smem[];
    unsigned sb = smem_u32(smem);
    const int tid = threadIdx.x, w = tid >> 5, lane = tid & 31;
    const int brow = blockIdx.y * 128, bcol = blockIdx.x * 128;
    const int wm = (w >> 1) * 64;
    const int wn = (w & 1) * 64;
    const int lrow = lane & 15;
    const int lcol = (lane >> 4) * 16;

    const int nch = K >> 5;

    float acc[4][8][4] = {};

    prefetch_chunk1(A, BT, brow, bcol, K, 0, sb, tid);
    CP_COMMIT();
    prefetch_chunk1(A, BT, brow, bcol, K, 32, sb + G1_STAGE, tid);
    CP_COMMIT();
    CP_WAIT1();
    __syncthreads();

    int s_cur = 0;
    for (int c = 0; c < nch; c++) {
        if (c + 2 < nch) {
            int s2 = s_cur + 2; if (s2 >= 3) s2 -= 3;
            prefetch_chunk1(A, BT, brow, bcol, K, (c + 2) << 5,
                            sb + s2 * G1_STAGE, tid);
            CP_COMMIT();
        }

        unsigned base = sb + s_cur * G1_STAGE;
        #pragma unroll
        for (int ks = 0; ks < 2; ks++) {
            int kb = ks * 32;
            unsigned bF[4][4];
            #pragma unroll
            for (int j2 = 0; j2 < 4; j2++) {
                unsigned off = (unsigned)((wn + j2 * 16 + lrow) * 64 + kb + lcol);
                LDMX4(bF[j2][0], bF[j2][1], bF[j2][2], bF[j2][3], base + 8192 + SWZ64(off));
            }
            #pragma unroll
            for (int i = 0; i < 4; i++) {
                unsigned off = (unsigned)((wm + i * 16 + lrow) * 64 + kb + lcol);
                unsigned aF[4];
                LDMX4(aF[0], aF[1], aF[2], aF[3], base + SWZ64(off));
                #pragma unroll
                for (int j = 0; j < 8; j++) {
                    unsigned b0 = (j & 1) ? bF[j >> 1][1] : bF[j >> 1][0];
                    unsigned b1 = (j & 1) ? bF[j >> 1][3] : bF[j >> 1][2];
                    MMAF16(acc[i][j], aF, b0, b1);
                }
            }
        }

        if (c + 1 < nch) {
            if (c + 2 < nch) { CP_WAIT1(); } else { CP_WAIT0(); }
        }
        __syncthreads();
        if (++s_cur == 3) s_cur = 0;
    }

    const int r0 = brow + wm + (lane >> 2);
    const int c0 = bcol + wn + (lane & 3) * 2;
    #pragma unroll
    for (int i = 0; i < 4; i++) {
        #pragma unroll
        for (int j = 0; j < 8; j++) {
            int col = c0 + j * 8;
            float bx = bias[col], by = bias[col + 1];
            float v00 = acc[i][j][0] + bx, v01 = acc[i][j][1] + by;
            float v10 = acc[i][j][2] + bx, v11 = acc[i][j][3] + by;
            size_t o0 = (size_t)(r0 + i * 16) * Nstr + col;
            size_t o1 = (size_t)(r0 + i * 16 + 8) * Nstr + col;
            if (C) {
                *(float2*)&C[o0] = make_float2(v00, v01);
                *(float2*)&C[o1] = make_float2(v10, v11);
            } else {
                *(unsigned*)&Ch[o0] = packs2(v00, v01);
                *(unsigned*)&Ch[o1] = packs2(v10, v11);
            }
        }
    }
}

// ---------------------------------------------------------------------------
// Kernel A: QK^T (2-pass Q x K-hi) + register softmax. QT=16, 128 threads.
// Permuted layout: Q cols at h*64, K cols at 1024 + h*64.
// smem: K 3x16384 @0, LF fp32 @49152 (16 x 4128B) = 115200 -> 2 CTA/SM.
// ---------------------------------------------------------------------------
#define LA_K0 0
#define LA_LF 49152
#define LA_TOTAL 115200
#define PSTRB 4128

__device__ __forceinline__ void la_load_k(
    const __half* __restrict__ qh, int b, int h, int kb, unsigned dst, int tid)
{
    #pragma unroll
    for (int i = 0; i < 8; i++) {
        int idx = tid + i * 128;
        int row = idx >> 3, c16 = (idx & 7) * 16;
        unsigned so = SWZ128((unsigned)(row * 128 + c16));
        CP_ASYNC16(dst + so, (const char*)(qh + (size_t)(b * SS + kb + row) * 3072 + 1024 + h * 64) + c16);
    }
}

__global__ __launch_bounds__(128, 2) void attn_logits(
    const __half* __restrict__ qh, const __half* __restrict__ ql,
    float* __restrict__ attn_out, __half* __restrict__ pOut)
{
    extern __shared__ char smem[];
    unsigned sb = smem_u32(smem);

    const int qt = blockIdx.x, h = blockIdx.y, b = blockIdx.z;
    const int bh = b * HH + h;
    const int q0 = qt * 16;
    const int tid = threadIdx.x, w = tid >> 5, lane = tid & 31;
    const int lrow = lane & 15, lcol = (lane >> 4) * 16;
    const int wn = w * 32;

    // ---- prologue: Q (into LF temp) + K chunks 0,1
    {
        int row = tid >> 3, c16 = (tid & 7) * 16;
        unsigned so = SWZ128((unsigned)(row * 128 + c16));
        CP_ASYNC16(sb + LA_LF + so, (const char*)(qh + (size_t)(b * SS + q0 + row) * 3072 + h * 64) + c16);
        CP_ASYNC16(sb + LA_LF + 2048 + so, (const char*)(ql + (size_t)(b * SS + q0 + row) * 3072 + h * 64) + c16);
    }
    la_load_k(qh, b, h, 0, sb + LA_K0, tid);
    CP_COMMIT();
    la_load_k(qh, b, h, 128, sb + LA_K0 + 16384, tid);
    CP_COMMIT();
    CP_WAIT1();
    __syncthreads();

    // ---- Q fragments -> registers
    unsigned qHf[4][4], qLf[4][4];
    #pragma unroll
    for (int ks = 0; ks < 4; ks++) {
        unsigned aoff = SWZ128((unsigned)(lrow * 128 + ks * 32 + lcol));
        LDMX4(qHf[ks][0], qHf[ks][1], qHf[ks][2], qHf[ks][3], sb + LA_LF + aoff);
        LDMX4(qLf[ks][0], qLf[ks][1], qLf[ks][2], qLf[ks][3], sb + LA_LF + 2048 + aoff);
    }
    __syncthreads();

    // ---- phase 1: 8 chunks of 128 keys, triple-buffered
    for (int c = 0; c < 8; c++) {
        if (c + 2 < 8) {
            int s2 = (c + 2) % 3;
            la_load_k(qh, b, h, (c + 2) * 128, sb + LA_K0 + s2 * 16384, tid);
            CP_COMMIT();
        }
        unsigned base = sb + LA_K0 + (c % 3) * 16384;
        float acc[4][4] = {};
        #pragma unroll
        for (int ks = 0; ks < 4; ks++) {
            int kb = ks * 32;
            unsigned bF[2][4];
            #pragma unroll
            for (int j2 = 0; j2 < 2; j2++) {
                unsigned boff = SWZ128((unsigned)((wn + j2 * 16 + lrow) * 128 + kb + lcol));
                LDMX4(bF[j2][0], bF[j2][1], bF[j2][2], bF[j2][3], base + boff);
            }
            #pragma unroll
            for (int j = 0; j < 4; j++) {
                unsigned b0 = (j & 1) ? bF[j >> 1][1] : bF[j >> 1][0];
                unsigned b1 = (j & 1) ? bF[j >> 1][3] : bF[j >> 1][2];
                MMAF16(acc[j], qHf[ks], b0, b1);
                MMAF16(acc[j], qLf[ks], b0, b1);
            }
        }
        int r0 = lane >> 2;
        int cb = c * 128 + wn + (lane & 3) * 2;
        #pragma unroll
        for (int j = 0; j < 4; j++) {
            int col = cb + j * 8;
            *(float2*)(smem + LA_LF + r0 * PSTRB + col * 4) =
                make_float2(acc[j][0] * 0.125f, acc[j][1] * 0.125f);
            *(float2*)(smem + LA_LF + (r0 + 8) * PSTRB + col * 4) =
                make_float2(acc[j][2] * 0.125f, acc[j][3] * 0.125f);
        }
        if (c + 1 < 8) {
            if (c + 2 < 8) { CP_WAIT1(); } else { CP_WAIT0(); }
        }
        __syncthreads();
    }

    // ---- register-resident softmax
    for (int r = w; r < 16; r += 4) {
        const char* rowp = smem + LA_LF + r * PSTRB;
        float e[32];
        float m = -1e30f;
        #pragma unroll
        for (int it = 0; it < 16; it++) {
            float2 v = *(const float2*)(rowp + it * 256 + lane * 8);
            e[it * 2] = v.x;
            e[it * 2 + 1] = v.y;
            m = fmaxf(m, fmaxf(v.x, v.y));
        }
        #pragma unroll
        for (int o = 16; o > 0; o >>= 1) m = fmaxf(m, __shfl_xor_sync(0xFFFFFFFFu, m, o));
        float sum = 0.f;
        #pragma unroll
        for (int i = 0; i < 32; i++) {
            e[i] = __expf(e[i] - m);
            sum += e[i];
        }
        #pragma unroll
        for (int o = 16; o > 0; o >>= 1) sum += __shfl_xor_sync(0xFFFFFFFFu, sum, o);
        float inv = 1.0f / sum;
        size_t base = ((size_t)(bh * SS) + q0 + r) * SS;
        #pragma unroll
        for (int it = 0; it < 16; it++) {
            float v0 = e[it * 2] * inv, v1 = e[it * 2 + 1] * inv;
            *(float2*)&attn_out[base + it * 64 + lane * 2] = make_float2(v0, v1);
            *(unsigned*)&pOut[base + it * 64 + lane * 2] = packs2(v0, v1);
        }
    }
}

// ---------------------------------------------------------------------------
// Kernel B: values = P(fp16) @ V^T (fp16 single)
// ---------------------------------------------------------------------------
#define AV_STAGE 24576
#define AV_TOTAL 73728

__device__ __forceinline__ void av_load(
    const __half* __restrict__ P, const __half* __restrict__ vTh,
    int bh, int brow, int kt, unsigned stage, int tid)
{
    #pragma unroll
    for (int i = 0; i < 8; i++) {
        int idx = tid + i * 128;
        int row = idx >> 3, c16 = (idx & 7) * 16;
        unsigned so = SWZ128((unsigned)(row * 128 + c16));
        CP_ASYNC16(stage + so, (const char*)(P + ((size_t)(bh * SS + brow + row)) * SS + kt) + c16);
    }
    #pragma unroll
    for (int i = 0; i < 4; i++) {
        int idx = tid + i * 128;
        int row = idx >> 3, c16 = (idx & 7) * 16;
        unsigned so = SWZ128((unsigned)(row * 128 + c16));
        CP_ASYNC16(stage + 16384 + so, (const char*)(vTh + (size_t)(bh * HDIM + row) * SS + kt) + c16);
    }
}

__global__ __launch_bounds__(128, 2) void av_gemm(
    const __half* __restrict__ P, const __half* __restrict__ vTh,
    __half* __restrict__ Vh)
{
    extern __shared__ char smem[];
    unsigned sb = smem_u32(smem);
    const int tid = threadIdx.x, w = tid >> 5, lane = tid & 31;
    const int brow = blockIdx.x * 128;
    const int bh = blockIdx.y;
    const int b = bh >> 4, h = bh & 15;
    const int wm = (w >> 1) * 64;
    const int wn = (w & 1) * 32;
    const int lrow = lane & 15;
    const int lcol = (lane >> 4) * 16;

    const int nch = 16;

    float acc[4][4][4] = {};

    av_load(P, vTh, bh, brow, 0, sb, tid);
    CP_COMMIT();
    av_load(P, vTh, bh, brow, 64, sb + AV_STAGE, tid);
    CP_COMMIT();
    CP_WAIT1();
    __syncthreads();

    int s_cur = 0;
    for (int c = 0; c < nch; c++) {
        if (c + 2 < nch) {
            int s2 = s_cur + 2; if (s2 >= 3) s2 -= 3;
            av_load(P, vTh, bh, brow, (c + 2) * 64, sb + s2 * AV_STAGE, tid);
            CP_COMMIT();
        }

        unsigned base = sb + s_cur * AV_STAGE;
        #pragma unroll
        for (int ks = 0; ks < 4; ks++) {
            int kb = ks * 32;
            unsigned vh[2][4];
            #pragma unroll
            for (int j2 = 0; j2 < 2; j2++) {
                unsigned off = SWZ128((unsigned)((wn + j2 * 16 + lrow) * 128 + kb + lcol));
                LDMX4(vh[j2][0], vh[j2][1], vh[j2][2], vh[j2][3], base + 16384 + off);
            }
            #pragma unroll
            for (int i = 0; i < 4; i++) {
                unsigned off = SWZ128((unsigned)((wm + i * 16 + lrow) * 128 + kb + lcol));
                unsigned aF[4];
                LDMX4(aF[0], aF[1], aF[2], aF[3], base + off);
                #pragma unroll
                for (int j = 0; j < 4; j++) {
                    unsigned h0 = (j & 1) ? vh[j >> 1][1] : vh[j >> 1][0];
                    unsigned h1 = (j & 1) ? vh[j >> 1][3] : vh[j >> 1][2];
                    MMAF16(acc[i][j], aF, h0, h1);
                }
            }
        }

        if (c + 1 < nch) {
            if (c + 2 < nch) { CP_WAIT1(); } else { CP_WAIT0(); }
        }
        __syncthreads();
        if (++s_cur == 3) s_cur = 0;
    }

    const int r0 = brow + wm + (lane >> 2);
    const int c0 = wn + (lane & 3) * 2;
    #pragma unroll
    for (int i = 0; i < 4; i++) {
        #pragma unroll
        for (int j = 0; j < 4; j++) {
            int col = h * 64 + c0 + j * 8;
            size_t o0 = (size_t)(b * SS + r0 + i * 16) * DD + col;
            size_t o1 = (size_t)(b * SS + r0 + i * 16 + 8) * DD + col;
            *(unsigned*)&Vh[o0] = packs2(acc[i][j][0], acc[i][j][1]);
            *(unsigned*)&Vh[o1] = packs2(acc[i][j][2], acc[i][j][3]);
        }
    }
}

// ---------------------------------------------------------------------------
extern "C" void kernel_launch(void* const* d_in, const int* in_sizes, int n_in,
                              void* d_out, int out_size)
{
    const float* x     = (const float*)d_in[0];
    const float* W_qkv = (const float*)d_in[1];
    const float* b_qkv = (const float*)d_in[2];
    const float* W_o   = (const float*)d_in[3];
    const float* b_o   = (const float*)d_in[4];

    float* out_o    = (float*)d_out;
    float* out_attn = (float*)d_out + (size_t)BB * SS * DD;

    __half *xhi, *xlo, *wqT, *woT, *vh, *qhp, *qlp, *vthp, *pp;
    float* bq;
    cudaGetSymbolAddress((void**)&xhi, g_xhi);
    cudaGetSymbolAddress((void**)&xlo, g_xlo);
    cudaGetSymbolAddress((void**)&wqT, g_wqT);
    cudaGetSymbolAddress((void**)&woT, g_woT);
    cudaGetSymbolAddress((void**)&vh, g_vh);
    cudaGetSymbolAddress((void**)&qhp, g_qh);
    cudaGetSymbolAddress((void**)&qlp, g_ql);
    cudaGetSymbolAddress((void**)&vthp, g_vTh);
    cudaGetSymbolAddress((void**)&pp, g_p);
    cudaGetSymbolAddress((void**)&bq, g_bq);

    cudaFuncSetAttribute(gemm2x_mma, cudaFuncAttributeMaxDynamicSharedMemorySize, GS_TOTAL);
    cudaFuncSetAttribute(gemm1x_mma, cudaFuncAttributeMaxDynamicSharedMemorySize, G1_TOTAL);
    cudaFuncSetAttribute(attn_logits, cudaFuncAttributeMaxDynamicSharedMemorySize, LA_TOTAL);
    cudaFuncSetAttribute(av_gemm, cudaFuncAttributeMaxDynamicSharedMemorySize, AV_TOTAL);

    // 0) prep: split x; permuted W_qkv^T + bias; W_o^T
    {
        int n4 = BB * SS * DD / 4;
        split_kernel<<<(n4 + 255) / 256, 256>>>(x, xhi, xlo, n4);
        dim3 g1(3 * DD / 32, DD / 32);
        tsingle_kernel<<<g1, dim3(32, 8)>>>(W_qkv, wqT, DD, 3 * DD, 1);
        dim3 g2(DD / 32, DD / 32);
        tsingle_kernel<<<g2, dim3(32, 8)>>>(W_o, woT, DD, DD, 0);
        bperm_kernel<<<(3 * DD + 255) / 256, 256>>>(b_qkv, bq);
    }

    // 1a) Q projection: 2-pass, hi/lo out (columns [0,1024) of permuted layout)
    {
        dim3 grid(DD / 128, BB * SS / 128);
        gemm2x_mma<<<grid, 128, GS_TOTAL>>>(xhi, xlo, wqT, bq,
                                            qhp, qlp, BB * SS, 3 * DD, DD);
    }

    // 1b) K+V projection: 1-pass, fp16 out (columns [1024,3072))
    {
        dim3 grid(2 * DD / 128, BB * SS / 128);
        gemm1x_mma<<<grid, 128, G1_TOTAL>>>(xhi, wqT + (size_t)DD * DD, bq + DD,
                                            (float*)nullptr, qhp + DD,
                                            BB * SS, 3 * DD, DD);
    }

    // 2) V^T (fp16 transpose of V block)
    {
        dim3 gv(SS / 32, HDIM / 32, BB * HH);
        vT_kernel<<<gv, dim3(32, 8)>>>(qhp, vthp);
    }

    // 3a) QK^T + register softmax -> attention + P fp16
    {
        dim3 grid(SS / 16, HH, BB);
        attn_logits<<<grid, 128, LA_TOTAL>>>(qhp, qlp, out_attn, pp);
    }

    // 3b) AV gemm -> values fp16
    {
        dim3 grid(SS / 128, BB * HH);
        av_gemm<<<grid, 128, AV_TOTAL>>>(pp, vthp, vh);
    }

    // 4) O-proj (1-pass fp16, fp32 out)
    {
        dim3 grid(DD / 128, BB * SS / 128);
        gemm1x_mma<<<grid, 128, G1_TOTAL>>>(vh, woT, b_o, out_o, (__half*)nullptr,
                                            BB * SS, DD, DD);
    }
}

// round 15
// speedup vs baseline: 2.2034x; 1.1141x over previous
#include <cuda_runtime.h>
#include <cuda_bf16.h>
#include <cuda_fp16.h>

#define BB 4
#define SS 1024
#define HH 16
#define HDIM 64
#define DD 1024

// ---------------------------------------------------------------------------
// scratch (device globals — no allocation allowed)
// ---------------------------------------------------------------------------
__device__ __half g_xh[BB * SS * DD];           // x fp16
__device__ __half g_wqT[3 * DD * DD];           // W_qkv^T fp16, permuted rows [Q|K|V]
__device__ float  g_bq[3 * DD];                 // permuted bias
__device__ __half g_woT[DD * DD];               // W_o^T fp16
__device__ __half g_vh[BB * SS * DD];           // values fp16 (av epilogue)
__device__ __half g_qh[BB * SS * 3 * DD];       // qkv hi, permuted cols [Q|K|V]
__device__ __half g_ql[BB * SS * 3 * DD];       // qkv lo (only Q cols used)
__device__ __half g_vTh[BB * HH * HDIM * SS];   // V^T fp16 per (b,h): [64][S]
__device__ __half g_p[(size_t)BB * HH * SS * SS]; // normalized attention fp16

// ---------------------------------------------------------------------------
__device__ __forceinline__ unsigned smem_u32(const void* p) {
    unsigned a;
    asm("{ .reg .u64 t; cvta.to.shared.u64 t, %1; cvt.u32.u64 %0, t; }" : "=r"(a) : "l"(p));
    return a;
}
#define SWZ128(o) ((o) ^ (((o) >> 3) & 0x70))
#define SWZ64(o)  ((o) ^ (((o) >> 3) & 0x30))

#define CP_ASYNC16(saddr, gptr) \
    asm volatile("cp.async.cg.shared.global [%0], [%1], 16;" :: "r"(saddr), "l"(gptr) : "memory")
#define CP_COMMIT() asm volatile("cp.async.commit_group;" ::: "memory")
#define CP_WAIT1()  asm volatile("cp.async.wait_group 1;" ::: "memory")
#define CP_WAIT0()  asm volatile("cp.async.wait_group 0;" ::: "memory")

#define LDMX4(r0, r1, r2, r3, a) \
    asm volatile("ldmatrix.sync.aligned.m8n8.x4.shared.b16 {%0,%1,%2,%3}, [%4];" \
        : "=r"(r0), "=r"(r1), "=r"(r2), "=r"(r3) : "r"(a))

#define MMAF16(d, a, b0, b1) \
    asm volatile("mma.sync.aligned.m16n8k16.row.col.f32.f16.f16.f32 " \
        "{%0,%1,%2,%3}, {%4,%5,%6,%7}, {%8,%9}, {%0,%1,%2,%3};" \
        : "+f"((d)[0]), "+f"((d)[1]), "+f"((d)[2]), "+f"((d)[3]) \
        : "r"((a)[0]), "r"((a)[1]), "r"((a)[2]), "r"((a)[3]), "r"(b0), "r"(b1))

__device__ __forceinline__ unsigned packh2(float x, float y, unsigned& lo) {
    __half hx = __float2half(x);
    __half hy = __float2half(y);
    __half lx = __float2half(x - __half2float(hx));
    __half ly = __float2half(y - __half2float(hy));
    lo = ((unsigned)__half_as_ushort(ly) << 16) | __half_as_ushort(lx);
    return ((unsigned)__half_as_ushort(hy) << 16) | __half_as_ushort(hx);
}
__device__ __forceinline__ unsigned packs2(float x, float y) {
    return ((unsigned)__half_as_ushort(__float2half(y)) << 16) |
           __half_as_ushort(__float2half(x));
}
__device__ __forceinline__ int qkv_perm(int n) {
    int head = n / 192, wi = n % 192;
    return (wi / 64) * 1024 + head * 64 + (wi % 64);
}

// ---------------------------------------------------------------------------
// x fp32 -> fp16 convert (single)
__global__ __launch_bounds__(256) void cvt_kernel(
    const float* __restrict__ src, __half* __restrict__ dst, int n4)
{
    int i = blockIdx.x * 256 + threadIdx.x;
    if (i >= n4) return;
    float4 v = ((const float4*)src)[i];
    ((uint2*)dst)[i] = make_uint2(packs2(v.x, v.y), packs2(v.z, v.w));
}

// transpose W[K,N] fp32 -> WT[N,K] fp16 (optionally column-permuted) + bias perm
__global__ __launch_bounds__(256) void tsingle_kernel(
    const float* __restrict__ W, __half* __restrict__ WT, int K, int N, int permute,
    const float* __restrict__ b, float* __restrict__ bp)
{
    __shared__ float t[32][33];
    int k0 = blockIdx.y * 32, n0 = blockIdx.x * 32;
    int tx = threadIdx.x, ty = threadIdx.y;
    #pragma unroll
    for (int i = 0; i < 32; i += 8)
        t[ty + i][tx] = W[(size_t)(k0 + ty + i) * N + n0 + tx];
    __syncthreads();
    #pragma unroll
    for (int i = 0; i < 32; i += 8) {
        int n = n0 + ty + i;
        int np = permute ? qkv_perm(n) : n;
        WT[(size_t)np * K + k0 + tx] = __float2half(t[tx][ty + i]);
    }
    // bias permute folded in: blocks of row 0 cover all N columns
    if (b && blockIdx.y == 0) {
        int tid = ty * 32 + tx;
        if (tid < 32) {
            int n = n0 + tid;
            bp[permute ? qkv_perm(n) : n] = b[n];
        }
    }
}

// V^T: fp16 transpose of qh V-block -> vTh [bh][64][S]
__global__ __launch_bounds__(256) void vT_kernel(
    const __half* __restrict__ qh, __half* __restrict__ vTh)
{
    __shared__ __half t[32][33];
    int s0 = blockIdx.x * 32, d0 = blockIdx.y * 32, bh = blockIdx.z;
    int b = bh >> 4, h = bh & 15;
    int tx = threadIdx.x, ty = threadIdx.y;
    #pragma unroll
    for (int i = 0; i < 32; i += 8)
        t[ty + i][tx] = qh[(size_t)(b * SS + s0 + ty + i) * 3072 + 2048 + h * 64 + d0 + tx];
    __syncthreads();
    #pragma unroll
    for (int i = 0; i < 32; i += 8)
        vTh[(size_t)(bh * HDIM + d0 + ty + i) * SS + s0 + tx] = t[tx][ty + i];
}

// ---------------------------------------------------------------------------
__device__ __forceinline__ void gload64h(const __half* __restrict__ src,
                                         int rbase, int K, int kt, unsigned dst, int tid)
{
    #pragma unroll
    for (int i = 0; i < 4; i++) {
        int idx = tid + i * 128;
        int row = idx >> 2;
        int c16 = (idx & 3) * 16;
        CP_ASYNC16(dst + SWZ64((unsigned)(row * 64 + c16)),
                   (const char*)(src + (size_t)(rbase + row) * K + kt) + c16);
    }
}

// ---------------------------------------------------------------------------
// 1-pass fp16 GEMM, mode by epilogue:
//   C != null           -> fp32 out
//   C == null, bcol<DD  -> hi/lo split out (Chi/Clo)
//   C == null, bcol>=DD -> single fp16 out (Chi)
// ---------------------------------------------------------------------------
#define G1_STAGE 16384
#define G1_TOTAL 49152

__device__ __forceinline__ void prefetch_chunk1(
    const __half* __restrict__ A, const __half* __restrict__ BT,
    int brow, int bcol, int K, int kt, unsigned stage, int tid)
{
    gload64h(A, brow, K, kt, stage, tid);
    gload64h(BT, bcol, K, kt, stage + 8192, tid);
}

__global__ __launch_bounds__(128, 2) void gemm1x_mma(
    const __half* __restrict__ A, const __half* __restrict__ BT,
    const float* __restrict__ bias, float* __restrict__ C,
    __half* __restrict__ Chi, __half* __restrict__ Clo,
    int M, int Nstr, int K)
{
    extern __shared__ char smem[];
    unsigned sb = smem_u32(smem);
    const int tid = threadIdx.x, w = tid >> 5, lane = tid & 31;
    const int brow = blockIdx.y * 128, bcol = blockIdx.x * 128;
    const int wm = (w >> 1) * 64;
    const int wn = (w & 1) * 64;
    const int lrow = lane & 15;
    const int lcol = (lane >> 4) * 16;

    const int nch = K >> 5;

    float acc[4][8][4] = {};

    prefetch_chunk1(A, BT, brow, bcol, K, 0, sb, tid);
    CP_COMMIT();
    prefetch_chunk1(A, BT, brow, bcol, K, 32, sb + G1_STAGE, tid);
    CP_COMMIT();
    CP_WAIT1();
    __syncthreads();

    int s_cur = 0;
    for (int c = 0; c < nch; c++) {
        if (c + 2 < nch) {
            int s2 = s_cur + 2; if (s2 >= 3) s2 -= 3;
            prefetch_chunk1(A, BT, brow, bcol, K, (c + 2) << 5,
                            sb + s2 * G1_STAGE, tid);
            CP_COMMIT();
        }

        unsigned base = sb + s_cur * G1_STAGE;
        #pragma unroll
        for (int ks = 0; ks < 2; ks++) {
            int kb = ks * 32;
            unsigned bF[4][4];
            #pragma unroll
            for (int j2 = 0; j2 < 4; j2++) {
                unsigned off = (unsigned)((wn + j2 * 16 + lrow) * 64 + kb + lcol);
                LDMX4(bF[j2][0], bF[j2][1], bF[j2][2], bF[j2][3], base + 8192 + SWZ64(off));
            }
            #pragma unroll
            for (int i = 0; i < 4; i++) {
                unsigned off = (unsigned)((wm + i * 16 + lrow) * 64 + kb + lcol);
                unsigned aF[4];
                LDMX4(aF[0], aF[1], aF[2], aF[3], base + SWZ64(off));
                #pragma unroll
                for (int j = 0; j < 8; j++) {
                    unsigned b0 = (j & 1) ? bF[j >> 1][1] : bF[j >> 1][0];
                    unsigned b1 = (j & 1) ? bF[j >> 1][3] : bF[j >> 1][2];
                    MMAF16(acc[i][j], aF, b0, b1);
                }
            }
        }

        if (c + 1 < nch) {
            if (c + 2 < nch) { CP_WAIT1(); } else { CP_WAIT0(); }
        }
        __syncthreads();
        if (++s_cur == 3) s_cur = 0;
    }

    const int r0 = brow + wm + (lane >> 2);
    const int c0 = bcol + wn + (lane & 3) * 2;
    const bool splitOut = (C == nullptr) && (bcol < DD);
    #pragma unroll
    for (int i = 0; i < 4; i++) {
        #pragma unroll
        for (int j = 0; j < 8; j++) {
            int col = c0 + j * 8;
            float bx = bias[col], by = bias[col + 1];
            float v00 = acc[i][j][0] + bx, v01 = acc[i][j][1] + by;
            float v10 = acc[i][j][2] + bx, v11 = acc[i][j][3] + by;
            size_t o0 = (size_t)(r0 + i * 16) * Nstr + col;
            size_t o1 = (size_t)(r0 + i * 16 + 8) * Nstr + col;
            if (C) {
                *(float2*)&C[o0] = make_float2(v00, v01);
                *(float2*)&C[o1] = make_float2(v10, v11);
            } else if (splitOut) {
                unsigned l0, l1;
                unsigned h0 = packh2(v00, v01, l0);
                unsigned h1 = packh2(v10, v11, l1);
                *(unsigned*)&Chi[o0] = h0;
                *(unsigned*)&Clo[o0] = l0;
                *(unsigned*)&Chi[o1] = h1;
                *(unsigned*)&Clo[o1] = l1;
            } else {
                *(unsigned*)&Chi[o0] = packs2(v00, v01);
                *(unsigned*)&Chi[o1] = packs2(v10, v11);
            }
        }
    }
}

// ---------------------------------------------------------------------------
// Kernel A: QK^T (2-pass Q x K-hi) + register softmax, vectorized stores.
// ---------------------------------------------------------------------------
#define LA_K0 0
#define LA_LF 49152
#define LA_TOTAL 115200
#define PSTRB 4128

__device__ __forceinline__ void la_load_k(
    const __half* __restrict__ qh, int b, int h, int kb, unsigned dst, int tid)
{
    #pragma unroll
    for (int i = 0; i < 8; i++) {
        int idx = tid + i * 128;
        int row = idx >> 3, c16 = (idx & 7) * 16;
        unsigned so = SWZ128((unsigned)(row * 128 + c16));
        CP_ASYNC16(dst + so, (const char*)(qh + (size_t)(b * SS + kb + row) * 3072 + 1024 + h * 64) + c16);
    }
}

__global__ __launch_bounds__(128, 2) void attn_logits(
    const __half* __restrict__ qh, const __half* __restrict__ ql,
    float* __restrict__ attn_out, __half* __restrict__ pOut)
{
    extern __shared__ char smem[];
    unsigned sb = smem_u32(smem);

    const int qt = blockIdx.x, h = blockIdx.y, b = blockIdx.z;
    const int bh = b * HH + h;
    const int q0 = qt * 16;
    const int tid = threadIdx.x, w = tid >> 5, lane = tid & 31;
    const int lrow = lane & 15, lcol = (lane >> 4) * 16;
    const int wn = w * 32;

    {
        int row = tid >> 3, c16 = (tid & 7) * 16;
        unsigned so = SWZ128((unsigned)(row * 128 + c16));
        CP_ASYNC16(sb + LA_LF + so, (const char*)(qh + (size_t)(b * SS + q0 + row) * 3072 + h * 64) + c16);
        CP_ASYNC16(sb + LA_LF + 2048 + so, (const char*)(ql + (size_t)(b * SS + q0 + row) * 3072 + h * 64) + c16);
    }
    la_load_k(qh, b, h, 0, sb + LA_K0, tid);
    CP_COMMIT();
    la_load_k(qh, b, h, 128, sb + LA_K0 + 16384, tid);
    CP_COMMIT();
    CP_WAIT1();
    __syncthreads();

    unsigned qHf[4][4], qLf[4][4];
    #pragma unroll
    for (int ks = 0; ks < 4; ks++) {
        unsigned aoff = SWZ128((unsigned)(lrow * 128 + ks * 32 + lcol));
        LDMX4(qHf[ks][0], qHf[ks][1], qHf[ks][2], qHf[ks][3], sb + LA_LF + aoff);
        LDMX4(qLf[ks][0], qLf[ks][1], qLf[ks][2], qLf[ks][3], sb + LA_LF + 2048 + aoff);
    }
    __syncthreads();

    for (int c = 0; c < 8; c++) {
        if (c + 2 < 8) {
            int s2 = (c + 2) % 3;
            la_load_k(qh, b, h, (c + 2) * 128, sb + LA_K0 + s2 * 16384, tid);
            CP_COMMIT();
        }
        unsigned base = sb + LA_K0 + (c % 3) * 16384;
        float acc[4][4] = {};
        #pragma unroll
        for (int ks = 0; ks < 4; ks++) {
            int kb = ks * 32;
            unsigned bF[2][4];
            #pragma unroll
            for (int j2 = 0; j2 < 2; j2++) {
                unsigned boff = SWZ128((unsigned)((wn + j2 * 16 + lrow) * 128 + kb + lcol));
                LDMX4(bF[j2][0], bF[j2][1], bF[j2][2], bF[j2][3], base + boff);
            }
            #pragma unroll
            for (int j = 0; j < 4; j++) {
                unsigned b0 = (j & 1) ? bF[j >> 1][1] : bF[j >> 1][0];
                unsigned b1 = (j & 1) ? bF[j >> 1][3] : bF[j >> 1][2];
                MMAF16(acc[j], qHf[ks], b0, b1);
                MMAF16(acc[j], qLf[ks], b0, b1);
            }
        }
        int r0 = lane >> 2;
        int cb = c * 128 + wn + (lane & 3) * 2;
        #pragma unroll
        for (int j = 0; j < 4; j++) {
            int col = cb + j * 8;
            *(float2*)(smem + LA_LF + r0 * PSTRB + col * 4) =
                make_float2(acc[j][0] * 0.125f, acc[j][1] * 0.125f);
            *(float2*)(smem + LA_LF + (r0 + 8) * PSTRB + col * 4) =
                make_float2(acc[j][2] * 0.125f, acc[j][3] * 0.125f);
        }
        if (c + 1 < 8) {
            if (c + 2 < 8) { CP_WAIT1(); } else { CP_WAIT0(); }
        }
        __syncthreads();
    }

    // register-resident softmax; float4/uint2 stores
    for (int r = w; r < 16; r += 4) {
        const char* rowp = smem + LA_LF + r * PSTRB;
        float e[32];
        float m = -1e30f;
        #pragma unroll
        for (int it = 0; it < 8; it++) {
            float4 v = *(const float4*)(rowp + it * 512 + lane * 16);
            e[it * 4 + 0] = v.x; e[it * 4 + 1] = v.y;
            e[it * 4 + 2] = v.z; e[it * 4 + 3] = v.w;
            m = fmaxf(m, fmaxf(fmaxf(v.x, v.y), fmaxf(v.z, v.w)));
        }
        #pragma unroll
        for (int o = 16; o > 0; o >>= 1) m = fmaxf(m, __shfl_xor_sync(0xFFFFFFFFu, m, o));
        float sum = 0.f;
        #pragma unroll
        for (int i = 0; i < 32; i++) {
            e[i] = __expf(e[i] - m);
            sum += e[i];
        }
        #pragma unroll
        for (int o = 16; o > 0; o >>= 1) sum += __shfl_xor_sync(0xFFFFFFFFu, sum, o);
        float inv = 1.0f / sum;
        size_t base = ((size_t)(bh * SS) + q0 + r) * SS;
        #pragma unroll
        for (int it = 0; it < 8; it++) {
            float4 o4;
            o4.x = e[it * 4 + 0] * inv;
            o4.y = e[it * 4 + 1] * inv;
            o4.z = e[it * 4 + 2] * inv;
            o4.w = e[it * 4 + 3] * inv;
            *(float4*)&attn_out[base + it * 128 + lane * 4] = o4;
            *(uint2*)&pOut[base + it * 128 + lane * 4] =
                make_uint2(packs2(o4.x, o4.y), packs2(o4.z, o4.w));
        }
    }
}

// ---------------------------------------------------------------------------
// Kernel B: values = P(fp16) @ V^T (fp16 single)
// ---------------------------------------------------------------------------
#define AV_STAGE 24576
#define AV_TOTAL 73728

__device__ __forceinline__ void av_load(
    const __half* __restrict__ P, const __half* __restrict__ vTh,
    int bh, int brow, int kt, unsigned stage, int tid)
{
    #pragma unroll
    for (int i = 0; i < 8; i++) {
        int idx = tid + i * 128;
        int row = idx >> 3, c16 = (idx & 7) * 16;
        unsigned so = SWZ128((unsigned)(row * 128 + c16));
        CP_ASYNC16(stage + so, (const char*)(P + ((size_t)(bh * SS + brow + row)) * SS + kt) + c16);
    }
    #pragma unroll
    for (int i = 0; i < 4; i++) {
        int idx = tid + i * 128;
        int row = idx >> 3, c16 = (idx & 7) * 16;
        unsigned so = SWZ128((unsigned)(row * 128 + c16));
        CP_ASYNC16(stage + 16384 + so, (const char*)(vTh + (size_t)(bh * HDIM + row) * SS + kt) + c16);
    }
}

__global__ __launch_bounds__(128, 2) void av_gemm(
    const __half* __restrict__ P, const __half* __restrict__ vTh,
    __half* __restrict__ Vh)
{
    extern __shared__ char smem[];
    unsigned sb = smem_u32(smem);
    const int tid = threadIdx.x, w = tid >> 5, lane = tid & 31;
    const int brow = blockIdx.x * 128;
    const int bh = blockIdx.y;
    const int b = bh >> 4, h = bh & 15;
    const int wm = (w >> 1) * 64;
    const int wn = (w & 1) * 32;
    const int lrow = lane & 15;
    const int lcol = (lane >> 4) * 16;

    const int nch = 16;

    float acc[4][4][4] = {};

    av_load(P, vTh, bh, brow, 0, sb, tid);
    CP_COMMIT();
    av_load(P, vTh, bh, brow, 64, sb + AV_STAGE, tid);
    CP_COMMIT();
    CP_WAIT1();
    __syncthreads();

    int s_cur = 0;
    for (int c = 0; c < nch; c++) {
        if (c + 2 < nch) {
            int s2 = s_cur + 2; if (s2 >= 3) s2 -= 3;
            av_load(P, vTh, bh, brow, (c + 2) * 64, sb + s2 * AV_STAGE, tid);
            CP_COMMIT();
        }

        unsigned base = sb + s_cur * AV_STAGE;
        #pragma unroll
        for (int ks = 0; ks < 4; ks++) {
            int kb = ks * 32;
            unsigned vh[2][4];
            #pragma unroll
            for (int j2 = 0; j2 < 2; j2++) {
                unsigned off = SWZ128((unsigned)((wn + j2 * 16 + lrow) * 128 + kb + lcol));
                LDMX4(vh[j2][0], vh[j2][1], vh[j2][2], vh[j2][3], base + 16384 + off);
            }
            #pragma unroll
            for (int i = 0; i < 4; i++) {
                unsigned off = SWZ128((unsigned)((wm + i * 16 + lrow) * 128 + kb + lcol));
                unsigned aF[4];
                LDMX4(aF[0], aF[1], aF[2], aF[3], base + off);
                #pragma unroll
                for (int j = 0; j < 4; j++) {
                    unsigned h0 = (j & 1) ? vh[j >> 1][1] : vh[j >> 1][0];
                    unsigned h1 = (j & 1) ? vh[j >> 1][3] : vh[j >> 1][2];
                    MMAF16(acc[i][j], aF, h0, h1);
                }
            }
        }

        if (c + 1 < nch) {
            if (c + 2 < nch) { CP_WAIT1(); } else { CP_WAIT0(); }
        }
        __syncthreads();
        if (++s_cur == 3) s_cur = 0;
    }

    const int r0 = brow + wm + (lane >> 2);
    const int c0 = wn + (lane & 3) * 2;
    #pragma unroll
    for (int i = 0; i < 4; i++) {
        #pragma unroll
        for (int j = 0; j < 4; j++) {
            int col = h * 64 + c0 + j * 8;
            size_t o0 = (size_t)(b * SS + r0 + i * 16) * DD + col;
            size_t o1 = (size_t)(b * SS + r0 + i * 16 + 8) * DD + col;
            *(unsigned*)&Vh[o0] = packs2(acc[i][j][0], acc[i][j][1]);
            *(unsigned*)&Vh[o1] = packs2(acc[i][j][2], acc[i][j][3]);
        }
    }
}

// ---------------------------------------------------------------------------
extern "C" void kernel_launch(void* const* d_in, const int* in_sizes, int n_in,
                              void* d_out, int out_size)
{
    const float* x     = (const float*)d_in[0];
    const float* W_qkv = (const float*)d_in[1];
    const float* b_qkv = (const float*)d_in[2];
    const float* W_o   = (const float*)d_in[3];
    const float* b_o   = (const float*)d_in[4];

    float* out_o    = (float*)d_out;
    float* out_attn = (float*)d_out + (size_t)BB * SS * DD;

    __half *xh, *wqT, *woT, *vh, *qhp, *qlp, *vthp, *pp;
    float* bq;
    cudaGetSymbolAddress((void**)&xh, g_xh);
    cudaGetSymbolAddress((void**)&wqT, g_wqT);
    cudaGetSymbolAddress((void**)&woT, g_woT);
    cudaGetSymbolAddress((void**)&vh, g_vh);
    cudaGetSymbolAddress((void**)&qhp, g_qh);
    cudaGetSymbolAddress((void**)&qlp, g_ql);
    cudaGetSymbolAddress((void**)&vthp, g_vTh);
    cudaGetSymbolAddress((void**)&pp, g_p);
    cudaGetSymbolAddress((void**)&bq, g_bq);

    cudaFuncSetAttribute(gemm1x_mma, cudaFuncAttributeMaxDynamicSharedMemorySize, G1_TOTAL);
    cudaFuncSetAttribute(attn_logits, cudaFuncAttributeMaxDynamicSharedMemorySize, LA_TOTAL);
    cudaFuncSetAttribute(av_gemm, cudaFuncAttributeMaxDynamicSharedMemorySize, AV_TOTAL);

    // 0) prep: convert x; permuted W_qkv^T (+bias); W_o^T
    {
        int n4 = BB * SS * DD / 4;
        cvt_kernel<<<(n4 + 255) / 256, 256>>>(x, xh, n4);
        dim3 g1(3 * DD / 32, DD / 32);
        tsingle_kernel<<<g1, dim3(32, 8)>>>(W_qkv, wqT, DD, 3 * DD, 1, b_qkv, bq);
        dim3 g2(DD / 32, DD / 32);
        tsingle_kernel<<<g2, dim3(32, 8)>>>(W_o, woT, DD, DD, 0,
                                            (const float*)nullptr, (float*)nullptr);
    }

    // 1) QKV projection: ONE 1-pass gemm over all 3072 cols.
    //    Q-cols get exact hi/lo split of fp32 result; K/V-cols single fp16.
    {
        dim3 grid(3 * DD / 128, BB * SS / 128);
        gemm1x_mma<<<grid, 128, G1_TOTAL>>>(xh, wqT, bq, (float*)nullptr,
                                            qhp, qlp, BB * SS, 3 * DD, DD);
    }

    // 2) V^T (fp16 transpose of V block)
    {
        dim3 gv(SS / 32, HDIM / 32, BB * HH);
        vT_kernel<<<gv, dim3(32, 8)>>>(qhp, vthp);
    }

    // 3a) QK^T + register softmax -> attention + P fp16
    {
        dim3 grid(SS / 16, HH, BB);
        attn_logits<<<grid, 128, LA_TOTAL>>>(qhp, qlp, out_attn, pp);
    }

    // 3b) AV gemm -> values fp16
    {
        dim3 grid(SS / 128, BB * HH);
        av_gemm<<<grid, 128, AV_TOTAL>>>(pp, vthp, vh);
    }

    // 4) O-proj (1-pass fp16, fp32 out)
    {
        dim3 grid(DD / 128, BB * SS / 128);
        gemm1x_mma<<<grid, 128, G1_TOTAL>>>(vh, woT, b_o, out_o,
                                            (__half*)nullptr, (__half*)nullptr,
                                            BB * SS, DD, DD);
    }
}